// round 1
// baseline (speedup 1.0000x reference)
#include <cuda_runtime.h>
#include <cstdint>
#include <math.h>
#include <cub/device/device_radix_sort.cuh>

// Problem-fixed sizes (from setup_inputs): N=300000, D=64, E=1000000, R=100000
#define DD 64
static const int    N_MAX = 300032;
static const int    M_MAX = 1200000;
static const size_t TEMP_BYTES = 64u << 20;

// Scratch (device globals — allocation-free per harness rules)
__device__ float              g_A[(size_t)N_MAX * DD];
__device__ float              g_B[(size_t)N_MAX * DD];
__device__ unsigned long long g_keys_in [M_MAX];
__device__ unsigned long long g_keys_out[M_MAX];
__device__ float              g_vals_in [M_MAX];
__device__ float              g_vals_out[M_MAX];
__device__ unsigned char      g_temp[TEMP_BYTES];

// ---------------------------------------------------------------------------
// Kernel 1: per-node partial GEMMs.
// A[n][j] = sum_k emb[n][k] * W1[j][k]       (left half of W1, cols 0..63)
// B[n][j] = sum_k emb[n][k] * W1[j][64+k]    (right half, cols 64..127)
// Block: 256 threads, 32 nodes per block, each thread owns (j, 8 nodes).
// ---------------------------------------------------------------------------
__global__ void precompute_ab(const float* __restrict__ emb,
                              const float* __restrict__ W1, int N) {
    __shared__ float ws[128 * 65]; // ws[kk*65 + j] = W1[j*128 + kk], padded row 65
    __shared__ float es[64 * 33];  // es[k*33 + ni] = emb[(n0+ni)*64 + k], padded 33

    const int tid = threadIdx.x;
    const int n0  = blockIdx.x * 32;

    // Load W1 (coalesced global read, conflict-free shared write via padding)
    for (int idx = tid; idx < 64 * 128; idx += 256) {
        int j  = idx >> 7;       // 0..63
        int kk = idx & 127;      // 0..127
        ws[kk * 65 + j] = W1[idx];
    }
    // Load 32 node embeddings, transposed (k-major)
    for (int idx = tid; idx < 32 * 64; idx += 256) {
        int ni = idx >> 6;       // 0..31
        int k  = idx & 63;       // 0..63
        int n  = n0 + ni;
        es[k * 33 + ni] = (n < N) ? emb[(size_t)n * DD + k] : 0.0f;
    }
    __syncthreads();

    const int j = tid & 63;      // output feature
    const int g = tid >> 6;      // node group 0..3 (8 nodes each)

    float a[8], b[8];
#pragma unroll
    for (int c = 0; c < 8; ++c) { a[c] = 0.0f; b[c] = 0.0f; }

#pragma unroll 4
    for (int k = 0; k < 64; ++k) {
        float wa = ws[k * 65 + j];          // left-half weight
        float wb = ws[(64 + k) * 65 + j];   // right-half weight
        const float* ep = &es[k * 33 + g * 8];
#pragma unroll
        for (int c = 0; c < 8; ++c) {
            float e = ep[c];                // warp-broadcast
            a[c] = fmaf(e, wa, a[c]);
            b[c] = fmaf(e, wb, b[c]);
        }
    }

#pragma unroll
    for (int c = 0; c < 8; ++c) {
        int n = n0 + g * 8 + c;
        if (n < N) {
            g_A[(size_t)n * DD + j] = a[c];
            g_B[(size_t)n * DD + j] = b[c];
        }
    }
}

// ---------------------------------------------------------------------------
// Kernel 2: warp per edge — gather A[src], B[dst], relu-add-b1, dot W2,
// then the Gumbel-sigmoid / RelaxedBernoulli scalar chain on lane 0.
// ---------------------------------------------------------------------------
__global__ void edge_kernel(const int* __restrict__ ei,
                            const float* __restrict__ b1,
                            const float* __restrict__ W2,
                            const float* __restrict__ b2,
                            const float* __restrict__ eps_u,
                            const float* __restrict__ rb_u,
                            int E) {
    int e    = (int)((blockIdx.x * (unsigned)blockDim.x + threadIdx.x) >> 5);
    int lane = threadIdx.x & 31;
    if (e >= E) return;

    int src = ei[e];
    int dst = ei[E + e];

    const float* Ap = g_A + (size_t)src * DD;
    const float* Bp = g_B + (size_t)dst * DD;

    float h1 = fmaxf(Ap[lane]      + Bp[lane]      + b1[lane],      0.0f);
    float h2 = fmaxf(Ap[lane + 32] + Bp[lane + 32] + b1[lane + 32], 0.0f);
    float p  = h1 * W2[lane] + h2 * W2[lane + 32];

#pragma unroll
    for (int o = 16; o; o >>= 1)
        p += __shfl_xor_sync(0xffffffffu, p, o);

    if (lane == 0) {
        float logit = p + b2[0];
        // eps = (bias - (1-bias))*eps_u + (1-bias),  bias = 1e-4
        float eps  = fmaf(-0.9998f, eps_u[e], 0.9999f);
        float gate = logf(eps) - log1pf(-eps) + logit;
        float w    = 1.0f / (1.0f + expf(-gate));
        float att  = fminf(fmaxf(w, 0.01f), 0.99f);
        float u    = fminf(fmaxf(rb_u[e], 1e-7f), 1.0f - 1e-7f);
        float sarg = (logf(att) - log1pf(-att) + logf(u) - log1pf(-u)) * (1.0f / 0.9f);
        float s    = 1.0f / (1.0f + expf(-sarg));
        // mask = (s > 0) is always 1 in fp32 here, so mat = s
        g_vals_in[e] = s;
        g_keys_in[e] = ((unsigned long long)(unsigned)src << 20) | (unsigned)dst;
    }
}

// ---------------------------------------------------------------------------
// Kernel 3: random-edge entries (value 0.05)
// ---------------------------------------------------------------------------
__global__ void rand_kernel(const int* __restrict__ ri, int R, int E) {
    int r = blockIdx.x * blockDim.x + threadIdx.x;
    if (r >= R) return;
    g_keys_in[E + r] = ((unsigned long long)(unsigned)ri[r] << 20) | (unsigned)ri[R + r];
    g_vals_in[E + r] = 0.05f;
}

// ---------------------------------------------------------------------------
// Kernel 4: coalesce duplicates on the sorted stream + write output.
// out layout: [0..M) rows, [M..2M) cols, [2M..3M) vals (float32)
// ---------------------------------------------------------------------------
__global__ void finalize_kernel(float* __restrict__ out, int M, int vals_only) {
    int i = blockIdx.x * blockDim.x + threadIdx.x;
    if (i >= M) return;
    unsigned long long k = g_keys_out[i];
    bool head = (i == 0) || (g_keys_out[i - 1] != k);
    float v = 0.0f;
    if (head) {
        v = g_vals_out[i];
        for (int j = i + 1; j < M && g_keys_out[j] == k; ++j)
            v += g_vals_out[j];  // duplicates are rare (~7 expected in 1.1M)
    }
    if (vals_only) {
        out[i] = v;
    } else {
        out[i]         = (float)(unsigned)(k >> 20);
        out[M + i]     = (float)(unsigned)(k & 0xFFFFFu);
        out[2 * M + i] = v;
    }
}

// ---------------------------------------------------------------------------
extern "C" void kernel_launch(void* const* d_in, const int* in_sizes, int n_in,
                              void* d_out, int out_size) {
    const float* emb   = (const float*)d_in[0];
    const float* W1    = (const float*)d_in[1];
    const float* b1    = (const float*)d_in[2];
    const float* W2    = (const float*)d_in[3];
    const float* b2    = (const float*)d_in[4];
    const int*   ei    = (const int*)  d_in[5];
    const int*   ri    = (const int*)  d_in[6];
    const float* eps_u = (const float*)d_in[7];
    const float* rb_u  = (const float*)d_in[8];

    const int N = in_sizes[0] / DD;
    const int E = in_sizes[5] / 2;
    const int R = in_sizes[6] / 2;
    const int M = E + R;

    // 1) Node-factored MLP partials
    precompute_ab<<<(N + 31) / 32, 256>>>(emb, W1, N);

    // 2) Per-edge gate values + packed keys (warp per edge)
    edge_kernel<<<(E + 7) / 8, 256>>>(ei, b1, W2, b2, eps_u, rb_u, E);

    // 3) Random-edge entries
    rand_kernel<<<(R + 255) / 256, 256>>>(ri, R, E);

    // 4) Stable radix sort on 40-bit packed (row,col) keys
    void *p_kin, *p_kout, *p_vin, *p_vout, *p_tmp;
    cudaGetSymbolAddress(&p_kin,  g_keys_in);
    cudaGetSymbolAddress(&p_kout, g_keys_out);
    cudaGetSymbolAddress(&p_vin,  g_vals_in);
    cudaGetSymbolAddress(&p_vout, g_vals_out);
    cudaGetSymbolAddress(&p_tmp,  g_temp);

    size_t tb = 0;
    cub::DeviceRadixSort::SortPairs(nullptr, tb,
        (const unsigned long long*)p_kin, (unsigned long long*)p_kout,
        (const float*)p_vin, (float*)p_vout, M, 0, 40, (cudaStream_t)0);
    if (tb <= TEMP_BYTES) {
        cub::DeviceRadixSort::SortPairs(p_tmp, tb,
            (const unsigned long long*)p_kin, (unsigned long long*)p_kout,
            (const float*)p_vin, (float*)p_vout, M, 0, 40, (cudaStream_t)0);
    }

    // 5) Coalesce + write output
    int vals_only = (out_size == M) ? 1 : 0;
    finalize_kernel<<<(M + 255) / 256, 256>>>((float*)d_out, M, vals_only);
}

// round 2
// speedup vs baseline: 1.0345x; 1.0345x over previous
#include <cuda_runtime.h>
#include <cuda_fp16.h>
#include <cstdint>
#include <math.h>
#include <cub/device/device_scan.cuh>

// Problem-fixed sizes (from setup_inputs): N=300000, D=64, E=1000000, R=100000
#define DD 64
static const int    N_MAX = 300032;
static const int    M_MAX = 1200000;
static const size_t TEMP_BYTES = 4u << 20;

// Scratch (device globals — allocation-free per harness rules)
__device__ __half2        g_A[(size_t)N_MAX * 32];   // [N][64] fp16, viewed as half2
__device__ __half2        g_B[(size_t)N_MAX * 32];
__device__ int            g_cnt [N_MAX];             // per-row entry count
__device__ int            g_offs[N_MAX + 1];         // exclusive prefix -> scatter cursor
__device__ unsigned       g_cols_s[M_MAX];           // scattered cols (grouped by row)
__device__ float          g_vals_s[M_MAX];           // scattered vals
__device__ unsigned char  g_temp[TEMP_BYTES];        // CUB scan temp

// ---------------------------------------------------------------------------
// Kernel 1: per-node partial GEMMs (node-factored edge MLP), fp16 output.
// A[n][j] = sum_k emb[n][k] * W1[j][k]     (left half of W1)
// B[n][j] = sum_k emb[n][k] * W1[j][64+k]  (right half)
// ---------------------------------------------------------------------------
__global__ void precompute_ab(const float* __restrict__ emb,
                              const float* __restrict__ W1, int N) {
    __shared__ float ws[128 * 65]; // ws[kk*65 + j] = W1[j*128 + kk]
    __shared__ float es[64 * 33];  // es[k*33 + ni] = emb[(n0+ni)*64 + k]

    const int tid = threadIdx.x;
    const int n0  = blockIdx.x * 32;

    for (int idx = tid; idx < 64 * 128; idx += 256) {
        int j  = idx >> 7;
        int kk = idx & 127;
        ws[kk * 65 + j] = W1[idx];
    }
    for (int idx = tid; idx < 32 * 64; idx += 256) {
        int ni = idx >> 6;
        int k  = idx & 63;
        int n  = n0 + ni;
        es[k * 33 + ni] = (n < N) ? emb[(size_t)n * DD + k] : 0.0f;
    }
    __syncthreads();

    const int j = tid & 63;
    const int g = tid >> 6;

    float a[8], b[8];
#pragma unroll
    for (int c = 0; c < 8; ++c) { a[c] = 0.0f; b[c] = 0.0f; }

#pragma unroll 4
    for (int k = 0; k < 64; ++k) {
        float wa = ws[k * 65 + j];
        float wb = ws[(64 + k) * 65 + j];
        const float* ep = &es[k * 33 + g * 8];
#pragma unroll
        for (int c = 0; c < 8; ++c) {
            float e = ep[c];
            a[c] = fmaf(e, wa, a[c]);
            b[c] = fmaf(e, wb, b[c]);
        }
    }

    __half* Ah = (__half*)g_A;
    __half* Bh = (__half*)g_B;
#pragma unroll
    for (int c = 0; c < 8; ++c) {
        int n = n0 + g * 8 + c;
        if (n < N) {
            Ah[(size_t)n * DD + j] = __float2half_rn(a[c]);
            Bh[(size_t)n * DD + j] = __float2half_rn(b[c]);
        }
    }
}

// ---------------------------------------------------------------------------
// Kernel 2: row histogram over all (edge + random) entries.
// ---------------------------------------------------------------------------
__global__ void hist_kernel(const int* __restrict__ ei,
                            const int* __restrict__ ri, int E, int R) {
    int i = blockIdx.x * blockDim.x + threadIdx.x;
    if (i < E)          atomicAdd(&g_cnt[ei[i]], 1);
    else if (i < E + R) atomicAdd(&g_cnt[ri[i - E]], 1);
}

// ---------------------------------------------------------------------------
// Kernel 3: warp per edge — fp16 gather + MLP gate + Gumbel/RelaxedBernoulli,
// then scatter (col,val) into the row's segment via cursor atomic.
// ---------------------------------------------------------------------------
__global__ void edge_kernel(const int* __restrict__ ei,
                            const float* __restrict__ b1,
                            const float* __restrict__ W2,
                            const float* __restrict__ b2,
                            const float* __restrict__ eps_u,
                            const float* __restrict__ rb_u,
                            int E) {
    int e    = (int)((blockIdx.x * (unsigned)blockDim.x + threadIdx.x) >> 5);
    int lane = threadIdx.x & 31;
    if (e >= E) return;

    int src = ei[e];
    int dst = ei[E + e];

    const __half2* Ap = g_A + (size_t)src * 32;
    const __half2* Bp = g_B + (size_t)dst * 32;
    const float2*  b1p = (const float2*)b1;
    const float2*  w2p = (const float2*)W2;

    float2 av = __half22float2(Ap[lane]);
    float2 bv = __half22float2(Bp[lane]);
    float2 b1v = b1p[lane];
    float2 w2v = w2p[lane];

    float h1 = fmaxf(av.x + bv.x + b1v.x, 0.0f);
    float h2 = fmaxf(av.y + bv.y + b1v.y, 0.0f);
    float p  = h1 * w2v.x + h2 * w2v.y;

#pragma unroll
    for (int o = 16; o; o >>= 1)
        p += __shfl_xor_sync(0xffffffffu, p, o);

    if (lane == 0) {
        float logit = p + b2[0];
        float eps  = fmaf(-0.9998f, eps_u[e], 0.9999f);
        float gate = logf(eps) - log1pf(-eps) + logit;
        float w    = 1.0f / (1.0f + expf(-gate));
        float att  = fminf(fmaxf(w, 0.01f), 0.99f);
        float u    = fminf(fmaxf(rb_u[e], 1e-7f), 1.0f - 1e-7f);
        float sarg = (logf(att) - log1pf(-att) + logf(u) - log1pf(-u)) * (1.0f / 0.9f);
        float s    = 1.0f / (1.0f + expf(-sarg));
        // mask = (s > 0) is always 1 in fp32, so mat = s
        int pos = atomicAdd(&g_offs[src], 1);
        g_cols_s[pos] = (unsigned)dst;
        g_vals_s[pos] = s;
    }
}

// ---------------------------------------------------------------------------
// Kernel 4: scatter random entries (value 0.05)
// ---------------------------------------------------------------------------
__global__ void rand_kernel(const int* __restrict__ ri, int R) {
    int r = blockIdx.x * blockDim.x + threadIdx.x;
    if (r >= R) return;
    int row = ri[r];
    int col = ri[R + r];
    int pos = atomicAdd(&g_offs[row], 1);
    g_cols_s[pos] = (unsigned)col;
    g_vals_s[pos] = 0.05f;
}

// ---------------------------------------------------------------------------
// Kernel 5: per-row sort by col + coalesce duplicates + write output.
// out layout: [0..M) rows, [M..2M) cols, [2M..3M) vals (float32)
// After the scatter phase, g_offs[r] == segment_end; start = end - cnt.
// ---------------------------------------------------------------------------
__global__ void row_sort_kernel(float* __restrict__ out, int M, int NROWS,
                                int vals_only) {
    int r = blockIdx.x * blockDim.x + threadIdx.x;
    if (r >= NROWS) return;
    int cnt = g_cnt[r];
    if (cnt == 0) return;
    int start = g_offs[r] - cnt;

    unsigned lc[32];
    float    lv[32];
    unsigned* c;
    float*    v;
    if (cnt <= 32) {
        for (int j = 0; j < cnt; ++j) {
            lc[j] = g_cols_s[start + j];
            lv[j] = g_vals_s[start + j];
        }
        c = lc; v = lv;
    } else {
        // Astronomically rare (Poisson mean ~3.7), but stay correct.
        c = &g_cols_s[start];
        v = &g_vals_s[start];
    }

    // insertion sort ascending by col
    for (int j = 1; j < cnt; ++j) {
        unsigned ck = c[j];
        float    vk = v[j];
        int k = j - 1;
        while (k >= 0 && c[k] > ck) {
            c[k + 1] = c[k];
            v[k + 1] = v[k];
            --k;
        }
        c[k + 1] = ck;
        v[k + 1] = vk;
    }

    // coalesce runs of equal col: first gets sum, rest get 0
    float frow = (float)r;
    int j = 0;
    while (j < cnt) {
        int k = j + 1;
        float s = v[j];
        while (k < cnt && c[k] == c[j]) { s += v[k]; ++k; }
        for (int t = j; t < k; ++t) {
            int   o  = start + t;
            float ov = (t == j) ? s : 0.0f;
            if (vals_only) {
                out[o] = ov;
            } else {
                out[o]         = frow;
                out[M + o]     = (float)c[t];
                out[2 * M + o] = ov;
            }
        }
        j = k;
    }
}

// ---------------------------------------------------------------------------
extern "C" void kernel_launch(void* const* d_in, const int* in_sizes, int n_in,
                              void* d_out, int out_size) {
    const float* emb   = (const float*)d_in[0];
    const float* W1    = (const float*)d_in[1];
    const float* b1    = (const float*)d_in[2];
    const float* W2    = (const float*)d_in[3];
    const float* b2    = (const float*)d_in[4];
    const int*   ei    = (const int*)  d_in[5];
    const int*   ri    = (const int*)  d_in[6];
    const float* eps_u = (const float*)d_in[7];
    const float* rb_u  = (const float*)d_in[8];

    const int N = in_sizes[0] / DD;
    const int E = in_sizes[5] / 2;
    const int R = in_sizes[6] / 2;
    const int M = E + R;

    void *p_cnt, *p_offs, *p_tmp;
    cudaGetSymbolAddress(&p_cnt,  g_cnt);
    cudaGetSymbolAddress(&p_offs, g_offs);
    cudaGetSymbolAddress(&p_tmp,  g_temp);

    // 1) zero row counters
    cudaMemsetAsync(p_cnt, 0, (size_t)N * sizeof(int), (cudaStream_t)0);

    // 2) row histogram from raw indices
    hist_kernel<<<(E + R + 255) / 256, 256>>>(ei, ri, E, R);

    // 3) exclusive scan -> segment offsets (doubles as scatter cursor)
    size_t tb = TEMP_BYTES;
    cub::DeviceScan::ExclusiveSum(p_tmp, tb, (const int*)p_cnt, (int*)p_offs,
                                  N, (cudaStream_t)0);

    // 4) node-factored MLP partials (fp16)
    precompute_ab<<<(N + 31) / 32, 256>>>(emb, W1, N);

    // 5) per-edge gate values, scattered directly into row segments
    edge_kernel<<<(E + 7) / 8, 256>>>(ei, b1, W2, b2, eps_u, rb_u, E);

    // 6) random entries
    rand_kernel<<<(R + 255) / 256, 256>>>(ri, R);

    // 7) per-row col sort + coalesce + output
    int vals_only = (out_size == M) ? 1 : 0;
    row_sort_kernel<<<(N + 255) / 256, 256>>>((float*)d_out, M, N, vals_only);
}

// round 3
// speedup vs baseline: 2.4643x; 2.3821x over previous
#include <cuda_runtime.h>
#include <cuda_fp16.h>
#include <cstdint>
#include <math.h>
#include <cub/device/device_scan.cuh>

// Problem-fixed sizes (from setup_inputs): N=300000, D=64, E=1000000, R=100000
#define DD 64
static const int    N_MAX = 300032;
static const int    M_MAX = 1200000;
static const size_t TEMP_BYTES = 4u << 20;

// Scratch (device globals — allocation-free per harness rules)
__device__ __align__(16) __half2 g_A[(size_t)N_MAX * 32];   // [N][64] fp16
__device__ __align__(16) __half2 g_B[(size_t)N_MAX * 32];
__device__ int            g_cnt [N_MAX];             // per-row entry count
__device__ int            g_offs[N_MAX + 1];         // exclusive prefix -> cursor
__device__ unsigned       g_cols_s[M_MAX];           // scattered cols (row-grouped)
__device__ float          g_vals_s[M_MAX];           // scattered vals
__device__ unsigned char  g_temp[TEMP_BYTES];        // CUB scan temp

// ---------------------------------------------------------------------------
// Kernel 1: tensor-core node-factored MLP partials.
// [A|B][n][jj] = sum_k emb[n][k] * Wcat[jj][k],  Wcat[jj] = W1[jj][0:64] (jj<64)
//                                                 Wcat[64+j] = W1[j][64:128]
// mma.sync m16n8k8 tf32. Block: 256 thr (8 warps), 128 nodes; warp = 16 rows.
// ---------------------------------------------------------------------------
__device__ __forceinline__ unsigned f2tf32(float x) {
    unsigned r;
    asm("cvt.rna.tf32.f32 %0, %1;" : "=r"(r) : "f"(x));
    return r;
}

#define SW_PITCH 136   // 128 + 8 : (8*k + jj) mod 32 distinct -> conflict-free B frags
#define SE_PITCH 68    // 64 + 4  : (4*row + col) mod 32 distinct -> conflict-free A frags
#define PRE_SMEM ((64 * SW_PITCH + 128 * SE_PITCH) * 4)

__global__ void precompute_mma(const float* __restrict__ emb,
                               const float* __restrict__ W1, int N) {
    extern __shared__ float smem[];
    float* sW = smem;                  // [64][SW_PITCH]  sW[k][jj] = Wcat[jj][k]
    float* sE = smem + 64 * SW_PITCH;  // [128][SE_PITCH] node tile

    const int tid = threadIdx.x;
    const int n0  = blockIdx.x * 128;

    // Load W1 (8192 floats, coalesced) into sW
    for (int idx = tid; idx < 8192; idx += 256) {
        int j  = idx >> 7;
        int c  = idx & 127;
        int jj = (c < 64) ? j : j + 64;
        int k  = c & 63;
        sW[k * SW_PITCH + jj] = W1[idx];
    }
    // Load 128 node embeddings
    for (int idx = tid; idx < 8192; idx += 256) {
        int ni = idx >> 6;
        int k  = idx & 63;
        int n  = n0 + ni;
        sE[ni * SE_PITCH + k] = (n < N) ? emb[(size_t)n * DD + k] : 0.0f;
    }
    __syncthreads();

    const int warp  = tid >> 5;
    const int lane  = tid & 31;
    const int gid   = lane >> 2;   // 0..7
    const int tig   = lane & 3;    // 0..3
    const int mrow0 = warp * 16;

    float acc[16][4];
#pragma unroll
    for (int nt = 0; nt < 16; ++nt)
#pragma unroll
        for (int c = 0; c < 4; ++c) acc[nt][c] = 0.0f;

#pragma unroll
    for (int kt = 0; kt < 8; ++kt) {
        const int kb = kt * 8;
        unsigned a0 = f2tf32(sE[(mrow0 + gid)     * SE_PITCH + kb + tig]);
        unsigned a1 = f2tf32(sE[(mrow0 + gid + 8) * SE_PITCH + kb + tig]);
        unsigned a2 = f2tf32(sE[(mrow0 + gid)     * SE_PITCH + kb + tig + 4]);
        unsigned a3 = f2tf32(sE[(mrow0 + gid + 8) * SE_PITCH + kb + tig + 4]);
#pragma unroll
        for (int nt = 0; nt < 16; ++nt) {
            unsigned b0 = f2tf32(sW[(kb + tig)     * SW_PITCH + nt * 8 + gid]);
            unsigned b1 = f2tf32(sW[(kb + tig + 4) * SW_PITCH + nt * 8 + gid]);
            asm volatile(
                "mma.sync.aligned.m16n8k8.row.col.f32.tf32.tf32.f32 "
                "{%0,%1,%2,%3}, {%4,%5,%6,%7}, {%8,%9}, {%0,%1,%2,%3};"
                : "+f"(acc[nt][0]), "+f"(acc[nt][1]),
                  "+f"(acc[nt][2]), "+f"(acc[nt][3])
                : "r"(a0), "r"(a1), "r"(a2), "r"(a3), "r"(b0), "r"(b1));
        }
    }

    // Store: c0/c1 -> row (mrow0+gid), cols nt*8+2tig(+1); c2/c3 -> row +8
    const int r0 = n0 + mrow0 + gid;
    const int r1 = r0 + 8;
#pragma unroll
    for (int nt = 0; nt < 16; ++nt) {
        int h2i = (nt & 7) * 4 + tig;   // half2 index within 32-wide row
        __half2 lo = __floats2half2_rn(acc[nt][0], acc[nt][1]);
        __half2 hi = __floats2half2_rn(acc[nt][2], acc[nt][3]);
        __half2* tab = (nt < 8) ? g_A : g_B;
        if (r0 < N) tab[(size_t)r0 * 32 + h2i] = lo;
        if (r1 < N) tab[(size_t)r1 * 32 + h2i] = hi;
    }
}

// ---------------------------------------------------------------------------
// Kernel 2: row histogram over all (edge + random) entries.
// ---------------------------------------------------------------------------
__global__ void hist_kernel(const int* __restrict__ ei,
                            const int* __restrict__ ri, int E, int R) {
    int i = blockIdx.x * blockDim.x + threadIdx.x;
    if (i < E)          atomicAdd(&g_cnt[ei[i]], 1);
    else if (i < E + R) atomicAdd(&g_cnt[ri[i - E]], 1);
}

// ---------------------------------------------------------------------------
// Kernel 3: 8 threads/edge gather + dot, then warp 0 runs the transcendental
// chain for all 32 block edges at full lane occupancy, scatters via cursor.
// ---------------------------------------------------------------------------
__global__ void edge_kernel(const int* __restrict__ ei,
                            const float* __restrict__ b1,
                            const float* __restrict__ W2,
                            const float* __restrict__ b2,
                            const float* __restrict__ eps_u,
                            const float* __restrict__ rb_u,
                            int E) {
    __shared__ float s_logit[32];
    __shared__ int   s_src[32];
    __shared__ int   s_dst[32];

    const int tid = threadIdx.x;
    const int sub = tid & 7;     // thread within edge-group
    const int le  = tid >> 3;    // local edge 0..31
    const int e   = blockIdx.x * 32 + le;

    float p = 0.0f;
    int src = 0, dst = 0;
    if (e < E) {
        src = ei[e];
        dst = ei[E + e];
        const float4* Ap = (const float4*)(g_A + (size_t)src * 32) + sub;
        const float4* Bp = (const float4*)(g_B + (size_t)dst * 32) + sub;
        float4 a4 = *Ap;
        float4 b4 = *Bp;
        const __half2* ah = (const __half2*)&a4;
        const __half2* bh = (const __half2*)&b4;
        const float2* b1p = (const float2*)b1 + sub * 4;
        const float2* w2p = (const float2*)W2 + sub * 4;
#pragma unroll
        for (int q = 0; q < 4; ++q) {
            float2 av = __half22float2(ah[q]);
            float2 bv = __half22float2(bh[q]);
            float2 c1 = b1p[q];
            float2 c2 = w2p[q];
            p += fmaxf(av.x + bv.x + c1.x, 0.0f) * c2.x
               + fmaxf(av.y + bv.y + c1.y, 0.0f) * c2.y;
        }
    }
    p += __shfl_xor_sync(0xffffffffu, p, 4);
    p += __shfl_xor_sync(0xffffffffu, p, 2);
    p += __shfl_xor_sync(0xffffffffu, p, 1);

    if (sub == 0) {
        s_logit[le] = p;
        s_src[le]   = src;
        s_dst[le]   = dst;
    }
    __syncthreads();

    if (tid < 32) {
        int e2 = blockIdx.x * 32 + tid;
        if (e2 < E) {
            float logit = s_logit[tid] + b2[0];
            float eps  = fmaf(-0.9998f, eps_u[e2], 0.9999f);
            float gate = logf(eps) - log1pf(-eps) + logit;
            float w    = 1.0f / (1.0f + expf(-gate));
            float att  = fminf(fmaxf(w, 0.01f), 0.99f);
            float u    = fminf(fmaxf(rb_u[e2], 1e-7f), 1.0f - 1e-7f);
            float sarg = (logf(att) - log1pf(-att) + logf(u) - log1pf(-u))
                         * (1.0f / 0.9f);
            float s    = 1.0f / (1.0f + expf(-sarg));
            // mask = (s > 0) is always 1 in fp32, so mat = s
            int pos = atomicAdd(&g_offs[s_src[tid]], 1);
            g_cols_s[pos] = (unsigned)s_dst[tid];
            g_vals_s[pos] = s;
        }
    }
}

// ---------------------------------------------------------------------------
// Kernel 4: scatter random entries (value 0.05)
// ---------------------------------------------------------------------------
__global__ void rand_kernel(const int* __restrict__ ri, int R) {
    int r = blockIdx.x * blockDim.x + threadIdx.x;
    if (r >= R) return;
    int row = ri[r];
    int col = ri[R + r];
    int pos = atomicAdd(&g_offs[row], 1);
    g_cols_s[pos] = (unsigned)col;
    g_vals_s[pos] = 0.05f;
}

// ---------------------------------------------------------------------------
// Kernel 5: per-row sort by col + coalesce duplicates + write output.
// out layout: [0..M) rows, [M..2M) cols, [2M..3M) vals (float32)
// ---------------------------------------------------------------------------
__global__ void row_sort_kernel(float* __restrict__ out, int M, int NROWS,
                                int vals_only) {
    int r = blockIdx.x * blockDim.x + threadIdx.x;
    if (r >= NROWS) return;
    int cnt = g_cnt[r];
    if (cnt == 0) return;
    int start = g_offs[r] - cnt;

    unsigned lc[32];
    float    lv[32];
    unsigned* c;
    float*    v;
    if (cnt <= 32) {
        for (int j = 0; j < cnt; ++j) {
            lc[j] = g_cols_s[start + j];
            lv[j] = g_vals_s[start + j];
        }
        c = lc; v = lv;
    } else {
        c = &g_cols_s[start];
        v = &g_vals_s[start];
    }

    for (int j = 1; j < cnt; ++j) {
        unsigned ck = c[j];
        float    vk = v[j];
        int k = j - 1;
        while (k >= 0 && c[k] > ck) {
            c[k + 1] = c[k];
            v[k + 1] = v[k];
            --k;
        }
        c[k + 1] = ck;
        v[k + 1] = vk;
    }

    float frow = (float)r;
    int j = 0;
    while (j < cnt) {
        int k = j + 1;
        float s = v[j];
        while (k < cnt && c[k] == c[j]) { s += v[k]; ++k; }
        for (int t = j; t < k; ++t) {
            int   o  = start + t;
            float ov = (t == j) ? s : 0.0f;
            if (vals_only) {
                out[o] = ov;
            } else {
                out[o]         = frow;
                out[M + o]     = (float)c[t];
                out[2 * M + o] = ov;
            }
        }
        j = k;
    }
}

// ---------------------------------------------------------------------------
extern "C" void kernel_launch(void* const* d_in, const int* in_sizes, int n_in,
                              void* d_out, int out_size) {
    const float* emb   = (const float*)d_in[0];
    const float* W1    = (const float*)d_in[1];
    const float* b1    = (const float*)d_in[2];
    const float* W2    = (const float*)d_in[3];
    const float* b2    = (const float*)d_in[4];
    const int*   ei    = (const int*)  d_in[5];
    const int*   ri    = (const int*)  d_in[6];
    const float* eps_u = (const float*)d_in[7];
    const float* rb_u  = (const float*)d_in[8];

    const int N = in_sizes[0] / DD;
    const int E = in_sizes[5] / 2;
    const int R = in_sizes[6] / 2;
    const int M = E + R;

    void *p_cnt, *p_offs, *p_tmp;
    cudaGetSymbolAddress(&p_cnt,  g_cnt);
    cudaGetSymbolAddress(&p_offs, g_offs);
    cudaGetSymbolAddress(&p_tmp,  g_temp);

    // 1) zero row counters
    cudaMemsetAsync(p_cnt, 0, (size_t)N * sizeof(int), (cudaStream_t)0);

    // 2) row histogram from raw indices
    hist_kernel<<<(E + R + 255) / 256, 256>>>(ei, ri, E, R);

    // 3) exclusive scan -> segment offsets (doubles as scatter cursor)
    size_t tb = TEMP_BYTES;
    cub::DeviceScan::ExclusiveSum(p_tmp, tb, (const int*)p_cnt, (int*)p_offs,
                                  N, (cudaStream_t)0);

    // 4) tensor-core node-factored MLP partials (tf32 mma -> fp16 tables)
    cudaFuncSetAttribute(precompute_mma,
                         cudaFuncAttributeMaxDynamicSharedMemorySize, PRE_SMEM);
    precompute_mma<<<(N + 127) / 128, 256, PRE_SMEM>>>(emb, W1, N);

    // 5) per-edge gate values, scattered directly into row segments
    edge_kernel<<<(E + 31) / 32, 256>>>(ei, b1, W2, b2, eps_u, rb_u, E);

    // 6) random entries
    rand_kernel<<<(R + 255) / 256, 256>>>(ri, R);

    // 7) per-row col sort + coalesce + output
    int vals_only = (out_size == M) ? 1 : 0;
    row_sort_kernel<<<(N + 255) / 256, 256>>>((float*)d_out, M, N, vals_only);
}

// round 4
// speedup vs baseline: 2.7051x; 1.0977x over previous
#include <cuda_runtime.h>
#include <cuda_fp16.h>
#include <cstdint>
#include <math.h>
#include <cub/device/device_scan.cuh>

// Problem-fixed sizes (from setup_inputs): N=300000, D=64, E=1000000, R=100000
#define DD 64
static const int    N_MAX = 300032;
static const int    M_MAX = 1200000;
static const size_t TEMP_BYTES = 4u << 20;

// Scratch (device globals — allocation-free per harness rules)
__device__ __align__(16) __half2 g_A[(size_t)N_MAX * 32];   // [N][64] fp16
__device__ __align__(16) __half2 g_B[(size_t)N_MAX * 32];
__device__ int            g_cnt [N_MAX];             // per-row entry count
__device__ int            g_offs[N_MAX + 1];         // exclusive prefix -> cursor
__device__ unsigned       g_cols_s[M_MAX];           // scattered cols (row-grouped)
__device__ float          g_vals_s[M_MAX];           // scattered vals
__device__ unsigned char  g_temp[TEMP_BYTES];        // CUB scan temp

__device__ __forceinline__ unsigned f2tf32(float x) {
    unsigned r;
    asm("cvt.rna.tf32.f32 %0, %1;" : "=r"(r) : "f"(x));
    return r;
}

// ---------------------------------------------------------------------------
// Kernel 1: tensor-core node-factored MLP partials, weights register-resident.
// [A|B][n][jj] = sum_k emb[n][k] * Wcat[jj][k]
//   Wcat[jj]    = W1[jj][0:64]    for jj <  64  -> g_A
//   Wcat[64+j]  = W1[j][64:128]   for j  <  64  -> g_B
// Block 256 thr (8 warps). Warp w owns output cols [w*16, w*16+16).
// B frags (32 regs/warp) loaded once per block; grid-stride over node tiles.
// Node tile in shared, k-permuted so (k, k+4) is one LDS.64.
// ---------------------------------------------------------------------------
#define PITCH 72   // 64 + 8 floats: conflict-free LDS.64 fragment loads

__global__ void precompute_mma(const float* __restrict__ emb,
                               const float* __restrict__ W1,
                               int N, int n_tiles) {
    __shared__ float sE[128 * PITCH];

    const int tid  = threadIdx.x;
    const int warp = tid >> 5;
    const int lane = tid & 31;
    const int gid  = lane >> 2;   // 0..7
    const int tig  = lane & 3;    // 0..3

    // --- B fragments: col = warp*16 + nt*8 + gid, k = kt*8 + tig (+4) ---
    unsigned bf[8][2][2];
#pragma unroll
    for (int nt = 0; nt < 2; ++nt) {
        int c = warp * 16 + nt * 8 + gid;       // 0..127
        const float* wrow = (c < 64) ? (W1 + (size_t)c * 128)
                                     : (W1 + (size_t)(c - 64) * 128 + 64);
#pragma unroll
        for (int kt = 0; kt < 8; ++kt) {
            bf[kt][nt][0] = f2tf32(__ldg(wrow + kt * 8 + tig));
            bf[kt][nt][1] = f2tf32(__ldg(wrow + kt * 8 + tig + 4));
        }
    }

    __half2* tab = (warp < 4) ? g_A : g_B;
    const int cb = (warp * 16) & 63;            // col base within table

    for (int t = blockIdx.x; t < n_tiles; t += gridDim.x) {
        const int n0 = t * 128;
        __syncthreads();
        // Load node tile, k-permuted within each 8-group: [0,4,1,5,2,6,3,7]
        for (int idx = tid; idx < 8192; idx += 256) {
            int ni = idx >> 6;
            int k  = idx & 63;
            int w8 = k & 7;
            int pos = (k & ~7) + ((w8 & 3) * 2 + (w8 >> 2));
            int n  = n0 + ni;
            sE[ni * PITCH + pos] = (n < N) ? emb[(size_t)n * DD + k] : 0.0f;
        }
        __syncthreads();

#pragma unroll
        for (int mt = 0; mt < 8; ++mt) {
            const float* p0 = &sE[(mt * 16 + gid)     * PITCH + 2 * tig];
            const float* p1 = &sE[(mt * 16 + gid + 8) * PITCH + 2 * tig];
            float acc0[4] = {0.f, 0.f, 0.f, 0.f};
            float acc1[4] = {0.f, 0.f, 0.f, 0.f};
#pragma unroll
            for (int kt = 0; kt < 8; ++kt) {
                float2 A0 = *(const float2*)(p0 + kt * 8);
                float2 A1 = *(const float2*)(p1 + kt * 8);
                unsigned a0 = f2tf32(A0.x), a2 = f2tf32(A0.y);
                unsigned a1 = f2tf32(A1.x), a3 = f2tf32(A1.y);
                asm volatile(
                    "mma.sync.aligned.m16n8k8.row.col.f32.tf32.tf32.f32 "
                    "{%0,%1,%2,%3}, {%4,%5,%6,%7}, {%8,%9}, {%0,%1,%2,%3};"
                    : "+f"(acc0[0]), "+f"(acc0[1]), "+f"(acc0[2]), "+f"(acc0[3])
                    : "r"(a0), "r"(a1), "r"(a2), "r"(a3),
                      "r"(bf[kt][0][0]), "r"(bf[kt][0][1]));
                asm volatile(
                    "mma.sync.aligned.m16n8k8.row.col.f32.tf32.tf32.f32 "
                    "{%0,%1,%2,%3}, {%4,%5,%6,%7}, {%8,%9}, {%0,%1,%2,%3};"
                    : "+f"(acc1[0]), "+f"(acc1[1]), "+f"(acc1[2]), "+f"(acc1[3])
                    : "r"(a0), "r"(a1), "r"(a2), "r"(a3),
                      "r"(bf[kt][1][0]), "r"(bf[kt][1][1]));
            }
            // Store: acc0 -> cols cb+2tig(+1), acc1 -> cols cb+8+2tig(+1)
            int r0 = n0 + mt * 16 + gid;
            int r1 = r0 + 8;
            int h0 = (cb >> 1) + tig;       // half2 index in 32-wide row
            int h1 = h0 + 4;
            if (r0 < N) {
                tab[(size_t)r0 * 32 + h0] = __floats2half2_rn(acc0[0], acc0[1]);
                tab[(size_t)r0 * 32 + h1] = __floats2half2_rn(acc1[0], acc1[1]);
            }
            if (r1 < N) {
                tab[(size_t)r1 * 32 + h0] = __floats2half2_rn(acc0[2], acc0[3]);
                tab[(size_t)r1 * 32 + h1] = __floats2half2_rn(acc1[2], acc1[3]);
            }
        }
    }
}

// ---------------------------------------------------------------------------
// Kernel 2: row histogram over all (edge + random) entries.
// ---------------------------------------------------------------------------
__global__ void hist_kernel(const int* __restrict__ ei,
                            const int* __restrict__ ri, int E, int R) {
    int i = blockIdx.x * blockDim.x + threadIdx.x;
    if (i < E)          atomicAdd(&g_cnt[ei[i]], 1);
    else if (i < E + R) atomicAdd(&g_cnt[ri[i - E]], 1);
}

// ---------------------------------------------------------------------------
// Kernel 3: 8 threads/edge gather + dot, then warp 0 runs the transcendental
// chain for all 32 block edges at full lane occupancy, scatters via cursor.
// ---------------------------------------------------------------------------
__global__ void edge_kernel(const int* __restrict__ ei,
                            const float* __restrict__ b1,
                            const float* __restrict__ W2,
                            const float* __restrict__ b2,
                            const float* __restrict__ eps_u,
                            const float* __restrict__ rb_u,
                            int E) {
    __shared__ float s_logit[32];
    __shared__ int   s_src[32];
    __shared__ int   s_dst[32];

    const int tid = threadIdx.x;
    const int sub = tid & 7;
    const int le  = tid >> 3;
    const int e   = blockIdx.x * 32 + le;

    float p = 0.0f;
    int src = 0, dst = 0;
    if (e < E) {
        src = ei[e];
        dst = ei[E + e];
        const float4* Ap = (const float4*)(g_A + (size_t)src * 32) + sub;
        const float4* Bp = (const float4*)(g_B + (size_t)dst * 32) + sub;
        float4 a4 = *Ap;
        float4 b4 = *Bp;
        const __half2* ah = (const __half2*)&a4;
        const __half2* bh = (const __half2*)&b4;
        const float2* b1p = (const float2*)b1 + sub * 4;
        const float2* w2p = (const float2*)W2 + sub * 4;
#pragma unroll
        for (int q = 0; q < 4; ++q) {
            float2 av = __half22float2(ah[q]);
            float2 bv = __half22float2(bh[q]);
            float2 c1 = b1p[q];
            float2 c2 = w2p[q];
            p += fmaxf(av.x + bv.x + c1.x, 0.0f) * c2.x
               + fmaxf(av.y + bv.y + c1.y, 0.0f) * c2.y;
        }
    }
    p += __shfl_xor_sync(0xffffffffu, p, 4);
    p += __shfl_xor_sync(0xffffffffu, p, 2);
    p += __shfl_xor_sync(0xffffffffu, p, 1);

    if (sub == 0) {
        s_logit[le] = p;
        s_src[le]   = src;
        s_dst[le]   = dst;
    }
    __syncthreads();

    if (tid < 32) {
        int e2 = blockIdx.x * 32 + tid;
        if (e2 < E) {
            float logit = s_logit[tid] + b2[0];
            float eps  = fmaf(-0.9998f, eps_u[e2], 0.9999f);
            float gate = logf(eps) - log1pf(-eps) + logit;
            float w    = 1.0f / (1.0f + expf(-gate));
            float att  = fminf(fmaxf(w, 0.01f), 0.99f);
            float u    = fminf(fmaxf(rb_u[e2], 1e-7f), 1.0f - 1e-7f);
            float sarg = (logf(att) - log1pf(-att) + logf(u) - log1pf(-u))
                         * (1.0f / 0.9f);
            float s    = 1.0f / (1.0f + expf(-sarg));
            int pos = atomicAdd(&g_offs[s_src[tid]], 1);
            g_cols_s[pos] = (unsigned)s_dst[tid];
            g_vals_s[pos] = s;
        }
    }
}

// ---------------------------------------------------------------------------
// Kernel 4: scatter random entries (value 0.05)
// ---------------------------------------------------------------------------
__global__ void rand_kernel(const int* __restrict__ ri, int R) {
    int r = blockIdx.x * blockDim.x + threadIdx.x;
    if (r >= R) return;
    int row = ri[r];
    int col = ri[R + r];
    int pos = atomicAdd(&g_offs[row], 1);
    g_cols_s[pos] = (unsigned)col;
    g_vals_s[pos] = 0.05f;
}

// ---------------------------------------------------------------------------
// Kernel 5: per-row sort by col + coalesce duplicates + write output.
// out layout: [0..M) rows, [M..2M) cols, [2M..3M) vals (float32)
// ---------------------------------------------------------------------------
__global__ void row_sort_kernel(float* __restrict__ out, int M, int NROWS,
                                int vals_only) {
    int r = blockIdx.x * blockDim.x + threadIdx.x;
    if (r >= NROWS) return;
    int cnt = g_cnt[r];
    if (cnt == 0) return;
    int start = g_offs[r] - cnt;

    unsigned lc[32];
    float    lv[32];
    unsigned* c;
    float*    v;
    if (cnt <= 32) {
        for (int j = 0; j < cnt; ++j) {
            lc[j] = g_cols_s[start + j];
            lv[j] = g_vals_s[start + j];
        }
        c = lc; v = lv;
    } else {
        c = &g_cols_s[start];
        v = &g_vals_s[start];
    }

    for (int j = 1; j < cnt; ++j) {
        unsigned ck = c[j];
        float    vk = v[j];
        int k = j - 1;
        while (k >= 0 && c[k] > ck) {
            c[k + 1] = c[k];
            v[k + 1] = v[k];
            --k;
        }
        c[k + 1] = ck;
        v[k + 1] = vk;
    }

    float frow = (float)r;
    int j = 0;
    while (j < cnt) {
        int k = j + 1;
        float s = v[j];
        while (k < cnt && c[k] == c[j]) { s += v[k]; ++k; }
        for (int t = j; t < k; ++t) {
            int   o  = start + t;
            float ov = (t == j) ? s : 0.0f;
            if (vals_only) {
                out[o] = ov;
            } else {
                out[o]         = frow;
                out[M + o]     = (float)c[t];
                out[2 * M + o] = ov;
            }
        }
        j = k;
    }
}

// ---------------------------------------------------------------------------
extern "C" void kernel_launch(void* const* d_in, const int* in_sizes, int n_in,
                              void* d_out, int out_size) {
    const float* emb   = (const float*)d_in[0];
    const float* W1    = (const float*)d_in[1];
    const float* b1    = (const float*)d_in[2];
    const float* W2    = (const float*)d_in[3];
    const float* b2    = (const float*)d_in[4];
    const int*   ei    = (const int*)  d_in[5];
    const int*   ri    = (const int*)  d_in[6];
    const float* eps_u = (const float*)d_in[7];
    const float* rb_u  = (const float*)d_in[8];

    const int N = in_sizes[0] / DD;
    const int E = in_sizes[5] / 2;
    const int R = in_sizes[6] / 2;
    const int M = E + R;

    void *p_cnt, *p_offs, *p_tmp;
    cudaGetSymbolAddress(&p_cnt,  g_cnt);
    cudaGetSymbolAddress(&p_offs, g_offs);
    cudaGetSymbolAddress(&p_tmp,  g_temp);

    // 1) zero row counters
    cudaMemsetAsync(p_cnt, 0, (size_t)N * sizeof(int), (cudaStream_t)0);

    // 2) row histogram from raw indices
    hist_kernel<<<(E + R + 255) / 256, 256>>>(ei, ri, E, R);

    // 3) exclusive scan -> segment offsets (doubles as scatter cursor)
    size_t tb = TEMP_BYTES;
    cub::DeviceScan::ExclusiveSum(p_tmp, tb, (const int*)p_cnt, (int*)p_offs,
                                  N, (cudaStream_t)0);

    // 4) tensor-core node-factored MLP partials (tf32 mma -> fp16 tables)
    int n_tiles = (N + 127) / 128;
    int grid = 148 * 4;
    if (grid > n_tiles) grid = n_tiles;
    precompute_mma<<<grid, 256>>>(emb, W1, N, n_tiles);

    // 5) per-edge gate values, scattered directly into row segments
    edge_kernel<<<(E + 31) / 32, 256>>>(ei, b1, W2, b2, eps_u, rb_u, E);

    // 6) random entries
    rand_kernel<<<(R + 255) / 256, 256>>>(ri, R);

    // 7) per-row col sort + coalesce + output
    int vals_only = (out_size == M) ? 1 : 0;
    row_sort_kernel<<<(N + 255) / 256, 256>>>((float*)d_out, M, N, vals_only);
}

// round 5
// speedup vs baseline: 3.0812x; 1.1390x over previous
#include <cuda_runtime.h>
#include <cuda_fp16.h>
#include <cstdint>
#include <math.h>
#include <cub/device/device_scan.cuh>

// Problem-fixed sizes (from setup_inputs): N=300000, D=64, E=1000000, R=100000
#define DD 64
static const int    N_MAX = 300032;
static const int    M_MAX = 1200000;
static const size_t TEMP_BYTES = 4u << 20;

// Scratch (device globals — allocation-free per harness rules)
__device__ __align__(16) __half2 g_A[(size_t)N_MAX * 32];   // [N][64] fp16 (b1 folded in)
__device__ __align__(16) __half2 g_B[(size_t)N_MAX * 32];
__device__ int            g_cnt [N_MAX];             // per-row entry count
__device__ int            g_offs[N_MAX + 1];         // exclusive prefix -> cursor
__device__ unsigned       g_cols_s[M_MAX];           // scattered cols (row-grouped)
__device__ float          g_vals_s[M_MAX];           // scattered vals
__device__ unsigned char  g_temp[TEMP_BYTES];        // CUB scan temp

// ---------------------------------------------------------------------------
// Kernel 1: fp16 tensor-core node-factored MLP partials, weights in registers.
// [A|B][n][jj] = sum_k emb[n][k] * Wcat[jj][k]  (+ b1[jj] folded into A)
//   Wcat[jj]   = W1[jj][0:64]   jj<64  -> g_A
//   Wcat[64+j] = W1[j][64:128]  j<64   -> g_B
// mma.m16n8k16.f16 (fp32 accum). Block 256 thr (8 warps); warp w owns cols
// [w*16, w*16+16). B frags: 16 half2 regs loaded once; grid-stride node tiles.
// Tile in shared as half2, pitch 36 -> fragment LDS.32 banks (4*gid+tig)%32
// all distinct (conflict-free).
// ---------------------------------------------------------------------------
#define PITCH2 36   // half2 pitch per row

__global__ void precompute_mma(const float* __restrict__ emb,
                               const float* __restrict__ W1,
                               const float* __restrict__ b1,
                               int N, int n_tiles) {
    __shared__ __half2 sE[128 * PITCH2];

    const int tid  = threadIdx.x;
    const int warp = tid >> 5;
    const int lane = tid & 31;
    const int gid  = lane >> 2;   // 0..7
    const int tig  = lane & 3;    // 0..3

    // --- B fragments: col c = warp*16 + nt*8 + gid ---
    // b0: k = 2tig,2tig+1 ; b1: k = 2tig+8,2tig+9 (within k16 chunk kt)
    unsigned bf[4][2][2];
#pragma unroll
    for (int nt = 0; nt < 2; ++nt) {
        int c = warp * 16 + nt * 8 + gid;       // 0..127
        const float* wrow = (c < 64) ? (W1 + (size_t)c * 128)
                                     : (W1 + (size_t)(c - 64) * 128 + 64);
#pragma unroll
        for (int kt = 0; kt < 4; ++kt) {
            __half2 lo = __floats2half2_rn(__ldg(wrow + kt * 16 + 2 * tig),
                                           __ldg(wrow + kt * 16 + 2 * tig + 1));
            __half2 hi = __floats2half2_rn(__ldg(wrow + kt * 16 + 2 * tig + 8),
                                           __ldg(wrow + kt * 16 + 2 * tig + 9));
            bf[kt][nt][0] = *(unsigned*)&lo;
            bf[kt][nt][1] = *(unsigned*)&hi;
        }
    }

    __half2* tab = (warp < 4) ? g_A : g_B;
    const int cb = (warp * 16) & 63;            // col base within table

    // b1 folded into A-table columns only
    float b1v[2][2] = {{0.f, 0.f}, {0.f, 0.f}};
    if (warp < 4) {
        b1v[0][0] = __ldg(b1 + cb + 2 * tig);
        b1v[0][1] = __ldg(b1 + cb + 2 * tig + 1);
        b1v[1][0] = __ldg(b1 + cb + 8 + 2 * tig);
        b1v[1][1] = __ldg(b1 + cb + 8 + 2 * tig + 1);
    }

    for (int t = blockIdx.x; t < n_tiles; t += gridDim.x) {
        const int n0 = t * 128;
        __syncthreads();
        // Load 128x64 tile as half2 (4096 half2), coalesced float2 reads
        for (int idx = tid; idx < 4096; idx += 256) {
            int ni = idx >> 5;
            int h  = idx & 31;
            int n  = n0 + ni;
            float2 f = (n < N) ? ((const float2*)(emb + (size_t)n * DD))[h]
                               : make_float2(0.f, 0.f);
            sE[ni * PITCH2 + h] = __floats2half2_rn(f.x, f.y);
        }
        __syncthreads();

#pragma unroll
        for (int mt = 0; mt < 8; ++mt) {
            const __half2* p0 = &sE[(mt * 16 + gid)     * PITCH2];
            const __half2* p1 = &sE[(mt * 16 + gid + 8) * PITCH2];
            float acc0[4] = {0.f, 0.f, 0.f, 0.f};
            float acc1[4] = {0.f, 0.f, 0.f, 0.f};
#pragma unroll
            for (int kt = 0; kt < 4; ++kt) {
                unsigned a0 = *(const unsigned*)&p0[kt * 8 + tig];
                unsigned a1 = *(const unsigned*)&p1[kt * 8 + tig];
                unsigned a2 = *(const unsigned*)&p0[kt * 8 + tig + 4];
                unsigned a3 = *(const unsigned*)&p1[kt * 8 + tig + 4];
                asm volatile(
                    "mma.sync.aligned.m16n8k16.row.col.f32.f16.f16.f32 "
                    "{%0,%1,%2,%3}, {%4,%5,%6,%7}, {%8,%9}, {%0,%1,%2,%3};"
                    : "+f"(acc0[0]), "+f"(acc0[1]), "+f"(acc0[2]), "+f"(acc0[3])
                    : "r"(a0), "r"(a1), "r"(a2), "r"(a3),
                      "r"(bf[kt][0][0]), "r"(bf[kt][0][1]));
                asm volatile(
                    "mma.sync.aligned.m16n8k16.row.col.f32.f16.f16.f32 "
                    "{%0,%1,%2,%3}, {%4,%5,%6,%7}, {%8,%9}, {%0,%1,%2,%3};"
                    : "+f"(acc1[0]), "+f"(acc1[1]), "+f"(acc1[2]), "+f"(acc1[3])
                    : "r"(a0), "r"(a1), "r"(a2), "r"(a3),
                      "r"(bf[kt][1][0]), "r"(bf[kt][1][1]));
            }
            int r0 = n0 + mt * 16 + gid;
            int r1 = r0 + 8;
            int h0 = (cb >> 1) + tig;       // half2 index in 32-wide row
            int h1 = h0 + 4;
            if (r0 < N) {
                tab[(size_t)r0 * 32 + h0] =
                    __floats2half2_rn(acc0[0] + b1v[0][0], acc0[1] + b1v[0][1]);
                tab[(size_t)r0 * 32 + h1] =
                    __floats2half2_rn(acc1[0] + b1v[1][0], acc1[1] + b1v[1][1]);
            }
            if (r1 < N) {
                tab[(size_t)r1 * 32 + h0] =
                    __floats2half2_rn(acc0[2] + b1v[0][0], acc0[3] + b1v[0][1]);
                tab[(size_t)r1 * 32 + h1] =
                    __floats2half2_rn(acc1[2] + b1v[1][0], acc1[3] + b1v[1][1]);
            }
        }
    }
}

// ---------------------------------------------------------------------------
// Kernel 2: row histogram over all (edge + random) entries.
// ---------------------------------------------------------------------------
__global__ void hist_kernel(const int* __restrict__ ei,
                            const int* __restrict__ ri, int E, int R) {
    int i = blockIdx.x * blockDim.x + threadIdx.x;
    if (i < E)          atomicAdd(&g_cnt[ei[i]], 1);
    else if (i < E + R) atomicAdd(&g_cnt[ri[i - E]], 1);
}

// ---------------------------------------------------------------------------
// Kernel 3: 8 threads/edge gather + dot (b1 already folded into g_A), then
// warp 0 runs the transcendental chain for all 32 block edges.
// ---------------------------------------------------------------------------
__global__ void edge_kernel(const int* __restrict__ ei,
                            const float* __restrict__ W2,
                            const float* __restrict__ b2,
                            const float* __restrict__ eps_u,
                            const float* __restrict__ rb_u,
                            int E) {
    __shared__ float s_logit[32];
    __shared__ int   s_src[32];
    __shared__ int   s_dst[32];

    const int tid = threadIdx.x;
    const int sub = tid & 7;
    const int le  = tid >> 3;
    const int e   = blockIdx.x * 32 + le;

    float p = 0.0f;
    int src = 0, dst = 0;
    if (e < E) {
        src = ei[e];
        dst = ei[E + e];
        const float4* Ap = (const float4*)(g_A + (size_t)src * 32) + sub;
        const float4* Bp = (const float4*)(g_B + (size_t)dst * 32) + sub;
        float4 a4 = *Ap;
        float4 b4 = *Bp;
        const __half2* ah = (const __half2*)&a4;
        const __half2* bh = (const __half2*)&b4;
        const float2* w2p = (const float2*)W2 + sub * 4;
#pragma unroll
        for (int q = 0; q < 4; ++q) {
            float2 av = __half22float2(ah[q]);
            float2 bv = __half22float2(bh[q]);
            float2 c2 = w2p[q];
            p += fmaxf(av.x + bv.x, 0.0f) * c2.x
               + fmaxf(av.y + bv.y, 0.0f) * c2.y;
        }
    }
    p += __shfl_xor_sync(0xffffffffu, p, 4);
    p += __shfl_xor_sync(0xffffffffu, p, 2);
    p += __shfl_xor_sync(0xffffffffu, p, 1);

    if (sub == 0) {
        s_logit[le] = p;
        s_src[le]   = src;
        s_dst[le]   = dst;
    }
    __syncthreads();

    if (tid < 32) {
        int e2 = blockIdx.x * 32 + tid;
        if (e2 < E) {
            float logit = s_logit[tid] + b2[0];
            float eps  = fmaf(-0.9998f, eps_u[e2], 0.9999f);
            float gate = logf(eps) - log1pf(-eps) + logit;
            float w    = 1.0f / (1.0f + expf(-gate));
            float att  = fminf(fmaxf(w, 0.01f), 0.99f);
            float u    = fminf(fmaxf(rb_u[e2], 1e-7f), 1.0f - 1e-7f);
            float sarg = (logf(att) - log1pf(-att) + logf(u) - log1pf(-u))
                         * (1.0f / 0.9f);
            float s    = 1.0f / (1.0f + expf(-sarg));
            int pos = atomicAdd(&g_offs[s_src[tid]], 1);
            g_cols_s[pos] = (unsigned)s_dst[tid];
            g_vals_s[pos] = s;
        }
    }
}

// ---------------------------------------------------------------------------
// Kernel 4: scatter random entries (value 0.05)
// ---------------------------------------------------------------------------
__global__ void rand_kernel(const int* __restrict__ ri, int R) {
    int r = blockIdx.x * blockDim.x + threadIdx.x;
    if (r >= R) return;
    int row = ri[r];
    int col = ri[R + r];
    int pos = atomicAdd(&g_offs[row], 1);
    g_cols_s[pos] = (unsigned)col;
    g_vals_s[pos] = 0.05f;
}

// ---------------------------------------------------------------------------
// Kernel 5: per-row sort by col + coalesce duplicates + write output.
// out layout: [0..M) rows, [M..2M) cols, [2M..3M) vals (float32)
// ---------------------------------------------------------------------------
__global__ void row_sort_kernel(float* __restrict__ out, int M, int NROWS,
                                int vals_only) {
    int r = blockIdx.x * blockDim.x + threadIdx.x;
    if (r >= NROWS) return;
    int cnt = g_cnt[r];
    if (cnt == 0) return;
    int start = g_offs[r] - cnt;

    unsigned lc[32];
    float    lv[32];
    unsigned* c;
    float*    v;
    if (cnt <= 32) {
        for (int j = 0; j < cnt; ++j) {
            lc[j] = g_cols_s[start + j];
            lv[j] = g_vals_s[start + j];
        }
        c = lc; v = lv;
    } else {
        c = &g_cols_s[start];
        v = &g_vals_s[start];
    }

    for (int j = 1; j < cnt; ++j) {
        unsigned ck = c[j];
        float    vk = v[j];
        int k = j - 1;
        while (k >= 0 && c[k] > ck) {
            c[k + 1] = c[k];
            v[k + 1] = v[k];
            --k;
        }
        c[k + 1] = ck;
        v[k + 1] = vk;
    }

    float frow = (float)r;
    int j = 0;
    while (j < cnt) {
        int k = j + 1;
        float s = v[j];
        while (k < cnt && c[k] == c[j]) { s += v[k]; ++k; }
        for (int t = j; t < k; ++t) {
            int   o  = start + t;
            float ov = (t == j) ? s : 0.0f;
            if (vals_only) {
                out[o] = ov;
            } else {
                out[o]         = frow;
                out[M + o]     = (float)c[t];
                out[2 * M + o] = ov;
            }
        }
        j = k;
    }
}

// ---------------------------------------------------------------------------
extern "C" void kernel_launch(void* const* d_in, const int* in_sizes, int n_in,
                              void* d_out, int out_size) {
    const float* emb   = (const float*)d_in[0];
    const float* W1    = (const float*)d_in[1];
    const float* b1    = (const float*)d_in[2];
    const float* W2    = (const float*)d_in[3];
    const float* b2    = (const float*)d_in[4];
    const int*   ei    = (const int*)  d_in[5];
    const int*   ri    = (const int*)  d_in[6];
    const float* eps_u = (const float*)d_in[7];
    const float* rb_u  = (const float*)d_in[8];

    const int N = in_sizes[0] / DD;
    const int E = in_sizes[5] / 2;
    const int R = in_sizes[6] / 2;
    const int M = E + R;

    void *p_cnt, *p_offs, *p_tmp;
    cudaGetSymbolAddress(&p_cnt,  g_cnt);
    cudaGetSymbolAddress(&p_offs, g_offs);
    cudaGetSymbolAddress(&p_tmp,  g_temp);

    // 1) zero row counters
    cudaMemsetAsync(p_cnt, 0, (size_t)N * sizeof(int), (cudaStream_t)0);

    // 2) row histogram from raw indices
    hist_kernel<<<(E + R + 255) / 256, 256>>>(ei, ri, E, R);

    // 3) exclusive scan -> segment offsets (doubles as scatter cursor)
    size_t tb = TEMP_BYTES;
    cub::DeviceScan::ExclusiveSum(p_tmp, tb, (const int*)p_cnt, (int*)p_offs,
                                  N, (cudaStream_t)0);

    // 4) fp16 tensor-core node-factored MLP partials
    int n_tiles = (N + 127) / 128;
    int grid = 148 * 8;
    if (grid > n_tiles) grid = n_tiles;
    precompute_mma<<<grid, 256>>>(emb, W1, b1, N, n_tiles);

    // 5) per-edge gate values, scattered directly into row segments
    edge_kernel<<<(E + 31) / 32, 256>>>(ei, W2, b2, eps_u, rb_u, E);

    // 6) random entries
    rand_kernel<<<(R + 255) / 256, 256>>>(ri, R);

    // 7) per-row col sort + coalesce + output
    int vals_only = (out_size == M) ? 1 : 0;
    row_sort_kernel<<<(N + 255) / 256, 256>>>((float*)d_out, M, N, vals_only);
}

// round 6
// speedup vs baseline: 3.1903x; 1.0354x over previous
#include <cuda_runtime.h>
#include <cuda_fp16.h>
#include <cstdint>
#include <math.h>
#include <cub/device/device_scan.cuh>

// Problem-fixed sizes (from setup_inputs): N=300000, D=64, E=1000000, R=100000
#define DD 64
static const int    N_MAX = 300032;
static const int    M_MAX = 1200000;
static const size_t TEMP_BYTES = 4u << 20;

// Scratch (device globals — allocation-free per harness rules)
__device__ __align__(16) __half2 g_A[(size_t)N_MAX * 32];   // [N][64] fp16 (b1 folded)
__device__ __align__(16) __half2 g_B[(size_t)N_MAX * 32];
__device__ int            g_cnt [N_MAX];             // per-row entry count
__device__ int            g_offs[N_MAX + 1];         // exclusive prefix -> cursor
__device__ unsigned       g_cols_s[M_MAX];           // scattered cols (row-grouped)
__device__ float          g_vals_s[M_MAX];           // scattered vals
__device__ unsigned char  g_temp[TEMP_BYTES];        // CUB scan temp

// ---------------------------------------------------------------------------
// Kernel 1: fp16 tensor-core node-factored MLP partials.
// Warp = (row-group mg, table T). Each warp computes ALL 64 columns of table
// T for its 16 rows -> owns full 128B output rows -> STG.128 epilogue via
// conflict-free smem staging. Weights register-resident (64 regs/warp).
// Tile = 32 rows/block (4 warps). mma.m16n8k16.f16, fp32 accum.
// ---------------------------------------------------------------------------
#define PITCH2 36   // half2 pitch: fragment LDS banks (4*gid+tig)%32 distinct

__global__ void __launch_bounds__(128, 3)
precompute_mma(const float* __restrict__ emb,
               const float* __restrict__ W1,
               const float* __restrict__ b1,
               int N, int n_tiles) {
    __shared__ __align__(16) __half2 sE[32 * PITCH2];
    __shared__ __align__(16) __half2 sStage[4][16 * PITCH2];

    const int tid  = threadIdx.x;
    const int warp = tid >> 5;
    const int lane = tid & 31;
    const int gid  = lane >> 2;   // 0..7
    const int tig  = lane & 3;    // 0..3
    const int T    = warp & 1;    // 0 -> g_A (W1 left), 1 -> g_B (W1 right)
    const int base = (warp >> 1) * 16;

    // Weight fragments: col j = nt*8+gid of table T; k pairs per k16 chunk kt.
    unsigned bf[4][8][2];
    float2   b1v[8];
#pragma unroll
    for (int nt = 0; nt < 8; ++nt) {
        int c = nt * 8 + gid;
        const float* wrow = W1 + (size_t)c * 128 + (T ? 64 : 0);
#pragma unroll
        for (int kt = 0; kt < 4; ++kt) {
            __half2 lo = __floats2half2_rn(__ldg(wrow + kt * 16 + 2 * tig),
                                           __ldg(wrow + kt * 16 + 2 * tig + 1));
            __half2 hi = __floats2half2_rn(__ldg(wrow + kt * 16 + 2 * tig + 8),
                                           __ldg(wrow + kt * 16 + 2 * tig + 9));
            bf[kt][nt][0] = *(unsigned*)&lo;
            bf[kt][nt][1] = *(unsigned*)&hi;
        }
        b1v[nt] = T ? make_float2(0.f, 0.f)
                    : __ldg((const float2*)b1 + nt * 4 + tig);
    }

    __half2* tab = T ? g_B : g_A;
    __half2* st  = &sStage[warp][0];

    for (int t = blockIdx.x; t < n_tiles; t += gridDim.x) {
        const int n0 = t * 32;
        __syncthreads();
        // Load 32x64 emb tile as half2 (1024 half2), coalesced float2 reads
        for (int idx = tid; idx < 1024; idx += 128) {
            int ni = idx >> 5;
            int h  = idx & 31;
            int n  = n0 + ni;
            float2 f = (n < N) ? ((const float2*)(emb + (size_t)n * DD))[h]
                               : make_float2(0.f, 0.f);
            sE[ni * PITCH2 + h] = __floats2half2_rn(f.x, f.y);
        }
        __syncthreads();

        const __half2* p0 = &sE[(base + gid)     * PITCH2];
        const __half2* p1 = &sE[(base + gid + 8) * PITCH2];

        float acc[8][4];
#pragma unroll
        for (int nt = 0; nt < 8; ++nt)
#pragma unroll
            for (int c = 0; c < 4; ++c) acc[nt][c] = 0.f;

#pragma unroll
        for (int kt = 0; kt < 4; ++kt) {
            unsigned a0 = *(const unsigned*)&p0[kt * 8 + tig];
            unsigned a1 = *(const unsigned*)&p1[kt * 8 + tig];
            unsigned a2 = *(const unsigned*)&p0[kt * 8 + tig + 4];
            unsigned a3 = *(const unsigned*)&p1[kt * 8 + tig + 4];
#pragma unroll
            for (int nt = 0; nt < 8; ++nt) {
                asm volatile(
                    "mma.sync.aligned.m16n8k16.row.col.f32.f16.f16.f32 "
                    "{%0,%1,%2,%3}, {%4,%5,%6,%7}, {%8,%9}, {%0,%1,%2,%3};"
                    : "+f"(acc[nt][0]), "+f"(acc[nt][1]),
                      "+f"(acc[nt][2]), "+f"(acc[nt][3])
                    : "r"(a0), "r"(a1), "r"(a2), "r"(a3),
                      "r"(bf[kt][nt][0]), "r"(bf[kt][nt][1]));
            }
        }

        // Stage: row gid gets (acc0,acc1), row gid+8 gets (acc2,acc3);
        // half2 col index 4nt+tig. Banks (4gid+tig+4nt)%32 distinct.
#pragma unroll
        for (int nt = 0; nt < 8; ++nt) {
            float2 bb = b1v[nt];
            st[gid * PITCH2 + nt * 4 + tig] =
                __floats2half2_rn(acc[nt][0] + bb.x, acc[nt][1] + bb.y);
            st[(gid + 8) * PITCH2 + nt * 4 + tig] =
                __floats2half2_rn(acc[nt][2] + bb.x, acc[nt][3] + bb.y);
        }
        __syncwarp();

        // Coalesced write: 4 iters, each lane 16B; 4 full 128B rows per instr.
#pragma unroll
        for (int i = 0; i < 4; ++i) {
            int r = i * 4 + (lane >> 3);
            int c = lane & 7;
            int n = n0 + base + r;
            if (n < N) {
                float4 v = *(const float4*)((const char*)st + r * (PITCH2 * 4) + c * 16);
                *(float4*)((char*)(tab + (size_t)n * 32) + c * 16) = v;
            }
        }
        __syncwarp();
    }
}

// ---------------------------------------------------------------------------
// Kernel 2: row histogram over all (edge + random) entries.
// ---------------------------------------------------------------------------
__global__ void hist_kernel(const int* __restrict__ ei,
                            const int* __restrict__ ri, int E, int R) {
    int i = blockIdx.x * blockDim.x + threadIdx.x;
    if (i < E)          atomicAdd(&g_cnt[ei[i]], 1);
    else if (i < E + R) atomicAdd(&g_cnt[ri[i - E]], 1);
}

// ---------------------------------------------------------------------------
// Kernel 3: 8 threads/edge gather + dot (b1 folded into g_A), then warp 0
// runs the transcendental chain for all 32 block edges, scatters via cursor.
// ---------------------------------------------------------------------------
__global__ void edge_kernel(const int* __restrict__ ei,
                            const float* __restrict__ W2,
                            const float* __restrict__ b2,
                            const float* __restrict__ eps_u,
                            const float* __restrict__ rb_u,
                            int E) {
    __shared__ float s_logit[32];
    __shared__ int   s_src[32];
    __shared__ int   s_dst[32];

    const int tid = threadIdx.x;
    const int sub = tid & 7;
    const int le  = tid >> 3;
    const int e   = blockIdx.x * 32 + le;

    float p = 0.0f;
    int src = 0, dst = 0;
    if (e < E) {
        src = ei[e];
        dst = ei[E + e];
        const float4* Ap = (const float4*)(g_A + (size_t)src * 32) + sub;
        const float4* Bp = (const float4*)(g_B + (size_t)dst * 32) + sub;
        float4 a4 = *Ap;
        float4 b4 = *Bp;
        const __half2* ah = (const __half2*)&a4;
        const __half2* bh = (const __half2*)&b4;
        const float2* w2p = (const float2*)W2 + sub * 4;
#pragma unroll
        for (int q = 0; q < 4; ++q) {
            float2 av = __half22float2(ah[q]);
            float2 bv = __half22float2(bh[q]);
            float2 c2 = w2p[q];
            p += fmaxf(av.x + bv.x, 0.0f) * c2.x
               + fmaxf(av.y + bv.y, 0.0f) * c2.y;
        }
    }
    p += __shfl_xor_sync(0xffffffffu, p, 4);
    p += __shfl_xor_sync(0xffffffffu, p, 2);
    p += __shfl_xor_sync(0xffffffffu, p, 1);

    if (sub == 0) {
        s_logit[le] = p;
        s_src[le]   = src;
        s_dst[le]   = dst;
    }
    __syncthreads();

    if (tid < 32) {
        int e2 = blockIdx.x * 32 + tid;
        if (e2 < E) {
            float logit = s_logit[tid] + b2[0];
            float eps  = fmaf(-0.9998f, eps_u[e2], 0.9999f);
            float gate = logf(eps) - log1pf(-eps) + logit;
            float w    = 1.0f / (1.0f + expf(-gate));
            float att  = fminf(fmaxf(w, 0.01f), 0.99f);
            float u    = fminf(fmaxf(rb_u[e2], 1e-7f), 1.0f - 1e-7f);
            float sarg = (logf(att) - log1pf(-att) + logf(u) - log1pf(-u))
                         * (1.0f / 0.9f);
            float s    = 1.0f / (1.0f + expf(-sarg));
            int pos = atomicAdd(&g_offs[s_src[tid]], 1);
            g_cols_s[pos] = (unsigned)s_dst[tid];
            g_vals_s[pos] = s;
        }
    }
}

// ---------------------------------------------------------------------------
// Kernel 4: scatter random entries (value 0.05)
// ---------------------------------------------------------------------------
__global__ void rand_kernel(const int* __restrict__ ri, int R) {
    int r = blockIdx.x * blockDim.x + threadIdx.x;
    if (r >= R) return;
    int row = ri[r];
    int col = ri[R + r];
    int pos = atomicAdd(&g_offs[row], 1);
    g_cols_s[pos] = (unsigned)col;
    g_vals_s[pos] = 0.05f;
}

// ---------------------------------------------------------------------------
// Kernel 5: per-row sort by col + coalesce duplicates + write output.
// out layout: [0..M) rows, [M..2M) cols, [2M..3M) vals (float32)
// ---------------------------------------------------------------------------
__global__ void row_sort_kernel(float* __restrict__ out, int M, int NROWS,
                                int vals_only) {
    int r = blockIdx.x * blockDim.x + threadIdx.x;
    if (r >= NROWS) return;
    int cnt = g_cnt[r];
    if (cnt == 0) return;
    int start = g_offs[r] - cnt;

    unsigned lc[32];
    float    lv[32];
    unsigned* c;
    float*    v;
    if (cnt <= 32) {
        for (int j = 0; j < cnt; ++j) {
            lc[j] = g_cols_s[start + j];
            lv[j] = g_vals_s[start + j];
        }
        c = lc; v = lv;
    } else {
        c = &g_cols_s[start];
        v = &g_vals_s[start];
    }

    for (int j = 1; j < cnt; ++j) {
        unsigned ck = c[j];
        float    vk = v[j];
        int k = j - 1;
        while (k >= 0 && c[k] > ck) {
            c[k + 1] = c[k];
            v[k + 1] = v[k];
            --k;
        }
        c[k + 1] = ck;
        v[k + 1] = vk;
    }

    float frow = (float)r;
    int j = 0;
    while (j < cnt) {
        int k = j + 1;
        float s = v[j];
        while (k < cnt && c[k] == c[j]) { s += v[k]; ++k; }
        for (int t = j; t < k; ++t) {
            int   o  = start + t;
            float ov = (t == j) ? s : 0.0f;
            if (vals_only) {
                out[o] = ov;
            } else {
                out[o]         = frow;
                out[M + o]     = (float)c[t];
                out[2 * M + o] = ov;
            }
        }
        j = k;
    }
}

// ---------------------------------------------------------------------------
extern "C" void kernel_launch(void* const* d_in, const int* in_sizes, int n_in,
                              void* d_out, int out_size) {
    const float* emb   = (const float*)d_in[0];
    const float* W1    = (const float*)d_in[1];
    const float* b1    = (const float*)d_in[2];
    const float* W2    = (const float*)d_in[3];
    const float* b2    = (const float*)d_in[4];
    const int*   ei    = (const int*)  d_in[5];
    const int*   ri    = (const int*)  d_in[6];
    const float* eps_u = (const float*)d_in[7];
    const float* rb_u  = (const float*)d_in[8];

    const int N = in_sizes[0] / DD;
    const int E = in_sizes[5] / 2;
    const int R = in_sizes[6] / 2;
    const int M = E + R;

    void *p_cnt, *p_offs, *p_tmp;
    cudaGetSymbolAddress(&p_cnt,  g_cnt);
    cudaGetSymbolAddress(&p_offs, g_offs);
    cudaGetSymbolAddress(&p_tmp,  g_temp);

    // 1) zero row counters
    cudaMemsetAsync(p_cnt, 0, (size_t)N * sizeof(int), (cudaStream_t)0);

    // 2) row histogram from raw indices
    hist_kernel<<<(E + R + 255) / 256, 256>>>(ei, ri, E, R);

    // 3) exclusive scan -> segment offsets (doubles as scatter cursor)
    size_t tb = TEMP_BYTES;
    cub::DeviceScan::ExclusiveSum(p_tmp, tb, (const int*)p_cnt, (int*)p_offs,
                                  N, (cudaStream_t)0);

    // 4) fp16 tensor-core node-factored MLP partials
    int n_tiles = (N + 31) / 32;
    int grid = 148 * 3;
    if (grid > n_tiles) grid = n_tiles;
    precompute_mma<<<grid, 128>>>(emb, W1, b1, N, n_tiles);

    // 5) per-edge gate values, scattered directly into row segments
    edge_kernel<<<(E + 31) / 32, 256>>>(ei, W2, b2, eps_u, rb_u, E);

    // 6) random entries
    rand_kernel<<<(R + 255) / 256, 256>>>(ri, R);

    // 7) per-row col sort + coalesce + output
    int vals_only = (out_size == M) ? 1 : 0;
    row_sort_kernel<<<(N + 255) / 256, 256>>>((float*)d_out, M, N, vals_only);
}

// round 7
// speedup vs baseline: 3.7863x; 1.1868x over previous
#include <cuda_runtime.h>
#include <cuda_fp16.h>
#include <cstdint>
#include <math.h>
#include <cub/device/device_scan.cuh>

// Problem-fixed sizes (from setup_inputs): N=300000, D=64, E=1000000, R=100000
#define DD 64
static const int    N_MAX = 300032;
static const int    M_MAX = 1200000;
static const size_t TEMP_BYTES = 4u << 20;

// Scratch (device globals — allocation-free per harness rules)
__device__ __align__(16) __half2 g_A[(size_t)N_MAX * 32];   // [N][64] fp16 (b1 folded)
__device__ __align__(16) __half2 g_B[(size_t)N_MAX * 32];
__device__ int            g_cnt [N_MAX];             // per-row entry count
__device__ int            g_offs[N_MAX + 1];         // exclusive prefix -> cursor
__device__ unsigned       g_cols_s[M_MAX];           // scattered cols (row-grouped)
__device__ float          g_vals_s[M_MAX];           // scattered vals
__device__ unsigned char  g_temp[TEMP_BYTES];        // CUB scan temp

// ---------------------------------------------------------------------------
// Kernel 1: fp16 tensor-core node-factored MLP partials, double-buffered.
// Warp = (row-group, table). Warp owns ALL 64 cols of its table for 16 rows
// -> full 128B output rows -> STG.128 epilogue via conflict-free staging.
// Ping-pong smem tile + register prefetch: next tile's LDGs issue before
// current tile's MMAs; ONE syncthreads per iteration.
// ---------------------------------------------------------------------------
#define PITCH2 36   // half2 pitch: fragment LDS banks (4*gid+tig)%32 distinct

__global__ void __launch_bounds__(128, 3)
precompute_mma(const float* __restrict__ emb,
               const float* __restrict__ W1,
               const float* __restrict__ b1,
               int N, int n_tiles) {
    __shared__ __align__(16) __half2 sE[2][32 * PITCH2];
    __shared__ __align__(16) __half2 sStage[4][16 * PITCH2];

    const int tid  = threadIdx.x;
    const int warp = tid >> 5;
    const int lane = tid & 31;
    const int gid  = lane >> 2;   // 0..7
    const int tig  = lane & 3;    // 0..3
    const int T    = warp & 1;    // 0 -> g_A (W1 left), 1 -> g_B (W1 right)
    const int base = (warp >> 1) * 16;

    // per-thread tile-load coords: element idx = j*128 + tid
    const int lni = tid >> 5;          // row 0..3 (+4 per j)
    const int lh  = tid & 31;          // half2 col

    // Weight fragments: col j = nt*8+gid of table T
    unsigned bf[4][8][2];
    float2   b1v[8];
#pragma unroll
    for (int nt = 0; nt < 8; ++nt) {
        int c = nt * 8 + gid;
        const float* wrow = W1 + (size_t)c * 128 + (T ? 64 : 0);
#pragma unroll
        for (int kt = 0; kt < 4; ++kt) {
            __half2 lo = __floats2half2_rn(__ldg(wrow + kt * 16 + 2 * tig),
                                           __ldg(wrow + kt * 16 + 2 * tig + 1));
            __half2 hi = __floats2half2_rn(__ldg(wrow + kt * 16 + 2 * tig + 8),
                                           __ldg(wrow + kt * 16 + 2 * tig + 9));
            bf[kt][nt][0] = *(unsigned*)&lo;
            bf[kt][nt][1] = *(unsigned*)&hi;
        }
        b1v[nt] = T ? make_float2(0.f, 0.f)
                    : __ldg((const float2*)b1 + nt * 4 + tig);
    }

    __half2* tab = T ? g_B : g_A;
    __half2* st  = &sStage[warp][0];

    const int G = gridDim.x;
    int t = blockIdx.x;

    // prologue: load tile t into buffer 0
    float2 r[8];
#pragma unroll
    for (int j = 0; j < 8; ++j) {
        int n = t * 32 + j * 4 + lni;
        r[j] = (t < n_tiles && n < N)
                   ? __ldg((const float2*)(emb + (size_t)n * DD) + lh)
                   : make_float2(0.f, 0.f);
    }
#pragma unroll
    for (int j = 0; j < 8; ++j)
        sE[0][(j * 4 + lni) * PITCH2 + lh] = __floats2half2_rn(r[j].x, r[j].y);
    __syncthreads();

    int buf = 0;
    for (; t < n_tiles; t += G) {
        const int tn = t + G;
        // issue next tile's loads first (latency overlapped with compute)
        if (tn < n_tiles) {
#pragma unroll
            for (int j = 0; j < 8; ++j) {
                int n = tn * 32 + j * 4 + lni;
                r[j] = (n < N)
                           ? __ldg((const float2*)(emb + (size_t)n * DD) + lh)
                           : make_float2(0.f, 0.f);
            }
        }

        const int n0 = t * 32;
        const __half2* p0 = &sE[buf][(base + gid)     * PITCH2];
        const __half2* p1 = &sE[buf][(base + gid + 8) * PITCH2];

        float acc[8][4];
#pragma unroll
        for (int nt = 0; nt < 8; ++nt)
#pragma unroll
            for (int c = 0; c < 4; ++c) acc[nt][c] = 0.f;

#pragma unroll
        for (int kt = 0; kt < 4; ++kt) {
            unsigned a0 = *(const unsigned*)&p0[kt * 8 + tig];
            unsigned a1 = *(const unsigned*)&p1[kt * 8 + tig];
            unsigned a2 = *(const unsigned*)&p0[kt * 8 + tig + 4];
            unsigned a3 = *(const unsigned*)&p1[kt * 8 + tig + 4];
#pragma unroll
            for (int nt = 0; nt < 8; ++nt) {
                asm volatile(
                    "mma.sync.aligned.m16n8k16.row.col.f32.f16.f16.f32 "
                    "{%0,%1,%2,%3}, {%4,%5,%6,%7}, {%8,%9}, {%0,%1,%2,%3};"
                    : "+f"(acc[nt][0]), "+f"(acc[nt][1]),
                      "+f"(acc[nt][2]), "+f"(acc[nt][3])
                    : "r"(a0), "r"(a1), "r"(a2), "r"(a3),
                      "r"(bf[kt][nt][0]), "r"(bf[kt][nt][1]));
            }
        }

        // Stage (conflict-free), then coalesced STG.128 of full rows
#pragma unroll
        for (int nt = 0; nt < 8; ++nt) {
            float2 bb = b1v[nt];
            st[gid * PITCH2 + nt * 4 + tig] =
                __floats2half2_rn(acc[nt][0] + bb.x, acc[nt][1] + bb.y);
            st[(gid + 8) * PITCH2 + nt * 4 + tig] =
                __floats2half2_rn(acc[nt][2] + bb.x, acc[nt][3] + bb.y);
        }
        __syncwarp();
#pragma unroll
        for (int i = 0; i < 4; ++i) {
            int rr = i * 4 + (lane >> 3);
            int cc = lane & 7;
            int n  = n0 + base + rr;
            if (n < N) {
                float4 v = *(const float4*)((const char*)st + rr * (PITCH2 * 4) + cc * 16);
                *(float4*)((char*)(tab + (size_t)n * 32) + cc * 16) = v;
            }
        }

        // store next tile into the other buffer; single barrier per iter
        if (tn < n_tiles) {
#pragma unroll
            for (int j = 0; j < 8; ++j)
                sE[buf ^ 1][(j * 4 + lni) * PITCH2 + lh] =
                    __floats2half2_rn(r[j].x, r[j].y);
        }
        __syncthreads();
        buf ^= 1;
    }
}

// ---------------------------------------------------------------------------
// Kernel 2: row histogram over all (edge + random) entries.
// ---------------------------------------------------------------------------
__global__ void hist_kernel(const int* __restrict__ ei,
                            const int* __restrict__ ri, int E, int R) {
    int i = blockIdx.x * blockDim.x + threadIdx.x;
    if (i < E)          atomicAdd(&g_cnt[ei[i]], 1);
    else if (i < E + R) atomicAdd(&g_cnt[ri[i - E]], 1);
}

// ---------------------------------------------------------------------------
// Kernel 3: 256 edges/block. Phase 1: 8-thread groups compute 8 partial dots
// each (16 LDG.128 in flight), reduce, logits -> smem. Phase 2: every thread
// runs the transcendental chain for its own edge (full occupancy).
// ---------------------------------------------------------------------------
__global__ void edge_kernel(const int* __restrict__ ei,
                            const float* __restrict__ W2,
                            const float* __restrict__ b2,
                            const float* __restrict__ eps_u,
                            const float* __restrict__ rb_u,
                            int E) {
    __shared__ float s_logit[256];

    const int tid  = threadIdx.x;
    const int sub  = tid & 7;
    const int le   = tid >> 3;          // 0..31
    const int base = blockIdx.x * 256;

    float2 w2v[4];
#pragma unroll
    for (int q = 0; q < 4; ++q)
        w2v[q] = __ldg((const float2*)W2 + sub * 4 + q);

    float p[8];
#pragma unroll
    for (int i = 0; i < 8; ++i) {
        int e = base + i * 32 + le;
        float acc = 0.f;
        if (e < E) {
            int src = __ldg(ei + e);
            int dst = __ldg(ei + E + e);
            float4 a4 = *((const float4*)(g_A + (size_t)src * 32) + sub);
            float4 b4 = *((const float4*)(g_B + (size_t)dst * 32) + sub);
            const __half2* ah = (const __half2*)&a4;
            const __half2* bh = (const __half2*)&b4;
#pragma unroll
            for (int q = 0; q < 4; ++q) {
                float2 av = __half22float2(ah[q]);
                float2 bv = __half22float2(bh[q]);
                acc += fmaxf(av.x + bv.x, 0.0f) * w2v[q].x
                     + fmaxf(av.y + bv.y, 0.0f) * w2v[q].y;
            }
        }
        p[i] = acc;
    }
#pragma unroll
    for (int i = 0; i < 8; ++i) {
        float v = p[i];
        v += __shfl_xor_sync(0xffffffffu, v, 4);
        v += __shfl_xor_sync(0xffffffffu, v, 2);
        v += __shfl_xor_sync(0xffffffffu, v, 1);
        if (sub == 0) s_logit[i * 32 + le] = v;
    }
    __syncthreads();

    int e = base + tid;
    if (e < E) {
        int src = __ldg(ei + e);
        int dst = __ldg(ei + E + e);
        float logit = s_logit[tid] + __ldg(b2);
        float eps  = fmaf(-0.9998f, __ldg(eps_u + e), 0.9999f);
        float gate = logf(eps) - log1pf(-eps) + logit;
        float w    = 1.0f / (1.0f + expf(-gate));
        float att  = fminf(fmaxf(w, 0.01f), 0.99f);
        float u    = fminf(fmaxf(__ldg(rb_u + e), 1e-7f), 1.0f - 1e-7f);
        float sarg = (logf(att) - log1pf(-att) + logf(u) - log1pf(-u))
                     * (1.0f / 0.9f);
        float s    = 1.0f / (1.0f + expf(-sarg));
        // mask = (s > 0) is always 1 in fp32, so mat = s
        int pos = atomicAdd(&g_offs[src], 1);
        g_cols_s[pos] = (unsigned)dst;
        g_vals_s[pos] = s;
    }
}

// ---------------------------------------------------------------------------
// Kernel 4: scatter random entries (value 0.05)
// ---------------------------------------------------------------------------
__global__ void rand_kernel(const int* __restrict__ ri, int R) {
    int r = blockIdx.x * blockDim.x + threadIdx.x;
    if (r >= R) return;
    int row = ri[r];
    int col = ri[R + r];
    int pos = atomicAdd(&g_offs[row], 1);
    g_cols_s[pos] = (unsigned)col;
    g_vals_s[pos] = 0.05f;
}

// ---------------------------------------------------------------------------
// Kernel 5: per-row sort by col + coalesce duplicates + write output.
// out layout: [0..M) rows, [M..2M) cols, [2M..3M) vals (float32)
// ---------------------------------------------------------------------------
__global__ void row_sort_kernel(float* __restrict__ out, int M, int NROWS,
                                int vals_only) {
    int r = blockIdx.x * blockDim.x + threadIdx.x;
    if (r >= NROWS) return;
    int cnt = g_cnt[r];
    if (cnt == 0) return;
    int start = g_offs[r] - cnt;

    unsigned lc[32];
    float    lv[32];
    unsigned* c;
    float*    v;
    if (cnt <= 32) {
        for (int j = 0; j < cnt; ++j) {
            lc[j] = g_cols_s[start + j];
            lv[j] = g_vals_s[start + j];
        }
        c = lc; v = lv;
    } else {
        c = &g_cols_s[start];
        v = &g_vals_s[start];
    }

    for (int j = 1; j < cnt; ++j) {
        unsigned ck = c[j];
        float    vk = v[j];
        int k = j - 1;
        while (k >= 0 && c[k] > ck) {
            c[k + 1] = c[k];
            v[k + 1] = v[k];
            --k;
        }
        c[k + 1] = ck;
        v[k + 1] = vk;
    }

    float frow = (float)r;
    int j = 0;
    while (j < cnt) {
        int k = j + 1;
        float s = v[j];
        while (k < cnt && c[k] == c[j]) { s += v[k]; ++k; }
        for (int t = j; t < k; ++t) {
            int   o  = start + t;
            float ov = (t == j) ? s : 0.0f;
            if (vals_only) {
                out[o] = ov;
            } else {
                out[o]         = frow;
                out[M + o]     = (float)c[t];
                out[2 * M + o] = ov;
            }
        }
        j = k;
    }
}

// ---------------------------------------------------------------------------
extern "C" void kernel_launch(void* const* d_in, const int* in_sizes, int n_in,
                              void* d_out, int out_size) {
    const float* emb   = (const float*)d_in[0];
    const float* W1    = (const float*)d_in[1];
    const float* b1    = (const float*)d_in[2];
    const float* W2    = (const float*)d_in[3];
    const float* b2    = (const float*)d_in[4];
    const int*   ei    = (const int*)  d_in[5];
    const int*   ri    = (const int*)  d_in[6];
    const float* eps_u = (const float*)d_in[7];
    const float* rb_u  = (const float*)d_in[8];

    const int N = in_sizes[0] / DD;
    const int E = in_sizes[5] / 2;
    const int R = in_sizes[6] / 2;
    const int M = E + R;

    void *p_cnt, *p_offs, *p_tmp;
    cudaGetSymbolAddress(&p_cnt,  g_cnt);
    cudaGetSymbolAddress(&p_offs, g_offs);
    cudaGetSymbolAddress(&p_tmp,  g_temp);

    // 1) zero row counters
    cudaMemsetAsync(p_cnt, 0, (size_t)N * sizeof(int), (cudaStream_t)0);

    // 2) row histogram from raw indices
    hist_kernel<<<(E + R + 255) / 256, 256>>>(ei, ri, E, R);

    // 3) exclusive scan -> segment offsets (doubles as scatter cursor)
    size_t tb = TEMP_BYTES;
    cub::DeviceScan::ExclusiveSum(p_tmp, tb, (const int*)p_cnt, (int*)p_offs,
                                  N, (cudaStream_t)0);

    // 4) fp16 tensor-core node-factored MLP partials (double-buffered)
    int n_tiles = (N + 31) / 32;
    int grid = 148 * 3;
    if (grid > n_tiles) grid = n_tiles;
    precompute_mma<<<grid, 128>>>(emb, W1, b1, N, n_tiles);

    // 5) per-edge gate values, scattered directly into row segments
    edge_kernel<<<(E + 255) / 256, 256>>>(ei, W2, b2, eps_u, rb_u, E);

    // 6) random entries
    rand_kernel<<<(R + 255) / 256, 256>>>(ri, R);

    // 7) per-row col sort + coalesce + output
    int vals_only = (out_size == M) ? 1 : 0;
    row_sort_kernel<<<(N + 255) / 256, 256>>>((float*)d_out, M, N, vals_only);
}

// round 8
// speedup vs baseline: 3.7959x; 1.0025x over previous
#include <cuda_runtime.h>
#include <cuda_fp16.h>
#include <cstdint>
#include <math.h>
#include <cub/device/device_scan.cuh>

// Problem-fixed sizes (from setup_inputs): N=300000, D=64, E=1000000, R=100000
#define DD 64
static const int    N_MAX = 300032;
static const int    M_MAX = 1200000;
static const size_t TEMP_BYTES = 4u << 20;

// Scratch (device globals — allocation-free per harness rules)
__device__ __align__(16) __half2 g_A[(size_t)N_MAX * 32];   // [N][64] fp16 (b1 folded)
__device__ __align__(16) __half2 g_B[(size_t)N_MAX * 32];
__device__ int            g_cnt [N_MAX];             // per-row entry count
__device__ int            g_offs[N_MAX + 1];         // exclusive prefix -> cursor
__device__ unsigned       g_cols_s[M_MAX];           // scattered cols (row-grouped)
__device__ float          g_vals_s[M_MAX];           // scattered vals
__device__ unsigned char  g_temp[TEMP_BYTES];        // CUB scan temp

// ---------------------------------------------------------------------------
// Kernel 1: fp16 tensor-core node-factored MLP partials, double-buffered.
// Warp = (row-group, table). Warp owns ALL 64 cols of its table for 16 rows
// -> full 128B output rows -> STG.128 epilogue via conflict-free staging.
// Ping-pong smem tile + register prefetch: next tile's LDGs issue before
// current tile's MMAs; ONE syncthreads per iteration.
// ---------------------------------------------------------------------------
#define PITCH2 36   // half2 pitch: fragment LDS banks (4*gid+tig)%32 distinct

__global__ void __launch_bounds__(128, 3)
precompute_mma(const float* __restrict__ emb,
               const float* __restrict__ W1,
               const float* __restrict__ b1,
               int N, int n_tiles) {
    __shared__ __align__(16) __half2 sE[2][32 * PITCH2];
    __shared__ __align__(16) __half2 sStage[4][16 * PITCH2];

    const int tid  = threadIdx.x;
    const int warp = tid >> 5;
    const int lane = tid & 31;
    const int gid  = lane >> 2;   // 0..7
    const int tig  = lane & 3;    // 0..3
    const int T    = warp & 1;    // 0 -> g_A (W1 left), 1 -> g_B (W1 right)
    const int base = (warp >> 1) * 16;

    // per-thread tile-load coords: element idx = j*128 + tid
    const int lni = tid >> 5;          // row 0..3 (+4 per j)
    const int lh  = tid & 31;          // half2 col

    // Weight fragments: col j = nt*8+gid of table T
    unsigned bf[4][8][2];
    float2   b1v[8];
#pragma unroll
    for (int nt = 0; nt < 8; ++nt) {
        int c = nt * 8 + gid;
        const float* wrow = W1 + (size_t)c * 128 + (T ? 64 : 0);
#pragma unroll
        for (int kt = 0; kt < 4; ++kt) {
            __half2 lo = __floats2half2_rn(__ldg(wrow + kt * 16 + 2 * tig),
                                           __ldg(wrow + kt * 16 + 2 * tig + 1));
            __half2 hi = __floats2half2_rn(__ldg(wrow + kt * 16 + 2 * tig + 8),
                                           __ldg(wrow + kt * 16 + 2 * tig + 9));
            bf[kt][nt][0] = *(unsigned*)&lo;
            bf[kt][nt][1] = *(unsigned*)&hi;
        }
        b1v[nt] = T ? make_float2(0.f, 0.f)
                    : __ldg((const float2*)b1 + nt * 4 + tig);
    }

    __half2* tab = T ? g_B : g_A;
    __half2* st  = &sStage[warp][0];

    const int G = gridDim.x;
    int t = blockIdx.x;

    // prologue: load tile t into buffer 0
    float2 r[8];
#pragma unroll
    for (int j = 0; j < 8; ++j) {
        int n = t * 32 + j * 4 + lni;
        r[j] = (t < n_tiles && n < N)
                   ? __ldg((const float2*)(emb + (size_t)n * DD) + lh)
                   : make_float2(0.f, 0.f);
    }
#pragma unroll
    for (int j = 0; j < 8; ++j)
        sE[0][(j * 4 + lni) * PITCH2 + lh] = __floats2half2_rn(r[j].x, r[j].y);
    __syncthreads();

    int buf = 0;
    for (; t < n_tiles; t += G) {
        const int tn = t + G;
        // issue next tile's loads first (latency overlapped with compute)
        if (tn < n_tiles) {
#pragma unroll
            for (int j = 0; j < 8; ++j) {
                int n = tn * 32 + j * 4 + lni;
                r[j] = (n < N)
                           ? __ldg((const float2*)(emb + (size_t)n * DD) + lh)
                           : make_float2(0.f, 0.f);
            }
        }

        const int n0 = t * 32;
        const __half2* p0 = &sE[buf][(base + gid)     * PITCH2];
        const __half2* p1 = &sE[buf][(base + gid + 8) * PITCH2];

        float acc[8][4];
#pragma unroll
        for (int nt = 0; nt < 8; ++nt)
#pragma unroll
            for (int c = 0; c < 4; ++c) acc[nt][c] = 0.f;

#pragma unroll
        for (int kt = 0; kt < 4; ++kt) {
            unsigned a0 = *(const unsigned*)&p0[kt * 8 + tig];
            unsigned a1 = *(const unsigned*)&p1[kt * 8 + tig];
            unsigned a2 = *(const unsigned*)&p0[kt * 8 + tig + 4];
            unsigned a3 = *(const unsigned*)&p1[kt * 8 + tig + 4];
#pragma unroll
            for (int nt = 0; nt < 8; ++nt) {
                asm volatile(
                    "mma.sync.aligned.m16n8k16.row.col.f32.f16.f16.f32 "
                    "{%0,%1,%2,%3}, {%4,%5,%6,%7}, {%8,%9}, {%0,%1,%2,%3};"
                    : "+f"(acc[nt][0]), "+f"(acc[nt][1]),
                      "+f"(acc[nt][2]), "+f"(acc[nt][3])
                    : "r"(a0), "r"(a1), "r"(a2), "r"(a3),
                      "r"(bf[kt][nt][0]), "r"(bf[kt][nt][1]));
            }
        }

        // Stage (conflict-free), then coalesced STG.128 of full rows
#pragma unroll
        for (int nt = 0; nt < 8; ++nt) {
            float2 bb = b1v[nt];
            st[gid * PITCH2 + nt * 4 + tig] =
                __floats2half2_rn(acc[nt][0] + bb.x, acc[nt][1] + bb.y);
            st[(gid + 8) * PITCH2 + nt * 4 + tig] =
                __floats2half2_rn(acc[nt][2] + bb.x, acc[nt][3] + bb.y);
        }
        __syncwarp();
#pragma unroll
        for (int i = 0; i < 4; ++i) {
            int rr = i * 4 + (lane >> 3);
            int cc = lane & 7;
            int n  = n0 + base + rr;
            if (n < N) {
                float4 v = *(const float4*)((const char*)st + rr * (PITCH2 * 4) + cc * 16);
                *(float4*)((char*)(tab + (size_t)n * 32) + cc * 16) = v;
            }
        }

        // store next tile into the other buffer; single barrier per iter
        if (tn < n_tiles) {
#pragma unroll
            for (int j = 0; j < 8; ++j)
                sE[buf ^ 1][(j * 4 + lni) * PITCH2 + lh] =
                    __floats2half2_rn(r[j].x, r[j].y);
        }
        __syncthreads();
        buf ^= 1;
    }
}

// ---------------------------------------------------------------------------
// Kernel 2: row histogram over all (edge + random) entries.
// ---------------------------------------------------------------------------
__global__ void hist_kernel(const int* __restrict__ ei,
                            const int* __restrict__ ri, int E, int R) {
    int i = blockIdx.x * blockDim.x + threadIdx.x;
    if (i < E)          atomicAdd(&g_cnt[ei[i]], 1);
    else if (i < E + R) atomicAdd(&g_cnt[ri[i - E]], 1);
}

// ---------------------------------------------------------------------------
// Kernel 3: 256 edges/block. Phase 1: 8-thread groups compute 8 partial dots
// each (16 LDG.128 in flight), reduce, logits -> smem. Phase 2: every thread
// runs the transcendental chain for its own edge (full occupancy).
// ---------------------------------------------------------------------------
__global__ void edge_kernel(const int* __restrict__ ei,
                            const float* __restrict__ W2,
                            const float* __restrict__ b2,
                            const float* __restrict__ eps_u,
                            const float* __restrict__ rb_u,
                            int E) {
    __shared__ float s_logit[256];

    const int tid  = threadIdx.x;
    const int sub  = tid & 7;
    const int le   = tid >> 3;          // 0..31
    const int base = blockIdx.x * 256;

    float2 w2v[4];
#pragma unroll
    for (int q = 0; q < 4; ++q)
        w2v[q] = __ldg((const float2*)W2 + sub * 4 + q);

    float p[8];
#pragma unroll
    for (int i = 0; i < 8; ++i) {
        int e = base + i * 32 + le;
        float acc = 0.f;
        if (e < E) {
            int src = __ldg(ei + e);
            int dst = __ldg(ei + E + e);
            float4 a4 = *((const float4*)(g_A + (size_t)src * 32) + sub);
            float4 b4 = *((const float4*)(g_B + (size_t)dst * 32) + sub);
            const __half2* ah = (const __half2*)&a4;
            const __half2* bh = (const __half2*)&b4;
#pragma unroll
            for (int q = 0; q < 4; ++q) {
                float2 av = __half22float2(ah[q]);
                float2 bv = __half22float2(bh[q]);
                acc += fmaxf(av.x + bv.x, 0.0f) * w2v[q].x
                     + fmaxf(av.y + bv.y, 0.0f) * w2v[q].y;
            }
        }
        p[i] = acc;
    }
#pragma unroll
    for (int i = 0; i < 8; ++i) {
        float v = p[i];
        v += __shfl_xor_sync(0xffffffffu, v, 4);
        v += __shfl_xor_sync(0xffffffffu, v, 2);
        v += __shfl_xor_sync(0xffffffffu, v, 1);
        if (sub == 0) s_logit[i * 32 + le] = v;
    }
    __syncthreads();

    int e = base + tid;
    if (e < E) {
        int src = __ldg(ei + e);
        int dst = __ldg(ei + E + e);
        float logit = s_logit[tid] + __ldg(b2);
        float eps  = fmaf(-0.9998f, __ldg(eps_u + e), 0.9999f);
        float gate = logf(eps) - log1pf(-eps) + logit;
        float w    = 1.0f / (1.0f + expf(-gate));
        float att  = fminf(fmaxf(w, 0.01f), 0.99f);
        float u    = fminf(fmaxf(__ldg(rb_u + e), 1e-7f), 1.0f - 1e-7f);
        float sarg = (logf(att) - log1pf(-att) + logf(u) - log1pf(-u))
                     * (1.0f / 0.9f);
        float s    = 1.0f / (1.0f + expf(-sarg));
        // mask = (s > 0) is always 1 in fp32, so mat = s
        int pos = atomicAdd(&g_offs[src], 1);
        g_cols_s[pos] = (unsigned)dst;
        g_vals_s[pos] = s;
    }
}

// ---------------------------------------------------------------------------
// Kernel 4: scatter random entries (value 0.05)
// ---------------------------------------------------------------------------
__global__ void rand_kernel(const int* __restrict__ ri, int R) {
    int r = blockIdx.x * blockDim.x + threadIdx.x;
    if (r >= R) return;
    int row = ri[r];
    int col = ri[R + r];
    int pos = atomicAdd(&g_offs[row], 1);
    g_cols_s[pos] = (unsigned)col;
    g_vals_s[pos] = 0.05f;
}

// ---------------------------------------------------------------------------
// Kernel 5: per-row sort by col + coalesce duplicates + write output.
// out layout: [0..M) rows, [M..2M) cols, [2M..3M) vals (float32)
// ---------------------------------------------------------------------------
__global__ void row_sort_kernel(float* __restrict__ out, int M, int NROWS,
                                int vals_only) {
    int r = blockIdx.x * blockDim.x + threadIdx.x;
    if (r >= NROWS) return;
    int cnt = g_cnt[r];
    if (cnt == 0) return;
    int start = g_offs[r] - cnt;

    unsigned lc[32];
    float    lv[32];
    unsigned* c;
    float*    v;
    if (cnt <= 32) {
        for (int j = 0; j < cnt; ++j) {
            lc[j] = g_cols_s[start + j];
            lv[j] = g_vals_s[start + j];
        }
        c = lc; v = lv;
    } else {
        c = &g_cols_s[start];
        v = &g_vals_s[start];
    }

    for (int j = 1; j < cnt; ++j) {
        unsigned ck = c[j];
        float    vk = v[j];
        int k = j - 1;
        while (k >= 0 && c[k] > ck) {
            c[k + 1] = c[k];
            v[k + 1] = v[k];
            --k;
        }
        c[k + 1] = ck;
        v[k + 1] = vk;
    }

    float frow = (float)r;
    int j = 0;
    while (j < cnt) {
        int k = j + 1;
        float s = v[j];
        while (k < cnt && c[k] == c[j]) { s += v[k]; ++k; }
        for (int t = j; t < k; ++t) {
            int   o  = start + t;
            float ov = (t == j) ? s : 0.0f;
            if (vals_only) {
                out[o] = ov;
            } else {
                out[o]         = frow;
                out[M + o]     = (float)c[t];
                out[2 * M + o] = ov;
            }
        }
        j = k;
    }
}

// ---------------------------------------------------------------------------
extern "C" void kernel_launch(void* const* d_in, const int* in_sizes, int n_in,
                              void* d_out, int out_size) {
    const float* emb   = (const float*)d_in[0];
    const float* W1    = (const float*)d_in[1];
    const float* b1    = (const float*)d_in[2];
    const float* W2    = (const float*)d_in[3];
    const float* b2    = (const float*)d_in[4];
    const int*   ei    = (const int*)  d_in[5];
    const int*   ri    = (const int*)  d_in[6];
    const float* eps_u = (const float*)d_in[7];
    const float* rb_u  = (const float*)d_in[8];

    const int N = in_sizes[0] / DD;
    const int E = in_sizes[5] / 2;
    const int R = in_sizes[6] / 2;
    const int M = E + R;

    void *p_cnt, *p_offs, *p_tmp;
    cudaGetSymbolAddress(&p_cnt,  g_cnt);
    cudaGetSymbolAddress(&p_offs, g_offs);
    cudaGetSymbolAddress(&p_tmp,  g_temp);

    // 1) zero row counters
    cudaMemsetAsync(p_cnt, 0, (size_t)N * sizeof(int), (cudaStream_t)0);

    // 2) row histogram from raw indices
    hist_kernel<<<(E + R + 255) / 256, 256>>>(ei, ri, E, R);

    // 3) exclusive scan -> segment offsets (doubles as scatter cursor)
    size_t tb = TEMP_BYTES;
    cub::DeviceScan::ExclusiveSum(p_tmp, tb, (const int*)p_cnt, (int*)p_offs,
                                  N, (cudaStream_t)0);

    // 4) fp16 tensor-core node-factored MLP partials (double-buffered)
    int n_tiles = (N + 31) / 32;
    int grid = 148 * 3;
    if (grid > n_tiles) grid = n_tiles;
    precompute_mma<<<grid, 128>>>(emb, W1, b1, N, n_tiles);

    // 5) per-edge gate values, scattered directly into row segments
    edge_kernel<<<(E + 255) / 256, 256>>>(ei, W2, b2, eps_u, rb_u, E);

    // 6) random entries
    rand_kernel<<<(R + 255) / 256, 256>>>(ri, R);

    // 7) per-row col sort + coalesce + output
    int vals_only = (out_size == M) ? 1 : 0;
    row_sort_kernel<<<(N + 255) / 256, 256>>>((float*)d_out, M, N, vals_only);
}

// round 9
// speedup vs baseline: 4.0096x; 1.0563x over previous
#include <cuda_runtime.h>
#include <cuda_fp16.h>
#include <cstdint>
#include <math.h>
#include <cub/device/device_scan.cuh>

// Problem-fixed sizes (from setup_inputs): N=300000, D=64, E=1000000, R=100000
#define DD 64
static const int    N_MAX = 300032;
static const int    M_MAX = 1200000;
static const size_t TEMP_BYTES = 4u << 20;

// Scratch (device globals — allocation-free per harness rules)
__device__ __align__(16) __half2 g_A[(size_t)N_MAX * 32];   // [N][64] fp16 (b1 folded)
__device__ __align__(16) __half2 g_B[(size_t)N_MAX * 32];
__device__ int            g_cnt [N_MAX];             // per-row entry count
__device__ int            g_offs[N_MAX + 1];         // exclusive prefix -> cursor
__device__ unsigned       g_cols_s[M_MAX];           // scattered cols (row-grouped)
__device__ float          g_vals_s[M_MAX];           // scattered vals
__device__ unsigned char  g_temp[TEMP_BYTES];        // CUB scan temp

// ---------------------------------------------------------------------------
// Kernel 1: fp16 tensor-core node-factored MLP partials, double-buffered.
// (unchanged from R7 winner)
// ---------------------------------------------------------------------------
#define PITCH2 36   // half2 pitch: fragment LDS banks (4*gid+tig)%32 distinct

__global__ void __launch_bounds__(128, 3)
precompute_mma(const float* __restrict__ emb,
               const float* __restrict__ W1,
               const float* __restrict__ b1,
               int N, int n_tiles) {
    __shared__ __align__(16) __half2 sE[2][32 * PITCH2];
    __shared__ __align__(16) __half2 sStage[4][16 * PITCH2];

    const int tid  = threadIdx.x;
    const int warp = tid >> 5;
    const int lane = tid & 31;
    const int gid  = lane >> 2;   // 0..7
    const int tig  = lane & 3;    // 0..3
    const int T    = warp & 1;    // 0 -> g_A (W1 left), 1 -> g_B (W1 right)
    const int base = (warp >> 1) * 16;

    const int lni = tid >> 5;          // row 0..3 (+4 per j)
    const int lh  = tid & 31;          // half2 col

    unsigned bf[4][8][2];
    float2   b1v[8];
#pragma unroll
    for (int nt = 0; nt < 8; ++nt) {
        int c = nt * 8 + gid;
        const float* wrow = W1 + (size_t)c * 128 + (T ? 64 : 0);
#pragma unroll
        for (int kt = 0; kt < 4; ++kt) {
            __half2 lo = __floats2half2_rn(__ldg(wrow + kt * 16 + 2 * tig),
                                           __ldg(wrow + kt * 16 + 2 * tig + 1));
            __half2 hi = __floats2half2_rn(__ldg(wrow + kt * 16 + 2 * tig + 8),
                                           __ldg(wrow + kt * 16 + 2 * tig + 9));
            bf[kt][nt][0] = *(unsigned*)&lo;
            bf[kt][nt][1] = *(unsigned*)&hi;
        }
        b1v[nt] = T ? make_float2(0.f, 0.f)
                    : __ldg((const float2*)b1 + nt * 4 + tig);
    }

    __half2* tab = T ? g_B : g_A;
    __half2* st  = &sStage[warp][0];

    const int G = gridDim.x;
    int t = blockIdx.x;

    float2 r[8];
#pragma unroll
    for (int j = 0; j < 8; ++j) {
        int n = t * 32 + j * 4 + lni;
        r[j] = (t < n_tiles && n < N)
                   ? __ldg((const float2*)(emb + (size_t)n * DD) + lh)
                   : make_float2(0.f, 0.f);
    }
#pragma unroll
    for (int j = 0; j < 8; ++j)
        sE[0][(j * 4 + lni) * PITCH2 + lh] = __floats2half2_rn(r[j].x, r[j].y);
    __syncthreads();

    int buf = 0;
    for (; t < n_tiles; t += G) {
        const int tn = t + G;
        if (tn < n_tiles) {
#pragma unroll
            for (int j = 0; j < 8; ++j) {
                int n = tn * 32 + j * 4 + lni;
                r[j] = (n < N)
                           ? __ldg((const float2*)(emb + (size_t)n * DD) + lh)
                           : make_float2(0.f, 0.f);
            }
        }

        const int n0 = t * 32;
        const __half2* p0 = &sE[buf][(base + gid)     * PITCH2];
        const __half2* p1 = &sE[buf][(base + gid + 8) * PITCH2];

        float acc[8][4];
#pragma unroll
        for (int nt = 0; nt < 8; ++nt)
#pragma unroll
            for (int c = 0; c < 4; ++c) acc[nt][c] = 0.f;

#pragma unroll
        for (int kt = 0; kt < 4; ++kt) {
            unsigned a0 = *(const unsigned*)&p0[kt * 8 + tig];
            unsigned a1 = *(const unsigned*)&p1[kt * 8 + tig];
            unsigned a2 = *(const unsigned*)&p0[kt * 8 + tig + 4];
            unsigned a3 = *(const unsigned*)&p1[kt * 8 + tig + 4];
#pragma unroll
            for (int nt = 0; nt < 8; ++nt) {
                asm volatile(
                    "mma.sync.aligned.m16n8k16.row.col.f32.f16.f16.f32 "
                    "{%0,%1,%2,%3}, {%4,%5,%6,%7}, {%8,%9}, {%0,%1,%2,%3};"
                    : "+f"(acc[nt][0]), "+f"(acc[nt][1]),
                      "+f"(acc[nt][2]), "+f"(acc[nt][3])
                    : "r"(a0), "r"(a1), "r"(a2), "r"(a3),
                      "r"(bf[kt][nt][0]), "r"(bf[kt][nt][1]));
            }
        }

#pragma unroll
        for (int nt = 0; nt < 8; ++nt) {
            float2 bb = b1v[nt];
            st[gid * PITCH2 + nt * 4 + tig] =
                __floats2half2_rn(acc[nt][0] + bb.x, acc[nt][1] + bb.y);
            st[(gid + 8) * PITCH2 + nt * 4 + tig] =
                __floats2half2_rn(acc[nt][2] + bb.x, acc[nt][3] + bb.y);
        }
        __syncwarp();
#pragma unroll
        for (int i = 0; i < 4; ++i) {
            int rr = i * 4 + (lane >> 3);
            int cc = lane & 7;
            int n  = n0 + base + rr;
            if (n < N) {
                float4 v = *(const float4*)((const char*)st + rr * (PITCH2 * 4) + cc * 16);
                *(float4*)((char*)(tab + (size_t)n * 32) + cc * 16) = v;
            }
        }

        if (tn < n_tiles) {
#pragma unroll
            for (int j = 0; j < 8; ++j)
                sE[buf ^ 1][(j * 4 + lni) * PITCH2 + lh] =
                    __floats2half2_rn(r[j].x, r[j].y);
        }
        __syncthreads();
        buf ^= 1;
    }
}

// ---------------------------------------------------------------------------
// Kernel 2: row histogram over all (edge + random) entries.
// ---------------------------------------------------------------------------
__global__ void hist_kernel(const int* __restrict__ ei,
                            const int* __restrict__ ri, int E, int R) {
    int i = blockIdx.x * blockDim.x + threadIdx.x;
    if (i < E)          atomicAdd(&g_cnt[ei[i]], 1);
    else if (i < E + R) atomicAdd(&g_cnt[ri[i - E]], 1);
}

// ---------------------------------------------------------------------------
// Kernel 3: edges + random entries in one launch.
// Blocks [0, EB): 256 edges/block — phase 1 gathers/dots, phase 2 full-
// occupancy transcendental chain + scatter. Blocks [EB, ...): random entries.
// ---------------------------------------------------------------------------
__global__ void edge_rand_kernel(const int* __restrict__ ei,
                                 const float* __restrict__ W2,
                                 const float* __restrict__ b2,
                                 const float* __restrict__ eps_u,
                                 const float* __restrict__ rb_u,
                                 const int* __restrict__ ri,
                                 int E, int R, int EB) {
    __shared__ float s_logit[256];

    if (blockIdx.x >= EB) {
        int r = (blockIdx.x - EB) * 256 + threadIdx.x;
        if (r < R) {
            int row = __ldg(ri + r);
            int col = __ldg(ri + R + r);
            int pos = atomicAdd(&g_offs[row], 1);
            g_cols_s[pos] = (unsigned)col;
            g_vals_s[pos] = 0.05f;
        }
        return;
    }

    const int tid  = threadIdx.x;
    const int sub  = tid & 7;
    const int le   = tid >> 3;          // 0..31
    const int base = blockIdx.x * 256;

    float2 w2v[4];
#pragma unroll
    for (int q = 0; q < 4; ++q)
        w2v[q] = __ldg((const float2*)W2 + sub * 4 + q);

    float p[8];
#pragma unroll
    for (int i = 0; i < 8; ++i) {
        int e = base + i * 32 + le;
        float acc = 0.f;
        if (e < E) {
            int src = __ldg(ei + e);
            int dst = __ldg(ei + E + e);
            float4 a4 = *((const float4*)(g_A + (size_t)src * 32) + sub);
            float4 b4 = *((const float4*)(g_B + (size_t)dst * 32) + sub);
            const __half2* ah = (const __half2*)&a4;
            const __half2* bh = (const __half2*)&b4;
#pragma unroll
            for (int q = 0; q < 4; ++q) {
                float2 av = __half22float2(ah[q]);
                float2 bv = __half22float2(bh[q]);
                acc += fmaxf(av.x + bv.x, 0.0f) * w2v[q].x
                     + fmaxf(av.y + bv.y, 0.0f) * w2v[q].y;
            }
        }
        p[i] = acc;
    }
#pragma unroll
    for (int i = 0; i < 8; ++i) {
        float v = p[i];
        v += __shfl_xor_sync(0xffffffffu, v, 4);
        v += __shfl_xor_sync(0xffffffffu, v, 2);
        v += __shfl_xor_sync(0xffffffffu, v, 1);
        if (sub == 0) s_logit[i * 32 + le] = v;
    }
    __syncthreads();

    int e = base + tid;
    if (e < E) {
        int src = __ldg(ei + e);
        int dst = __ldg(ei + E + e);
        float logit = s_logit[tid] + __ldg(b2);
        float eps  = fmaf(-0.9998f, __ldg(eps_u + e), 0.9999f);
        float gate = logf(eps) - log1pf(-eps) + logit;
        float w    = 1.0f / (1.0f + expf(-gate));
        float att  = fminf(fmaxf(w, 0.01f), 0.99f);
        float u    = fminf(fmaxf(__ldg(rb_u + e), 1e-7f), 1.0f - 1e-7f);
        float sarg = (logf(att) - log1pf(-att) + logf(u) - log1pf(-u))
                     * (1.0f / 0.9f);
        float s    = 1.0f / (1.0f + expf(-sarg));
        // mask = (s > 0) is always 1 in fp32, so mat = s
        int pos = atomicAdd(&g_offs[src], 1);
        g_cols_s[pos] = (unsigned)dst;
        g_vals_s[pos] = s;
    }
}

// ---------------------------------------------------------------------------
// Kernel 5: per-row sort by col + coalesce duplicates + write output.
// out layout: [0..M) rows, [M..2M) cols, [2M..3M) vals (float32)
// ---------------------------------------------------------------------------
__global__ void row_sort_kernel(float* __restrict__ out, int M, int NROWS,
                                int vals_only) {
    int r = blockIdx.x * blockDim.x + threadIdx.x;
    if (r >= NROWS) return;
    int cnt = g_cnt[r];
    if (cnt == 0) return;
    int start = g_offs[r] - cnt;

    unsigned lc[32];
    float    lv[32];
    unsigned* c;
    float*    v;
    if (cnt <= 32) {
        for (int j = 0; j < cnt; ++j) {
            lc[j] = g_cols_s[start + j];
            lv[j] = g_vals_s[start + j];
        }
        c = lc; v = lv;
    } else {
        c = &g_cols_s[start];
        v = &g_vals_s[start];
    }

    for (int j = 1; j < cnt; ++j) {
        unsigned ck = c[j];
        float    vk = v[j];
        int k = j - 1;
        while (k >= 0 && c[k] > ck) {
            c[k + 1] = c[k];
            v[k + 1] = v[k];
            --k;
        }
        c[k + 1] = ck;
        v[k + 1] = vk;
    }

    float frow = (float)r;
    int j = 0;
    while (j < cnt) {
        int k = j + 1;
        float s = v[j];
        while (k < cnt && c[k] == c[j]) { s += v[k]; ++k; }
        for (int t = j; t < k; ++t) {
            int   o  = start + t;
            float ov = (t == j) ? s : 0.0f;
            if (vals_only) {
                out[o] = ov;
            } else {
                out[o]         = frow;
                out[M + o]     = (float)c[t];
                out[2 * M + o] = ov;
            }
        }
        j = k;
    }
}

// ---------------------------------------------------------------------------
extern "C" void kernel_launch(void* const* d_in, const int* in_sizes, int n_in,
                              void* d_out, int out_size) {
    const float* emb   = (const float*)d_in[0];
    const float* W1    = (const float*)d_in[1];
    const float* b1    = (const float*)d_in[2];
    const float* W2    = (const float*)d_in[3];
    const float* b2    = (const float*)d_in[4];
    const int*   ei    = (const int*)  d_in[5];
    const int*   ri    = (const int*)  d_in[6];
    const float* eps_u = (const float*)d_in[7];
    const float* rb_u  = (const float*)d_in[8];

    const int N = in_sizes[0] / DD;
    const int E = in_sizes[5] / 2;
    const int R = in_sizes[6] / 2;
    const int M = E + R;

    void *p_cnt, *p_offs, *p_tmp;
    cudaGetSymbolAddress(&p_cnt,  g_cnt);
    cudaGetSymbolAddress(&p_offs, g_offs);
    cudaGetSymbolAddress(&p_tmp,  g_temp);

    // Aux stream + fork/join events (host objects only; leaked deliberately —
    // destroying them mid-capture would invalidate the capture).
    cudaStream_t s_aux;
    cudaEvent_t  ev_fork, ev_join;
    cudaStreamCreateWithFlags(&s_aux, cudaStreamNonBlocking);
    cudaEventCreateWithFlags(&ev_fork, cudaEventDisableTiming);
    cudaEventCreateWithFlags(&ev_join, cudaEventDisableTiming);

    // ---- fork: index chain (memset -> hist -> scan) on aux stream ----
    cudaEventRecord(ev_fork, (cudaStream_t)0);
    cudaStreamWaitEvent(s_aux, ev_fork, 0);

    cudaMemsetAsync(p_cnt, 0, (size_t)N * sizeof(int), s_aux);
    hist_kernel<<<(E + R + 255) / 256, 256, 0, s_aux>>>(ei, ri, E, R);
    size_t tb = TEMP_BYTES;
    cub::DeviceScan::ExclusiveSum(p_tmp, tb, (const int*)p_cnt, (int*)p_offs,
                                  N, s_aux);
    cudaEventRecord(ev_join, s_aux);

    // ---- main stream: fp16 tensor-core MLP partials (overlaps aux) ----
    int n_tiles = (N + 31) / 32;
    int grid = 148 * 3;
    if (grid > n_tiles) grid = n_tiles;
    precompute_mma<<<grid, 128>>>(emb, W1, b1, N, n_tiles);

    // ---- join ----
    cudaStreamWaitEvent((cudaStream_t)0, ev_join, 0);

    // ---- edges + random entries, scattered into row segments ----
    int EB = (E + 255) / 256;
    int RB = (R + 255) / 256;
    edge_rand_kernel<<<EB + RB, 256>>>(ei, W2, b2, eps_u, rb_u, ri, E, R, EB);

    // ---- per-row col sort + coalesce + output ----
    int vals_only = (out_size == M) ? 1 : 0;
    row_sort_kernel<<<(N + 255) / 256, 256>>>((float*)d_out, M, N, vals_only);
}

// round 10
// speedup vs baseline: 4.6863x; 1.1688x over previous
#include <cuda_runtime.h>
#include <cuda_fp16.h>
#include <cstdint>
#include <math.h>
#include <cub/device/device_scan.cuh>

// Problem-fixed sizes (from setup_inputs): N=300000, D=64, E=1000000, R=100000
#define DD 64
static const int    N_MAX = 300032;
static const int    M_MAX = 1200000;
static const size_t TEMP_BYTES = 4u << 20;

// Scratch (device globals — allocation-free per harness rules)
__device__ __align__(16) __half2 g_A[(size_t)N_MAX * 32];   // [N][64] fp16 (b1 folded)
__device__ __align__(16) __half2 g_B[(size_t)N_MAX * 32];
__device__ int            g_cnt [N_MAX];             // per-row entry count
__device__ int            g_offs[N_MAX + 1];         // exclusive prefix -> cursor
__device__ unsigned       g_cols_s[M_MAX];           // scattered cols (row-grouped)
__device__ float          g_vals_s[M_MAX];           // scattered vals
__device__ int            g_rows_s[M_MAX];           // scattered row ids
__device__ unsigned char  g_temp[TEMP_BYTES];        // CUB scan temp

// ---------------------------------------------------------------------------
// Kernel 1: fp16 tensor-core node-factored MLP partials, double-buffered.
// (unchanged from R7/R8 winner)
// ---------------------------------------------------------------------------
#define PITCH2 36   // half2 pitch: fragment LDS banks (4*gid+tig)%32 distinct

__global__ void __launch_bounds__(128, 3)
precompute_mma(const float* __restrict__ emb,
               const float* __restrict__ W1,
               const float* __restrict__ b1,
               int N, int n_tiles) {
    __shared__ __align__(16) __half2 sE[2][32 * PITCH2];
    __shared__ __align__(16) __half2 sStage[4][16 * PITCH2];

    const int tid  = threadIdx.x;
    const int warp = tid >> 5;
    const int lane = tid & 31;
    const int gid  = lane >> 2;   // 0..7
    const int tig  = lane & 3;    // 0..3
    const int T    = warp & 1;    // 0 -> g_A (W1 left), 1 -> g_B (W1 right)
    const int base = (warp >> 1) * 16;

    const int lni = tid >> 5;          // row 0..3 (+4 per j)
    const int lh  = tid & 31;          // half2 col

    unsigned bf[4][8][2];
    float2   b1v[8];
#pragma unroll
    for (int nt = 0; nt < 8; ++nt) {
        int c = nt * 8 + gid;
        const float* wrow = W1 + (size_t)c * 128 + (T ? 64 : 0);
#pragma unroll
        for (int kt = 0; kt < 4; ++kt) {
            __half2 lo = __floats2half2_rn(__ldg(wrow + kt * 16 + 2 * tig),
                                           __ldg(wrow + kt * 16 + 2 * tig + 1));
            __half2 hi = __floats2half2_rn(__ldg(wrow + kt * 16 + 2 * tig + 8),
                                           __ldg(wrow + kt * 16 + 2 * tig + 9));
            bf[kt][nt][0] = *(unsigned*)&lo;
            bf[kt][nt][1] = *(unsigned*)&hi;
        }
        b1v[nt] = T ? make_float2(0.f, 0.f)
                    : __ldg((const float2*)b1 + nt * 4 + tig);
    }

    __half2* tab = T ? g_B : g_A;
    __half2* st  = &sStage[warp][0];

    const int G = gridDim.x;
    int t = blockIdx.x;

    float2 r[8];
#pragma unroll
    for (int j = 0; j < 8; ++j) {
        int n = t * 32 + j * 4 + lni;
        r[j] = (t < n_tiles && n < N)
                   ? __ldg((const float2*)(emb + (size_t)n * DD) + lh)
                   : make_float2(0.f, 0.f);
    }
#pragma unroll
    for (int j = 0; j < 8; ++j)
        sE[0][(j * 4 + lni) * PITCH2 + lh] = __floats2half2_rn(r[j].x, r[j].y);
    __syncthreads();

    int buf = 0;
    for (; t < n_tiles; t += G) {
        const int tn = t + G;
        if (tn < n_tiles) {
#pragma unroll
            for (int j = 0; j < 8; ++j) {
                int n = tn * 32 + j * 4 + lni;
                r[j] = (n < N)
                           ? __ldg((const float2*)(emb + (size_t)n * DD) + lh)
                           : make_float2(0.f, 0.f);
            }
        }

        const int n0 = t * 32;
        const __half2* p0 = &sE[buf][(base + gid)     * PITCH2];
        const __half2* p1 = &sE[buf][(base + gid + 8) * PITCH2];

        float acc[8][4];
#pragma unroll
        for (int nt = 0; nt < 8; ++nt)
#pragma unroll
            for (int c = 0; c < 4; ++c) acc[nt][c] = 0.f;

#pragma unroll
        for (int kt = 0; kt < 4; ++kt) {
            unsigned a0 = *(const unsigned*)&p0[kt * 8 + tig];
            unsigned a1 = *(const unsigned*)&p1[kt * 8 + tig];
            unsigned a2 = *(const unsigned*)&p0[kt * 8 + tig + 4];
            unsigned a3 = *(const unsigned*)&p1[kt * 8 + tig + 4];
#pragma unroll
            for (int nt = 0; nt < 8; ++nt) {
                asm volatile(
                    "mma.sync.aligned.m16n8k16.row.col.f32.f16.f16.f32 "
                    "{%0,%1,%2,%3}, {%4,%5,%6,%7}, {%8,%9}, {%0,%1,%2,%3};"
                    : "+f"(acc[nt][0]), "+f"(acc[nt][1]),
                      "+f"(acc[nt][2]), "+f"(acc[nt][3])
                    : "r"(a0), "r"(a1), "r"(a2), "r"(a3),
                      "r"(bf[kt][nt][0]), "r"(bf[kt][nt][1]));
            }
        }

#pragma unroll
        for (int nt = 0; nt < 8; ++nt) {
            float2 bb = b1v[nt];
            st[gid * PITCH2 + nt * 4 + tig] =
                __floats2half2_rn(acc[nt][0] + bb.x, acc[nt][1] + bb.y);
            st[(gid + 8) * PITCH2 + nt * 4 + tig] =
                __floats2half2_rn(acc[nt][2] + bb.x, acc[nt][3] + bb.y);
        }
        __syncwarp();
#pragma unroll
        for (int i = 0; i < 4; ++i) {
            int rr = i * 4 + (lane >> 3);
            int cc = lane & 7;
            int n  = n0 + base + rr;
            if (n < N) {
                float4 v = *(const float4*)((const char*)st + rr * (PITCH2 * 4) + cc * 16);
                *(float4*)((char*)(tab + (size_t)n * 32) + cc * 16) = v;
            }
        }

        if (tn < n_tiles) {
#pragma unroll
            for (int j = 0; j < 8; ++j)
                sE[buf ^ 1][(j * 4 + lni) * PITCH2 + lh] =
                    __floats2half2_rn(r[j].x, r[j].y);
        }
        __syncthreads();
        buf ^= 1;
    }
}

// ---------------------------------------------------------------------------
// Kernel 2: row histogram over all (edge + random) entries.
// ---------------------------------------------------------------------------
__global__ void hist_kernel(const int* __restrict__ ei,
                            const int* __restrict__ ri, int E, int R) {
    int i = blockIdx.x * blockDim.x + threadIdx.x;
    if (i < E)          atomicAdd(&g_cnt[ei[i]], 1);
    else if (i < E + R) atomicAdd(&g_cnt[ri[i - E]], 1);
}

// ---------------------------------------------------------------------------
// Kernel 3: edges + random entries in one launch (scatter row/col/val).
// ---------------------------------------------------------------------------
__global__ void edge_rand_kernel(const int* __restrict__ ei,
                                 const float* __restrict__ W2,
                                 const float* __restrict__ b2,
                                 const float* __restrict__ eps_u,
                                 const float* __restrict__ rb_u,
                                 const int* __restrict__ ri,
                                 int E, int R, int EB) {
    __shared__ float s_logit[256];

    if (blockIdx.x >= EB) {
        int r = (blockIdx.x - EB) * 256 + threadIdx.x;
        if (r < R) {
            int row = __ldg(ri + r);
            int col = __ldg(ri + R + r);
            int pos = atomicAdd(&g_offs[row], 1);
            g_cols_s[pos] = (unsigned)col;
            g_vals_s[pos] = 0.05f;
            g_rows_s[pos] = row;
        }
        return;
    }

    const int tid  = threadIdx.x;
    const int sub  = tid & 7;
    const int le   = tid >> 3;          // 0..31
    const int base = blockIdx.x * 256;

    float2 w2v[4];
#pragma unroll
    for (int q = 0; q < 4; ++q)
        w2v[q] = __ldg((const float2*)W2 + sub * 4 + q);

    float p[8];
#pragma unroll
    for (int i = 0; i < 8; ++i) {
        int e = base + i * 32 + le;
        float acc = 0.f;
        if (e < E) {
            int src = __ldg(ei + e);
            int dst = __ldg(ei + E + e);
            float4 a4 = *((const float4*)(g_A + (size_t)src * 32) + sub);
            float4 b4 = *((const float4*)(g_B + (size_t)dst * 32) + sub);
            const __half2* ah = (const __half2*)&a4;
            const __half2* bh = (const __half2*)&b4;
#pragma unroll
            for (int q = 0; q < 4; ++q) {
                float2 av = __half22float2(ah[q]);
                float2 bv = __half22float2(bh[q]);
                acc += fmaxf(av.x + bv.x, 0.0f) * w2v[q].x
                     + fmaxf(av.y + bv.y, 0.0f) * w2v[q].y;
            }
        }
        p[i] = acc;
    }
#pragma unroll
    for (int i = 0; i < 8; ++i) {
        float v = p[i];
        v += __shfl_xor_sync(0xffffffffu, v, 4);
        v += __shfl_xor_sync(0xffffffffu, v, 2);
        v += __shfl_xor_sync(0xffffffffu, v, 1);
        if (sub == 0) s_logit[i * 32 + le] = v;
    }
    __syncthreads();

    int e = base + tid;
    if (e < E) {
        int src = __ldg(ei + e);
        int dst = __ldg(ei + E + e);
        float logit = s_logit[tid] + __ldg(b2);
        float eps  = fmaf(-0.9998f, __ldg(eps_u + e), 0.9999f);
        float gate = logf(eps) - log1pf(-eps) + logit;
        float w    = 1.0f / (1.0f + expf(-gate));
        float att  = fminf(fmaxf(w, 0.01f), 0.99f);
        float u    = fminf(fmaxf(__ldg(rb_u + e), 1e-7f), 1.0f - 1e-7f);
        float sarg = (logf(att) - log1pf(-att) + logf(u) - log1pf(-u))
                     * (1.0f / 0.9f);
        float s    = 1.0f / (1.0f + expf(-sarg));
        // mask = (s > 0) is always 1 in fp32, so mat = s
        int pos = atomicAdd(&g_offs[src], 1);
        g_cols_s[pos] = (unsigned)dst;
        g_vals_s[pos] = s;
        g_rows_s[pos] = src;
    }
}

// ---------------------------------------------------------------------------
// Kernel 4: element-parallel rank/coalesce + output.
// Thread per entry: rank = #{j in segment : col_j < col_i, or equal and
// j < i}; head = no equal col with smaller scatter index; head gets the
// duplicate-sum, others 0. Output slot = start + rank (deterministic
// regardless of scatter order). out: [0..M) rows, [M..2M) cols, [2M..3M) vals.
// ---------------------------------------------------------------------------
__global__ void finalize_kernel(float* __restrict__ out, int M, int vals_only) {
    int i = blockIdx.x * blockDim.x + threadIdx.x;
    if (i >= M) return;

    int row   = g_rows_s[i];
    int end   = g_offs[row];          // segment end (post-scatter cursor)
    int cnt   = g_cnt[row];
    int start = end - cnt;
    unsigned mycol = g_cols_s[i];
    float    sum   = g_vals_s[i];

    int  rank = 0;
    bool head = true;
    for (int j = start; j < end; ++j) {
        if (j == i) continue;
        unsigned c = g_cols_s[j];
        if (c < mycol || (c == mycol && j < i)) ++rank;
        if (c == mycol) {
            if (j < i) head = false;
            sum += g_vals_s[j];
        }
    }

    int   o  = start + rank;
    float ov = head ? sum : 0.0f;
    if (vals_only) {
        out[o] = ov;
    } else {
        out[o]         = (float)row;
        out[M + o]     = (float)mycol;
        out[2 * M + o] = ov;
    }
}

// ---------------------------------------------------------------------------
extern "C" void kernel_launch(void* const* d_in, const int* in_sizes, int n_in,
                              void* d_out, int out_size) {
    const float* emb   = (const float*)d_in[0];
    const float* W1    = (const float*)d_in[1];
    const float* b1    = (const float*)d_in[2];
    const float* W2    = (const float*)d_in[3];
    const float* b2    = (const float*)d_in[4];
    const int*   ei    = (const int*)  d_in[5];
    const int*   ri    = (const int*)  d_in[6];
    const float* eps_u = (const float*)d_in[7];
    const float* rb_u  = (const float*)d_in[8];

    const int N = in_sizes[0] / DD;
    const int E = in_sizes[5] / 2;
    const int R = in_sizes[6] / 2;
    const int M = E + R;

    void *p_cnt, *p_offs, *p_tmp;
    cudaGetSymbolAddress(&p_cnt,  g_cnt);
    cudaGetSymbolAddress(&p_offs, g_offs);
    cudaGetSymbolAddress(&p_tmp,  g_temp);

    // Aux stream + fork/join events (host objects only; leaked deliberately —
    // destroying them mid-capture would invalidate the capture).
    cudaStream_t s_aux;
    cudaEvent_t  ev_fork, ev_join;
    cudaStreamCreateWithFlags(&s_aux, cudaStreamNonBlocking);
    cudaEventCreateWithFlags(&ev_fork, cudaEventDisableTiming);
    cudaEventCreateWithFlags(&ev_join, cudaEventDisableTiming);

    // ---- fork: index chain (memset -> hist -> scan) on aux stream ----
    cudaEventRecord(ev_fork, (cudaStream_t)0);
    cudaStreamWaitEvent(s_aux, ev_fork, 0);

    cudaMemsetAsync(p_cnt, 0, (size_t)N * sizeof(int), s_aux);
    hist_kernel<<<(E + R + 255) / 256, 256, 0, s_aux>>>(ei, ri, E, R);
    size_t tb = TEMP_BYTES;
    cub::DeviceScan::ExclusiveSum(p_tmp, tb, (const int*)p_cnt, (int*)p_offs,
                                  N, s_aux);
    cudaEventRecord(ev_join, s_aux);

    // ---- main stream: fp16 tensor-core MLP partials (overlaps aux) ----
    int n_tiles = (N + 31) / 32;
    int grid = 148 * 3;
    if (grid > n_tiles) grid = n_tiles;
    precompute_mma<<<grid, 128>>>(emb, W1, b1, N, n_tiles);

    // ---- join ----
    cudaStreamWaitEvent((cudaStream_t)0, ev_join, 0);

    // ---- edges + random entries, scattered into row segments ----
    int EB = (E + 255) / 256;
    int RB = (R + 255) / 256;
    edge_rand_kernel<<<EB + RB, 256>>>(ei, W2, b2, eps_u, rb_u, ri, E, R, EB);

    // ---- element-parallel rank/coalesce + output ----
    int vals_only = (out_size == M) ? 1 : 0;
    finalize_kernel<<<(M + 255) / 256, 256>>>((float*)d_out, M, vals_only);
}

// round 11
// speedup vs baseline: 4.8792x; 1.0412x over previous
#include <cuda_runtime.h>
#include <cuda_fp16.h>
#include <cstdint>
#include <math.h>
#include <cub/device/device_scan.cuh>

// Problem-fixed sizes (from setup_inputs): N=300000, D=64, E=1000000, R=100000
#define DD 64
static const int    N_MAX = 300032;
static const int    M_MAX = 1200000;
static const size_t TEMP_BYTES = 4u << 20;

// Scratch (device globals — allocation-free per harness rules)
__device__ __align__(16) __half2 g_A[(size_t)N_MAX * 32];   // [N][64] fp16 (b1 folded)
__device__ __align__(16) __half2 g_B[(size_t)N_MAX * 32];
__device__ int            g_cnt [N_MAX];             // per-row entry count
__device__ int            g_offs[N_MAX + 1];         // exclusive prefix -> cursor
__device__ unsigned       g_cols_s[M_MAX];           // scattered cols (row-grouped)
__device__ float          g_vals_s[M_MAX];           // scattered vals
__device__ int            g_rows_s[M_MAX];           // scattered row ids
__device__ unsigned char  g_temp[TEMP_BYTES];        // CUB scan temp

// ---------------------------------------------------------------------------
// Kernel 1: fp16 tensor-core node-factored MLP partials, double-buffered.
// (unchanged from R7-R9 winner)
// ---------------------------------------------------------------------------
#define PITCH2 36   // half2 pitch: fragment LDS banks (4*gid+tig)%32 distinct

__global__ void __launch_bounds__(128, 3)
precompute_mma(const float* __restrict__ emb,
               const float* __restrict__ W1,
               const float* __restrict__ b1,
               int N, int n_tiles) {
    __shared__ __align__(16) __half2 sE[2][32 * PITCH2];
    __shared__ __align__(16) __half2 sStage[4][16 * PITCH2];

    const int tid  = threadIdx.x;
    const int warp = tid >> 5;
    const int lane = tid & 31;
    const int gid  = lane >> 2;   // 0..7
    const int tig  = lane & 3;    // 0..3
    const int T    = warp & 1;    // 0 -> g_A (W1 left), 1 -> g_B (W1 right)
    const int base = (warp >> 1) * 16;

    const int lni = tid >> 5;          // row 0..3 (+4 per j)
    const int lh  = tid & 31;          // half2 col

    unsigned bf[4][8][2];
    float2   b1v[8];
#pragma unroll
    for (int nt = 0; nt < 8; ++nt) {
        int c = nt * 8 + gid;
        const float* wrow = W1 + (size_t)c * 128 + (T ? 64 : 0);
#pragma unroll
        for (int kt = 0; kt < 4; ++kt) {
            __half2 lo = __floats2half2_rn(__ldg(wrow + kt * 16 + 2 * tig),
                                           __ldg(wrow + kt * 16 + 2 * tig + 1));
            __half2 hi = __floats2half2_rn(__ldg(wrow + kt * 16 + 2 * tig + 8),
                                           __ldg(wrow + kt * 16 + 2 * tig + 9));
            bf[kt][nt][0] = *(unsigned*)&lo;
            bf[kt][nt][1] = *(unsigned*)&hi;
        }
        b1v[nt] = T ? make_float2(0.f, 0.f)
                    : __ldg((const float2*)b1 + nt * 4 + tig);
    }

    __half2* tab = T ? g_B : g_A;
    __half2* st  = &sStage[warp][0];

    const int G = gridDim.x;
    int t = blockIdx.x;

    float2 r[8];
#pragma unroll
    for (int j = 0; j < 8; ++j) {
        int n = t * 32 + j * 4 + lni;
        r[j] = (t < n_tiles && n < N)
                   ? __ldg((const float2*)(emb + (size_t)n * DD) + lh)
                   : make_float2(0.f, 0.f);
    }
#pragma unroll
    for (int j = 0; j < 8; ++j)
        sE[0][(j * 4 + lni) * PITCH2 + lh] = __floats2half2_rn(r[j].x, r[j].y);
    __syncthreads();

    int buf = 0;
    for (; t < n_tiles; t += G) {
        const int tn = t + G;
        if (tn < n_tiles) {
#pragma unroll
            for (int j = 0; j < 8; ++j) {
                int n = tn * 32 + j * 4 + lni;
                r[j] = (n < N)
                           ? __ldg((const float2*)(emb + (size_t)n * DD) + lh)
                           : make_float2(0.f, 0.f);
            }
        }

        const int n0 = t * 32;
        const __half2* p0 = &sE[buf][(base + gid)     * PITCH2];
        const __half2* p1 = &sE[buf][(base + gid + 8) * PITCH2];

        float acc[8][4];
#pragma unroll
        for (int nt = 0; nt < 8; ++nt)
#pragma unroll
            for (int c = 0; c < 4; ++c) acc[nt][c] = 0.f;

#pragma unroll
        for (int kt = 0; kt < 4; ++kt) {
            unsigned a0 = *(const unsigned*)&p0[kt * 8 + tig];
            unsigned a1 = *(const unsigned*)&p1[kt * 8 + tig];
            unsigned a2 = *(const unsigned*)&p0[kt * 8 + tig + 4];
            unsigned a3 = *(const unsigned*)&p1[kt * 8 + tig + 4];
#pragma unroll
            for (int nt = 0; nt < 8; ++nt) {
                asm volatile(
                    "mma.sync.aligned.m16n8k16.row.col.f32.f16.f16.f32 "
                    "{%0,%1,%2,%3}, {%4,%5,%6,%7}, {%8,%9}, {%0,%1,%2,%3};"
                    : "+f"(acc[nt][0]), "+f"(acc[nt][1]),
                      "+f"(acc[nt][2]), "+f"(acc[nt][3])
                    : "r"(a0), "r"(a1), "r"(a2), "r"(a3),
                      "r"(bf[kt][nt][0]), "r"(bf[kt][nt][1]));
            }
        }

#pragma unroll
        for (int nt = 0; nt < 8; ++nt) {
            float2 bb = b1v[nt];
            st[gid * PITCH2 + nt * 4 + tig] =
                __floats2half2_rn(acc[nt][0] + bb.x, acc[nt][1] + bb.y);
            st[(gid + 8) * PITCH2 + nt * 4 + tig] =
                __floats2half2_rn(acc[nt][2] + bb.x, acc[nt][3] + bb.y);
        }
        __syncwarp();
#pragma unroll
        for (int i = 0; i < 4; ++i) {
            int rr = i * 4 + (lane >> 3);
            int cc = lane & 7;
            int n  = n0 + base + rr;
            if (n < N) {
                float4 v = *(const float4*)((const char*)st + rr * (PITCH2 * 4) + cc * 16);
                *(float4*)((char*)(tab + (size_t)n * 32) + cc * 16) = v;
            }
        }

        if (tn < n_tiles) {
#pragma unroll
            for (int j = 0; j < 8; ++j)
                sE[buf ^ 1][(j * 4 + lni) * PITCH2 + lh] =
                    __floats2half2_rn(r[j].x, r[j].y);
        }
        __syncthreads();
        buf ^= 1;
    }
}

// ---------------------------------------------------------------------------
// Kernel 2: row histogram over all (edge + random) entries.
// ---------------------------------------------------------------------------
__global__ void hist_kernel(const int* __restrict__ ei,
                            const int* __restrict__ ri, int E, int R) {
    int i = blockIdx.x * blockDim.x + threadIdx.x;
    if (i < E)          atomicAdd(&g_cnt[ei[i]], 1);
    else if (i < E + R) atomicAdd(&g_cnt[ri[i - E]], 1);
}

// ---------------------------------------------------------------------------
// Kernel 3: edges + random entries in one launch (scatter row/col/val).
// Gate chain collapsed into log2-space:
//   s = z/(1+z), z = 2^Lz,
//   Lz = (clamp(log2(eps)-log2(1-eps)+logit*log2e, +-log2 99)
//         + log2(u) - log2(1-u)) * (10/9)
// Algebraically identical to sigmoid/Gumbel/RelaxedBernoulli reference.
// ---------------------------------------------------------------------------
__global__ void edge_rand_kernel(const int* __restrict__ ei,
                                 const float* __restrict__ W2,
                                 const float* __restrict__ b2,
                                 const float* __restrict__ eps_u,
                                 const float* __restrict__ rb_u,
                                 const int* __restrict__ ri,
                                 int E, int R, int EB) {
    __shared__ float s_logit[256];

    if (blockIdx.x >= EB) {
        int r = (blockIdx.x - EB) * 256 + threadIdx.x;
        if (r < R) {
            int row = __ldg(ri + r);
            int col = __ldg(ri + R + r);
            int pos = atomicAdd(&g_offs[row], 1);
            g_cols_s[pos] = (unsigned)col;
            g_vals_s[pos] = 0.05f;
            g_rows_s[pos] = row;
        }
        return;
    }

    const int tid  = threadIdx.x;
    const int sub  = tid & 7;
    const int le   = tid >> 3;          // 0..31
    const int base = blockIdx.x * 256;

    float2 w2v[4];
#pragma unroll
    for (int q = 0; q < 4; ++q)
        w2v[q] = __ldg((const float2*)W2 + sub * 4 + q);

    float p[8];
#pragma unroll
    for (int i = 0; i < 8; ++i) {
        int e = base + i * 32 + le;
        float acc = 0.f;
        if (e < E) {
            int src = __ldg(ei + e);
            int dst = __ldg(ei + E + e);
            float4 a4 = *((const float4*)(g_A + (size_t)src * 32) + sub);
            float4 b4 = *((const float4*)(g_B + (size_t)dst * 32) + sub);
            const __half2* ah = (const __half2*)&a4;
            const __half2* bh = (const __half2*)&b4;
#pragma unroll
            for (int q = 0; q < 4; ++q) {
                float2 av = __half22float2(ah[q]);
                float2 bv = __half22float2(bh[q]);
                acc += fmaxf(av.x + bv.x, 0.0f) * w2v[q].x
                     + fmaxf(av.y + bv.y, 0.0f) * w2v[q].y;
            }
        }
        p[i] = acc;
    }
#pragma unroll
    for (int i = 0; i < 8; ++i) {
        float v = p[i];
        v += __shfl_xor_sync(0xffffffffu, v, 4);
        v += __shfl_xor_sync(0xffffffffu, v, 2);
        v += __shfl_xor_sync(0xffffffffu, v, 1);
        if (sub == 0) s_logit[i * 32 + le] = v;
    }
    __syncthreads();

    int e = base + tid;
    if (e < E) {
        const float LOG2E  = 1.4426950408889634f;
        const float LOG299 = 6.6293566200796095f;   // log2(99)

        int src = __ldg(ei + e);
        int dst = __ldg(ei + E + e);
        float logit = s_logit[tid] + __ldg(b2);

        float eu        = __ldg(eps_u + e);
        float eps       = fmaf(-0.9998f, eu, 0.9999f);
        float one_m_eps = fmaf( 0.9998f, eu, 0.0001f);   // exact complement
        float u         = fminf(fmaxf(__ldg(rb_u + e), 1e-7f), 1.0f - 1e-7f);
        float one_m_u   = 1.0f - u;

        float La = __log2f(eps) - __log2f(one_m_eps) + logit * LOG2E;
        float Lc = fminf(fmaxf(La, -LOG299), LOG299);
        float Lz = (Lc + __log2f(u) - __log2f(one_m_u)) * (10.0f / 9.0f);
        float z  = exp2f(Lz);
        float s  = __fdividef(z, 1.0f + z);
        // mask = (s > 0) is always 1 (z > 0), so mat = s
        int pos = atomicAdd(&g_offs[src], 1);
        g_cols_s[pos] = (unsigned)dst;
        g_vals_s[pos] = s;
        g_rows_s[pos] = src;
    }
}

// ---------------------------------------------------------------------------
// Kernel 4: element-parallel rank/coalesce + output.
// out layout: [0..M) rows, [M..2M) cols, [2M..3M) vals (float32)
// ---------------------------------------------------------------------------
__global__ void finalize_kernel(float* __restrict__ out, int M, int vals_only) {
    int i = blockIdx.x * blockDim.x + threadIdx.x;
    if (i >= M) return;

    int row   = g_rows_s[i];
    int end   = g_offs[row];          // segment end (post-scatter cursor)
    int cnt   = g_cnt[row];
    int start = end - cnt;
    unsigned mycol = g_cols_s[i];
    float    sum   = g_vals_s[i];

    int  rank = 0;
    bool head = true;
    for (int j = start; j < end; ++j) {
        if (j == i) continue;
        unsigned c = g_cols_s[j];
        if (c < mycol || (c == mycol && j < i)) ++rank;
        if (c == mycol) {
            if (j < i) head = false;
            sum += g_vals_s[j];
        }
    }

    int   o  = start + rank;
    float ov = head ? sum : 0.0f;
    if (vals_only) {
        out[o] = ov;
    } else {
        out[o]         = (float)row;
        out[M + o]     = (float)mycol;
        out[2 * M + o] = ov;
    }
}

// ---------------------------------------------------------------------------
extern "C" void kernel_launch(void* const* d_in, const int* in_sizes, int n_in,
                              void* d_out, int out_size) {
    const float* emb   = (const float*)d_in[0];
    const float* W1    = (const float*)d_in[1];
    const float* b1    = (const float*)d_in[2];
    const float* W2    = (const float*)d_in[3];
    const float* b2    = (const float*)d_in[4];
    const int*   ei    = (const int*)  d_in[5];
    const int*   ri    = (const int*)  d_in[6];
    const float* eps_u = (const float*)d_in[7];
    const float* rb_u  = (const float*)d_in[8];

    const int N = in_sizes[0] / DD;
    const int E = in_sizes[5] / 2;
    const int R = in_sizes[6] / 2;
    const int M = E + R;

    void *p_cnt, *p_offs, *p_tmp;
    cudaGetSymbolAddress(&p_cnt,  g_cnt);
    cudaGetSymbolAddress(&p_offs, g_offs);
    cudaGetSymbolAddress(&p_tmp,  g_temp);

    // Aux stream + fork/join events (host objects only; leaked deliberately —
    // destroying them mid-capture would invalidate the capture).
    cudaStream_t s_aux;
    cudaEvent_t  ev_fork, ev_join;
    cudaStreamCreateWithFlags(&s_aux, cudaStreamNonBlocking);
    cudaEventCreateWithFlags(&ev_fork, cudaEventDisableTiming);
    cudaEventCreateWithFlags(&ev_join, cudaEventDisableTiming);

    // ---- fork: index chain (memset -> hist -> scan) on aux stream ----
    cudaEventRecord(ev_fork, (cudaStream_t)0);
    cudaStreamWaitEvent(s_aux, ev_fork, 0);

    cudaMemsetAsync(p_cnt, 0, (size_t)N * sizeof(int), s_aux);
    hist_kernel<<<(E + R + 255) / 256, 256, 0, s_aux>>>(ei, ri, E, R);
    size_t tb = TEMP_BYTES;
    cub::DeviceScan::ExclusiveSum(p_tmp, tb, (const int*)p_cnt, (int*)p_offs,
                                  N, s_aux);
    cudaEventRecord(ev_join, s_aux);

    // ---- main stream: fp16 tensor-core MLP partials (overlaps aux) ----
    int n_tiles = (N + 31) / 32;
    int grid = 148 * 3;
    if (grid > n_tiles) grid = n_tiles;
    precompute_mma<<<grid, 128>>>(emb, W1, b1, N, n_tiles);

    // ---- join ----
    cudaStreamWaitEvent((cudaStream_t)0, ev_join, 0);

    // ---- edges + random entries, scattered into row segments ----
    int EB = (E + 255) / 256;
    int RB = (R + 255) / 256;
    edge_rand_kernel<<<EB + RB, 256>>>(ei, W2, b2, eps_u, rb_u, ri, E, R, EB);

    // ---- element-parallel rank/coalesce + output ----
    int vals_only = (out_size == M) ? 1 : 0;
    finalize_kernel<<<(M + 255) / 256, 256>>>((float*)d_out, M, vals_only);
}

// round 12
// speedup vs baseline: 5.0901x; 1.0432x over previous
#include <cuda_runtime.h>
#include <cuda_fp16.h>
#include <cstdint>
#include <math.h>
#include <cub/device/device_scan.cuh>

// Problem-fixed sizes (from setup_inputs): N=300000, D=64, E=1000000, R=100000
#define DD 64
static const int    N_MAX = 300032;
static const int    M_MAX = 1200000;
static const size_t TEMP_BYTES = 4u << 20;

// Scratch (device globals — allocation-free per harness rules)
__device__ __align__(16) __half2 g_A[(size_t)N_MAX * 32];   // [N][64] fp16 (b1 folded)
__device__ __align__(16) __half2 g_B[(size_t)N_MAX * 32];
__device__ int            g_cnt [N_MAX];             // per-row entry count
__device__ int            g_offs[N_MAX + 1];         // exclusive prefix -> cursor
__device__ __align__(16) uint4 g_ent[M_MAX];         // packed (row, col, valbits, 0)
__device__ unsigned char  g_temp[TEMP_BYTES];        // CUB scan temp

// ---------------------------------------------------------------------------
// Kernel 1: fp16 tensor-core node-factored MLP partials, double-buffered.
// (unchanged from R7-R10 winner)
// ---------------------------------------------------------------------------
#define PITCH2 36   // half2 pitch: fragment LDS banks (4*gid+tig)%32 distinct

__global__ void __launch_bounds__(128, 3)
precompute_mma(const float* __restrict__ emb,
               const float* __restrict__ W1,
               const float* __restrict__ b1,
               int N, int n_tiles) {
    __shared__ __align__(16) __half2 sE[2][32 * PITCH2];
    __shared__ __align__(16) __half2 sStage[4][16 * PITCH2];

    const int tid  = threadIdx.x;
    const int warp = tid >> 5;
    const int lane = tid & 31;
    const int gid  = lane >> 2;   // 0..7
    const int tig  = lane & 3;    // 0..3
    const int T    = warp & 1;    // 0 -> g_A (W1 left), 1 -> g_B (W1 right)
    const int base = (warp >> 1) * 16;

    const int lni = tid >> 5;          // row 0..3 (+4 per j)
    const int lh  = tid & 31;          // half2 col

    unsigned bf[4][8][2];
    float2   b1v[8];
#pragma unroll
    for (int nt = 0; nt < 8; ++nt) {
        int c = nt * 8 + gid;
        const float* wrow = W1 + (size_t)c * 128 + (T ? 64 : 0);
#pragma unroll
        for (int kt = 0; kt < 4; ++kt) {
            __half2 lo = __floats2half2_rn(__ldg(wrow + kt * 16 + 2 * tig),
                                           __ldg(wrow + kt * 16 + 2 * tig + 1));
            __half2 hi = __floats2half2_rn(__ldg(wrow + kt * 16 + 2 * tig + 8),
                                           __ldg(wrow + kt * 16 + 2 * tig + 9));
            bf[kt][nt][0] = *(unsigned*)&lo;
            bf[kt][nt][1] = *(unsigned*)&hi;
        }
        b1v[nt] = T ? make_float2(0.f, 0.f)
                    : __ldg((const float2*)b1 + nt * 4 + tig);
    }

    __half2* tab = T ? g_B : g_A;
    __half2* st  = &sStage[warp][0];

    const int G = gridDim.x;
    int t = blockIdx.x;

    float2 r[8];
#pragma unroll
    for (int j = 0; j < 8; ++j) {
        int n = t * 32 + j * 4 + lni;
        r[j] = (t < n_tiles && n < N)
                   ? __ldg((const float2*)(emb + (size_t)n * DD) + lh)
                   : make_float2(0.f, 0.f);
    }
#pragma unroll
    for (int j = 0; j < 8; ++j)
        sE[0][(j * 4 + lni) * PITCH2 + lh] = __floats2half2_rn(r[j].x, r[j].y);
    __syncthreads();

    int buf = 0;
    for (; t < n_tiles; t += G) {
        const int tn = t + G;
        if (tn < n_tiles) {
#pragma unroll
            for (int j = 0; j < 8; ++j) {
                int n = tn * 32 + j * 4 + lni;
                r[j] = (n < N)
                           ? __ldg((const float2*)(emb + (size_t)n * DD) + lh)
                           : make_float2(0.f, 0.f);
            }
        }

        const int n0 = t * 32;
        const __half2* p0 = &sE[buf][(base + gid)     * PITCH2];
        const __half2* p1 = &sE[buf][(base + gid + 8) * PITCH2];

        float acc[8][4];
#pragma unroll
        for (int nt = 0; nt < 8; ++nt)
#pragma unroll
            for (int c = 0; c < 4; ++c) acc[nt][c] = 0.f;

#pragma unroll
        for (int kt = 0; kt < 4; ++kt) {
            unsigned a0 = *(const unsigned*)&p0[kt * 8 + tig];
            unsigned a1 = *(const unsigned*)&p1[kt * 8 + tig];
            unsigned a2 = *(const unsigned*)&p0[kt * 8 + tig + 4];
            unsigned a3 = *(const unsigned*)&p1[kt * 8 + tig + 4];
#pragma unroll
            for (int nt = 0; nt < 8; ++nt) {
                asm volatile(
                    "mma.sync.aligned.m16n8k16.row.col.f32.f16.f16.f32 "
                    "{%0,%1,%2,%3}, {%4,%5,%6,%7}, {%8,%9}, {%0,%1,%2,%3};"
                    : "+f"(acc[nt][0]), "+f"(acc[nt][1]),
                      "+f"(acc[nt][2]), "+f"(acc[nt][3])
                    : "r"(a0), "r"(a1), "r"(a2), "r"(a3),
                      "r"(bf[kt][nt][0]), "r"(bf[kt][nt][1]));
            }
        }

#pragma unroll
        for (int nt = 0; nt < 8; ++nt) {
            float2 bb = b1v[nt];
            st[gid * PITCH2 + nt * 4 + tig] =
                __floats2half2_rn(acc[nt][0] + bb.x, acc[nt][1] + bb.y);
            st[(gid + 8) * PITCH2 + nt * 4 + tig] =
                __floats2half2_rn(acc[nt][2] + bb.x, acc[nt][3] + bb.y);
        }
        __syncwarp();
#pragma unroll
        for (int i = 0; i < 4; ++i) {
            int rr = i * 4 + (lane >> 3);
            int cc = lane & 7;
            int n  = n0 + base + rr;
            if (n < N) {
                float4 v = *(const float4*)((const char*)st + rr * (PITCH2 * 4) + cc * 16);
                *(float4*)((char*)(tab + (size_t)n * 32) + cc * 16) = v;
            }
        }

        if (tn < n_tiles) {
#pragma unroll
            for (int j = 0; j < 8; ++j)
                sE[buf ^ 1][(j * 4 + lni) * PITCH2 + lh] =
                    __floats2half2_rn(r[j].x, r[j].y);
        }
        __syncthreads();
        buf ^= 1;
    }
}

// ---------------------------------------------------------------------------
// Kernel 2: row histogram over all (edge + random) entries.
// ---------------------------------------------------------------------------
__global__ void hist_kernel(const int* __restrict__ ei,
                            const int* __restrict__ ri, int E, int R) {
    int i = blockIdx.x * blockDim.x + threadIdx.x;
    if (i < E)          atomicAdd(&g_cnt[ei[i]], 1);
    else if (i < E + R) atomicAdd(&g_cnt[ri[i - E]], 1);
}

// ---------------------------------------------------------------------------
// Kernel 3: edges + random entries in one launch; packed uint4 scatter
// (one STG.128 = one sector, vs three scattered 4B stores).
// Gate chain in log2-space (algebraically identical to reference).
// ---------------------------------------------------------------------------
__global__ void edge_rand_kernel(const int* __restrict__ ei,
                                 const float* __restrict__ W2,
                                 const float* __restrict__ b2,
                                 const float* __restrict__ eps_u,
                                 const float* __restrict__ rb_u,
                                 const int* __restrict__ ri,
                                 int E, int R, int EB) {
    __shared__ float s_logit[256];

    if (blockIdx.x >= EB) {
        int r = (blockIdx.x - EB) * 256 + threadIdx.x;
        if (r < R) {
            int row = __ldg(ri + r);
            int col = __ldg(ri + R + r);
            int pos = atomicAdd(&g_offs[row], 1);
            g_ent[pos] = make_uint4((unsigned)row, (unsigned)col,
                                    __float_as_uint(0.05f), 0u);
        }
        return;
    }

    const int tid  = threadIdx.x;
    const int sub  = tid & 7;
    const int le   = tid >> 3;          // 0..31
    const int base = blockIdx.x * 256;

    float2 w2v[4];
#pragma unroll
    for (int q = 0; q < 4; ++q)
        w2v[q] = __ldg((const float2*)W2 + sub * 4 + q);

    float p[8];
#pragma unroll
    for (int i = 0; i < 8; ++i) {
        int e = base + i * 32 + le;
        float acc = 0.f;
        if (e < E) {
            int src = __ldg(ei + e);
            int dst = __ldg(ei + E + e);
            float4 a4 = *((const float4*)(g_A + (size_t)src * 32) + sub);
            float4 b4 = *((const float4*)(g_B + (size_t)dst * 32) + sub);
            const __half2* ah = (const __half2*)&a4;
            const __half2* bh = (const __half2*)&b4;
#pragma unroll
            for (int q = 0; q < 4; ++q) {
                float2 av = __half22float2(ah[q]);
                float2 bv = __half22float2(bh[q]);
                acc += fmaxf(av.x + bv.x, 0.0f) * w2v[q].x
                     + fmaxf(av.y + bv.y, 0.0f) * w2v[q].y;
            }
        }
        p[i] = acc;
    }
#pragma unroll
    for (int i = 0; i < 8; ++i) {
        float v = p[i];
        v += __shfl_xor_sync(0xffffffffu, v, 4);
        v += __shfl_xor_sync(0xffffffffu, v, 2);
        v += __shfl_xor_sync(0xffffffffu, v, 1);
        if (sub == 0) s_logit[i * 32 + le] = v;
    }
    __syncthreads();

    int e = base + tid;
    if (e < E) {
        const float LOG2E  = 1.4426950408889634f;
        const float LOG299 = 6.6293566200796095f;   // log2(99)

        int src = __ldg(ei + e);
        int dst = __ldg(ei + E + e);
        float logit = s_logit[tid] + __ldg(b2);

        float eu        = __ldg(eps_u + e);
        float eps       = fmaf(-0.9998f, eu, 0.9999f);
        float one_m_eps = fmaf( 0.9998f, eu, 0.0001f);   // exact complement
        float u         = fminf(fmaxf(__ldg(rb_u + e), 1e-7f), 1.0f - 1e-7f);
        float one_m_u   = 1.0f - u;

        float La = __log2f(eps) - __log2f(one_m_eps) + logit * LOG2E;
        float Lc = fminf(fmaxf(La, -LOG299), LOG299);
        float Lz = (Lc + __log2f(u) - __log2f(one_m_u)) * (10.0f / 9.0f);
        float z  = exp2f(Lz);
        float s  = __fdividef(z, 1.0f + z);
        // mask = (s > 0) is always 1 (z > 0), so mat = s
        int pos = atomicAdd(&g_offs[src], 1);
        g_ent[pos] = make_uint4((unsigned)src, (unsigned)dst,
                                __float_as_uint(s), 0u);
    }
}

// ---------------------------------------------------------------------------
// Kernel 4: element-parallel rank/coalesce + output (packed entries).
// Thread per entry: rank within its row segment by (col, scatter idx);
// head entry of each equal-col run gets the duplicate-sum, others 0.
// out layout: [0..M) rows, [M..2M) cols, [2M..3M) vals (float32)
// ---------------------------------------------------------------------------
__global__ void finalize_kernel(float* __restrict__ out, int M, int vals_only) {
    int i = blockIdx.x * blockDim.x + threadIdx.x;
    if (i >= M) return;

    uint4 me = g_ent[i];
    int      row   = (int)me.x;
    unsigned mycol = me.y;
    float    sum   = __uint_as_float(me.z);

    int end   = g_offs[row];          // segment end (post-scatter cursor)
    int cnt   = g_cnt[row];
    int start = end - cnt;

    int  rank = 0;
    bool head = true;
    for (int j = start; j < end; ++j) {
        if (j == i) continue;
        uint4 ej = g_ent[j];
        unsigned c = ej.y;
        if (c < mycol || (c == mycol && j < i)) ++rank;
        if (c == mycol) {
            if (j < i) head = false;
            sum += __uint_as_float(ej.z);
        }
    }

    int   o  = start + rank;
    float ov = head ? sum : 0.0f;
    if (vals_only) {
        out[o] = ov;
    } else {
        out[o]         = (float)row;
        out[M + o]     = (float)mycol;
        out[2 * M + o] = ov;
    }
}

// ---------------------------------------------------------------------------
extern "C" void kernel_launch(void* const* d_in, const int* in_sizes, int n_in,
                              void* d_out, int out_size) {
    const float* emb   = (const float*)d_in[0];
    const float* W1    = (const float*)d_in[1];
    const float* b1    = (const float*)d_in[2];
    const float* W2    = (const float*)d_in[3];
    const float* b2    = (const float*)d_in[4];
    const int*   ei    = (const int*)  d_in[5];
    const int*   ri    = (const int*)  d_in[6];
    const float* eps_u = (const float*)d_in[7];
    const float* rb_u  = (const float*)d_in[8];

    const int N = in_sizes[0] / DD;
    const int E = in_sizes[5] / 2;
    const int R = in_sizes[6] / 2;
    const int M = E + R;

    void *p_cnt, *p_offs, *p_tmp;
    cudaGetSymbolAddress(&p_cnt,  g_cnt);
    cudaGetSymbolAddress(&p_offs, g_offs);
    cudaGetSymbolAddress(&p_tmp,  g_temp);

    // Aux stream + fork/join events (host objects only; leaked deliberately —
    // destroying them mid-capture would invalidate the capture).
    cudaStream_t s_aux;
    cudaEvent_t  ev_fork, ev_join;
    cudaStreamCreateWithFlags(&s_aux, cudaStreamNonBlocking);
    cudaEventCreateWithFlags(&ev_fork, cudaEventDisableTiming);
    cudaEventCreateWithFlags(&ev_join, cudaEventDisableTiming);

    // ---- fork: index chain (memset -> hist -> scan) on aux stream ----
    cudaEventRecord(ev_fork, (cudaStream_t)0);
    cudaStreamWaitEvent(s_aux, ev_fork, 0);

    cudaMemsetAsync(p_cnt, 0, (size_t)N * sizeof(int), s_aux);
    hist_kernel<<<(E + R + 255) / 256, 256, 0, s_aux>>>(ei, ri, E, R);
    size_t tb = TEMP_BYTES;
    cub::DeviceScan::ExclusiveSum(p_tmp, tb, (const int*)p_cnt, (int*)p_offs,
                                  N, s_aux);
    cudaEventRecord(ev_join, s_aux);

    // ---- main stream: fp16 tensor-core MLP partials (overlaps aux) ----
    int n_tiles = (N + 31) / 32;
    int grid = 148 * 3;
    if (grid > n_tiles) grid = n_tiles;
    precompute_mma<<<grid, 128>>>(emb, W1, b1, N, n_tiles);

    // ---- join ----
    cudaStreamWaitEvent((cudaStream_t)0, ev_join, 0);

    // ---- edges + random entries, packed scatter into row segments ----
    int EB = (E + 255) / 256;
    int RB = (R + 255) / 256;
    edge_rand_kernel<<<EB + RB, 256>>>(ei, W2, b2, eps_u, rb_u, ri, E, R, EB);

    // ---- element-parallel rank/coalesce + output ----
    int vals_only = (out_size == M) ? 1 : 0;
    finalize_kernel<<<(M + 255) / 256, 256>>>((float*)d_out, M, vals_only);
}

// round 14
// speedup vs baseline: 5.1734x; 1.0164x over previous
#include <cuda_runtime.h>
#include <cuda_fp16.h>
#include <cstdint>
#include <math.h>
#include <cub/device/device_scan.cuh>

// Problem-fixed sizes (from setup_inputs): N=300000, D=64, E=1000000, R=100000
#define DD 64
static const int    N_MAX = 300032;
static const int    M_MAX = 1200000;
static const size_t TEMP_BYTES = 4u << 20;

// Scratch (device globals — allocation-free per harness rules)
__device__ __align__(16) __half2 g_A[(size_t)N_MAX * 32];   // [N][64] fp16 (b1 folded)
__device__ __align__(16) __half2 g_B[(size_t)N_MAX * 32];
__device__ int            g_cnt [N_MAX];             // per-row entry count
__device__ int            g_offs[N_MAX + 1];         // exclusive prefix -> cursor
__device__ __align__(16) uint4 g_ent[M_MAX];         // packed (row, col, valbits, 0)
__device__ unsigned char  g_temp[TEMP_BYTES];        // CUB scan temp

// ---------------------------------------------------------------------------
// Kernel 1: fp16 tensor-core node-factored MLP partials, double-buffered.
// (unchanged from R7-R11 winner)
// ---------------------------------------------------------------------------
#define PITCH2 36   // half2 pitch: fragment LDS banks (4*gid+tig)%32 distinct

__global__ void __launch_bounds__(128, 3)
precompute_mma(const float* __restrict__ emb,
               const float* __restrict__ W1,
               const float* __restrict__ b1,
               int N, int n_tiles) {
    __shared__ __align__(16) __half2 sE[2][32 * PITCH2];
    __shared__ __align__(16) __half2 sStage[4][16 * PITCH2];

    const int tid  = threadIdx.x;
    const int warp = tid >> 5;
    const int lane = tid & 31;
    const int gid  = lane >> 2;   // 0..7
    const int tig  = lane & 3;    // 0..3
    const int T    = warp & 1;    // 0 -> g_A (W1 left), 1 -> g_B (W1 right)
    const int base = (warp >> 1) * 16;

    const int lni = tid >> 5;          // row 0..3 (+4 per j)
    const int lh  = tid & 31;          // half2 col

    unsigned bf[4][8][2];
    float2   b1v[8];
#pragma unroll
    for (int nt = 0; nt < 8; ++nt) {
        int c = nt * 8 + gid;
        const float* wrow = W1 + (size_t)c * 128 + (T ? 64 : 0);
#pragma unroll
        for (int kt = 0; kt < 4; ++kt) {
            __half2 lo = __floats2half2_rn(__ldg(wrow + kt * 16 + 2 * tig),
                                           __ldg(wrow + kt * 16 + 2 * tig + 1));
            __half2 hi = __floats2half2_rn(__ldg(wrow + kt * 16 + 2 * tig + 8),
                                           __ldg(wrow + kt * 16 + 2 * tig + 9));
            bf[kt][nt][0] = *(unsigned*)&lo;
            bf[kt][nt][1] = *(unsigned*)&hi;
        }
        b1v[nt] = T ? make_float2(0.f, 0.f)
                    : __ldg((const float2*)b1 + nt * 4 + tig);
    }

    __half2* tab = T ? g_B : g_A;
    __half2* st  = &sStage[warp][0];

    const int G = gridDim.x;
    int t = blockIdx.x;

    float2 r[8];
#pragma unroll
    for (int j = 0; j < 8; ++j) {
        int n = t * 32 + j * 4 + lni;
        r[j] = (t < n_tiles && n < N)
                   ? __ldg((const float2*)(emb + (size_t)n * DD) + lh)
                   : make_float2(0.f, 0.f);
    }
#pragma unroll
    for (int j = 0; j < 8; ++j)
        sE[0][(j * 4 + lni) * PITCH2 + lh] = __floats2half2_rn(r[j].x, r[j].y);
    __syncthreads();

    int buf = 0;
    for (; t < n_tiles; t += G) {
        const int tn = t + G;
        if (tn < n_tiles) {
#pragma unroll
            for (int j = 0; j < 8; ++j) {
                int n = tn * 32 + j * 4 + lni;
                r[j] = (n < N)
                           ? __ldg((const float2*)(emb + (size_t)n * DD) + lh)
                           : make_float2(0.f, 0.f);
            }
        }

        const int n0 = t * 32;
        const __half2* p0 = &sE[buf][(base + gid)     * PITCH2];
        const __half2* p1 = &sE[buf][(base + gid + 8) * PITCH2];

        float acc[8][4];
#pragma unroll
        for (int nt = 0; nt < 8; ++nt)
#pragma unroll
            for (int c = 0; c < 4; ++c) acc[nt][c] = 0.f;

#pragma unroll
        for (int kt = 0; kt < 4; ++kt) {
            unsigned a0 = *(const unsigned*)&p0[kt * 8 + tig];
            unsigned a1 = *(const unsigned*)&p1[kt * 8 + tig];
            unsigned a2 = *(const unsigned*)&p0[kt * 8 + tig + 4];
            unsigned a3 = *(const unsigned*)&p1[kt * 8 + tig + 4];
#pragma unroll
            for (int nt = 0; nt < 8; ++nt) {
                asm volatile(
                    "mma.sync.aligned.m16n8k16.row.col.f32.f16.f16.f32 "
                    "{%0,%1,%2,%3}, {%4,%5,%6,%7}, {%8,%9}, {%0,%1,%2,%3};"
                    : "+f"(acc[nt][0]), "+f"(acc[nt][1]),
                      "+f"(acc[nt][2]), "+f"(acc[nt][3])
                    : "r"(a0), "r"(a1), "r"(a2), "r"(a3),
                      "r"(bf[kt][nt][0]), "r"(bf[kt][nt][1]));
            }
        }

#pragma unroll
        for (int nt = 0; nt < 8; ++nt) {
            float2 bb = b1v[nt];
            st[gid * PITCH2 + nt * 4 + tig] =
                __floats2half2_rn(acc[nt][0] + bb.x, acc[nt][1] + bb.y);
            st[(gid + 8) * PITCH2 + nt * 4 + tig] =
                __floats2half2_rn(acc[nt][2] + bb.x, acc[nt][3] + bb.y);
        }
        __syncwarp();
#pragma unroll
        for (int i = 0; i < 4; ++i) {
            int rr = i * 4 + (lane >> 3);
            int cc = lane & 7;
            int n  = n0 + base + rr;
            if (n < N) {
                float4 v = *(const float4*)((const char*)st + rr * (PITCH2 * 4) + cc * 16);
                *(float4*)((char*)(tab + (size_t)n * 32) + cc * 16) = v;
            }
        }

        if (tn < n_tiles) {
#pragma unroll
            for (int j = 0; j < 8; ++j)
                sE[buf ^ 1][(j * 4 + lni) * PITCH2 + lh] =
                    __floats2half2_rn(r[j].x, r[j].y);
        }
        __syncthreads();
        buf ^= 1;
    }
}

// ---------------------------------------------------------------------------
// Kernel 2: row histogram over all (edge + random) entries.
// ---------------------------------------------------------------------------
__global__ void hist_kernel(const int* __restrict__ ei,
                            const int* __restrict__ ri, int E, int R) {
    int i = blockIdx.x * blockDim.x + threadIdx.x;
    if (i < E)          atomicAdd(&g_cnt[ei[i]], 1);
    else if (i < E + R) atomicAdd(&g_cnt[ri[i - E]], 1);
}

// ---------------------------------------------------------------------------
// Register-only half2-bits -> float2 (no pointer reinterpretation).
// ---------------------------------------------------------------------------
__device__ __forceinline__ float2 u2f2(unsigned u) {
    __half2_raw hr;
    hr.x = (unsigned short)(u & 0xFFFFu);
    hr.y = (unsigned short)(u >> 16);
    return __half22float2(__half2(hr));
}

// dot over one uint4 pair (8 halves of A-row + 8 halves of B-row)
__device__ __forceinline__ float dot_u4(uint4 a, uint4 b, const float2* w2v) {
    float acc = 0.f;
    float2 av, bv;
    av = u2f2(a.x); bv = u2f2(b.x);
    acc += fmaxf(av.x + bv.x, 0.f) * w2v[0].x + fmaxf(av.y + bv.y, 0.f) * w2v[0].y;
    av = u2f2(a.y); bv = u2f2(b.y);
    acc += fmaxf(av.x + bv.x, 0.f) * w2v[1].x + fmaxf(av.y + bv.y, 0.f) * w2v[1].y;
    av = u2f2(a.z); bv = u2f2(b.z);
    acc += fmaxf(av.x + bv.x, 0.f) * w2v[2].x + fmaxf(av.y + bv.y, 0.f) * w2v[2].y;
    av = u2f2(a.w); bv = u2f2(b.w);
    acc += fmaxf(av.x + bv.x, 0.f) * w2v[3].x + fmaxf(av.y + bv.y, 0.f) * w2v[3].y;
    return acc;
}

// ---------------------------------------------------------------------------
// Kernel 3: edges + random entries in one launch; packed uint4 scatter.
// Phase 1: index batch first, then gathers as 8 back-to-back named LDG.128
// per 4-edge group (high MLP, register-only half conversion).
// ---------------------------------------------------------------------------
__global__ void edge_rand_kernel(const int* __restrict__ ei,
                                 const float* __restrict__ W2,
                                 const float* __restrict__ b2,
                                 const float* __restrict__ eps_u,
                                 const float* __restrict__ rb_u,
                                 const int* __restrict__ ri,
                                 int E, int R, int EB) {
    __shared__ float s_logit[256];

    if (blockIdx.x >= EB) {
        int r = (blockIdx.x - EB) * 256 + threadIdx.x;
        if (r < R) {
            int row = __ldg(ri + r);
            int col = __ldg(ri + R + r);
            int pos = atomicAdd(&g_offs[row], 1);
            g_ent[pos] = make_uint4((unsigned)row, (unsigned)col,
                                    __float_as_uint(0.05f), 0u);
        }
        return;
    }

    const int tid  = threadIdx.x;
    const int sub  = tid & 7;
    const int le   = tid >> 3;          // 0..31
    const int base = blockIdx.x * 256;

    const uint4* At = (const uint4*)g_A;   // row = 8 uint4
    const uint4* Bt = (const uint4*)g_B;

    float2 w2v[4];
#pragma unroll
    for (int q = 0; q < 4; ++q)
        w2v[q] = __ldg((const float2*)W2 + sub * 4 + q);

    // batch all index loads (coalesced, L2-hot); clamp OOB lanes to row 0
    int srcs[8], dsts[8];
#pragma unroll
    for (int i = 0; i < 8; ++i) {
        int e = base + i * 32 + le;
        bool ok = (e < E);
        srcs[i] = ok ? __ldg(ei + e)     : 0;
        dsts[i] = ok ? __ldg(ei + E + e) : 0;
    }

    float p[8];
#pragma unroll
    for (int h = 0; h < 2; ++h) {
        const int i0 = h * 4;
        // 8 independent LDG.128 issued before any dependent arithmetic
        uint4 A0 = At[(size_t)srcs[i0 + 0] * 8 + sub];
        uint4 B0 = Bt[(size_t)dsts[i0 + 0] * 8 + sub];
        uint4 A1 = At[(size_t)srcs[i0 + 1] * 8 + sub];
        uint4 B1 = Bt[(size_t)dsts[i0 + 1] * 8 + sub];
        uint4 A2 = At[(size_t)srcs[i0 + 2] * 8 + sub];
        uint4 B2 = Bt[(size_t)dsts[i0 + 2] * 8 + sub];
        uint4 A3 = At[(size_t)srcs[i0 + 3] * 8 + sub];
        uint4 B3 = Bt[(size_t)dsts[i0 + 3] * 8 + sub];
        p[i0 + 0] = dot_u4(A0, B0, w2v);
        p[i0 + 1] = dot_u4(A1, B1, w2v);
        p[i0 + 2] = dot_u4(A2, B2, w2v);
        p[i0 + 3] = dot_u4(A3, B3, w2v);
    }

#pragma unroll
    for (int i = 0; i < 8; ++i) {
        float v = p[i];
        v += __shfl_xor_sync(0xffffffffu, v, 4);
        v += __shfl_xor_sync(0xffffffffu, v, 2);
        v += __shfl_xor_sync(0xffffffffu, v, 1);
        if (sub == 0) s_logit[i * 32 + le] = v;
    }
    __syncthreads();

    int e = base + tid;
    if (e < E) {
        const float LOG2E  = 1.4426950408889634f;
        const float LOG299 = 6.6293566200796095f;   // log2(99)

        int src = __ldg(ei + e);
        int dst = __ldg(ei + E + e);
        float logit = s_logit[tid] + __ldg(b2);

        float eu        = __ldg(eps_u + e);
        float eps       = fmaf(-0.9998f, eu, 0.9999f);
        float one_m_eps = fmaf( 0.9998f, eu, 0.0001f);   // exact complement
        float u         = fminf(fmaxf(__ldg(rb_u + e), 1e-7f), 1.0f - 1e-7f);
        float one_m_u   = 1.0f - u;

        float La = __log2f(eps) - __log2f(one_m_eps) + logit * LOG2E;
        float Lc = fminf(fmaxf(La, -LOG299), LOG299);
        float Lz = (Lc + __log2f(u) - __log2f(one_m_u)) * (10.0f / 9.0f);
        float z  = exp2f(Lz);
        float s  = __fdividef(z, 1.0f + z);
        // mask = (s > 0) is always 1 (z > 0), so mat = s
        int pos = atomicAdd(&g_offs[src], 1);
        g_ent[pos] = make_uint4((unsigned)src, (unsigned)dst,
                                __float_as_uint(s), 0u);
    }
}

// ---------------------------------------------------------------------------
// Kernel 4: element-parallel rank/coalesce + output (packed entries).
// out layout: [0..M) rows, [M..2M) cols, [2M..3M) vals (float32)
// ---------------------------------------------------------------------------
__global__ void finalize_kernel(float* __restrict__ out, int M, int vals_only) {
    int i = blockIdx.x * blockDim.x + threadIdx.x;
    if (i >= M) return;

    uint4 me = g_ent[i];
    int      row   = (int)me.x;
    unsigned mycol = me.y;
    float    sum   = __uint_as_float(me.z);

    int end   = g_offs[row];          // segment end (post-scatter cursor)
    int cnt   = g_cnt[row];
    int start = end - cnt;

    int  rank = 0;
    bool head = true;
    for (int j = start; j < end; ++j) {
        if (j == i) continue;
        uint4 ej = g_ent[j];
        unsigned c = ej.y;
        if (c < mycol || (c == mycol && j < i)) ++rank;
        if (c == mycol) {
            if (j < i) head = false;
            sum += __uint_as_float(ej.z);
        }
    }

    int   o  = start + rank;
    float ov = head ? sum : 0.0f;
    if (vals_only) {
        out[o] = ov;
    } else {
        out[o]         = (float)row;
        out[M + o]     = (float)mycol;
        out[2 * M + o] = ov;
    }
}

// ---------------------------------------------------------------------------
extern "C" void kernel_launch(void* const* d_in, const int* in_sizes, int n_in,
                              void* d_out, int out_size) {
    const float* emb   = (const float*)d_in[0];
    const float* W1    = (const float*)d_in[1];
    const float* b1    = (const float*)d_in[2];
    const float* W2    = (const float*)d_in[3];
    const float* b2    = (const float*)d_in[4];
    const int*   ei    = (const int*)  d_in[5];
    const int*   ri    = (const int*)  d_in[6];
    const float* eps_u = (const float*)d_in[7];
    const float* rb_u  = (const float*)d_in[8];

    const int N = in_sizes[0] / DD;
    const int E = in_sizes[5] / 2;
    const int R = in_sizes[6] / 2;
    const int M = E + R;

    void *p_cnt, *p_offs, *p_tmp;
    cudaGetSymbolAddress(&p_cnt,  g_cnt);
    cudaGetSymbolAddress(&p_offs, g_offs);
    cudaGetSymbolAddress(&p_tmp,  g_temp);

    // Aux stream + fork/join events (host objects only; leaked deliberately —
    // destroying them mid-capture would invalidate the capture).
    cudaStream_t s_aux;
    cudaEvent_t  ev_fork, ev_join;
    cudaStreamCreateWithFlags(&s_aux, cudaStreamNonBlocking);
    cudaEventCreateWithFlags(&ev_fork, cudaEventDisableTiming);
    cudaEventCreateWithFlags(&ev_join, cudaEventDisableTiming);

    // ---- fork: index chain (memset -> hist -> scan) on aux stream ----
    cudaEventRecord(ev_fork, (cudaStream_t)0);
    cudaStreamWaitEvent(s_aux, ev_fork, 0);

    cudaMemsetAsync(p_cnt, 0, (size_t)N * sizeof(int), s_aux);
    hist_kernel<<<(E + R + 255) / 256, 256, 0, s_aux>>>(ei, ri, E, R);
    size_t tb = TEMP_BYTES;
    cub::DeviceScan::ExclusiveSum(p_tmp, tb, (const int*)p_cnt, (int*)p_offs,
                                  N, s_aux);
    cudaEventRecord(ev_join, s_aux);

    // ---- main stream: fp16 tensor-core MLP partials (overlaps aux) ----
    int n_tiles = (N + 31) / 32;
    int grid = 148 * 3;
    if (grid > n_tiles) grid = n_tiles;
    precompute_mma<<<grid, 128>>>(emb, W1, b1, N, n_tiles);

    // ---- join ----
    cudaStreamWaitEvent((cudaStream_t)0, ev_join, 0);

    // ---- edges + random entries, packed scatter into row segments ----
    int EB = (E + 255) / 256;
    int RB = (R + 255) / 256;
    edge_rand_kernel<<<EB + RB, 256>>>(ei, W2, b2, eps_u, rb_u, ri, E, R, EB);

    // ---- element-parallel rank/coalesce + output ----
    int vals_only = (out_size == M) ? 1 : 0;
    finalize_kernel<<<(M + 255) / 256, 256>>>((float*)d_out, M, vals_only);
}

// round 16
// speedup vs baseline: 5.4307x; 1.0497x over previous
#include <cuda_runtime.h>
#include <cuda_fp16.h>
#include <cstdint>
#include <math.h>
#include <cub/device/device_scan.cuh>

// Problem-fixed sizes (from setup_inputs): N=300000, D=64, E=1000000, R=100000
#define DD 64
static const int    N_MAX = 300032;
static const int    M_MAX = 1200000;
static const size_t TEMP_BYTES = 4u << 20;

// Scratch (device globals — allocation-free per harness rules)
__device__ __align__(16) __half2 g_A[(size_t)N_MAX * 32];   // [N][64] fp16 (b1 folded)
__device__ __align__(16) __half2 g_B[(size_t)N_MAX * 32];
__device__ int            g_cnt [N_MAX];             // per-row entry count
__device__ int            g_offs[N_MAX + 1];         // exclusive prefix -> cursor
__device__ __align__(16) uint4 g_ent[M_MAX];         // packed (row, col, valbits, 0)
__device__ unsigned char  g_temp[TEMP_BYTES];        // CUB scan temp

// ---------------------------------------------------------------------------
// L2 eviction-priority via cache-hint policy (createpolicy + L2::cache_hint;
// the direct .L2::evict_last qualifier needs 32B shapes on sm_103a ptxas).
// ---------------------------------------------------------------------------
__device__ __forceinline__ unsigned long long mk_evict_last_policy() {
    unsigned long long pol;
    asm("createpolicy.fractional.L2::evict_last.b64 %0, 1.0;" : "=l"(pol));
    return pol;
}
__device__ __forceinline__ uint4 ldg_el(const uint4* p, unsigned long long pol) {
    uint4 v;
    asm volatile("ld.global.nc.L2::cache_hint.v4.u32 {%0,%1,%2,%3}, [%4], %5;"
                 : "=r"(v.x), "=r"(v.y), "=r"(v.z), "=r"(v.w)
                 : "l"(p), "l"(pol));
    return v;
}
__device__ __forceinline__ void stg_el(uint4* p, uint4 v, unsigned long long pol) {
    asm volatile("st.global.L2::cache_hint.v4.u32 [%0], {%1,%2,%3,%4}, %5;"
                 :: "l"(p), "r"(v.x), "r"(v.y), "r"(v.z), "r"(v.w), "l"(pol)
                 : "memory");
}

// ---------------------------------------------------------------------------
// Kernel 1: fp16 tensor-core node-factored MLP partials, double-buffered.
// Output stores carry evict_last policy so A/B stay L2-resident for the gather.
// ---------------------------------------------------------------------------
#define PITCH2 36   // half2 pitch: fragment LDS banks (4*gid+tig)%32 distinct

__global__ void __launch_bounds__(128, 3)
precompute_mma(const float* __restrict__ emb,
               const float* __restrict__ W1,
               const float* __restrict__ b1,
               int N, int n_tiles) {
    __shared__ __align__(16) __half2 sE[2][32 * PITCH2];
    __shared__ __align__(16) __half2 sStage[4][16 * PITCH2];

    const int tid  = threadIdx.x;
    const int warp = tid >> 5;
    const int lane = tid & 31;
    const int gid  = lane >> 2;   // 0..7
    const int tig  = lane & 3;    // 0..3
    const int T    = warp & 1;    // 0 -> g_A (W1 left), 1 -> g_B (W1 right)
    const int base = (warp >> 1) * 16;

    const int lni = tid >> 5;          // row 0..3 (+4 per j)
    const int lh  = tid & 31;          // half2 col

    const unsigned long long pol = mk_evict_last_policy();

    unsigned bf[4][8][2];
    float2   b1v[8];
#pragma unroll
    for (int nt = 0; nt < 8; ++nt) {
        int c = nt * 8 + gid;
        const float* wrow = W1 + (size_t)c * 128 + (T ? 64 : 0);
#pragma unroll
        for (int kt = 0; kt < 4; ++kt) {
            __half2 lo = __floats2half2_rn(__ldg(wrow + kt * 16 + 2 * tig),
                                           __ldg(wrow + kt * 16 + 2 * tig + 1));
            __half2 hi = __floats2half2_rn(__ldg(wrow + kt * 16 + 2 * tig + 8),
                                           __ldg(wrow + kt * 16 + 2 * tig + 9));
            bf[kt][nt][0] = *(unsigned*)&lo;
            bf[kt][nt][1] = *(unsigned*)&hi;
        }
        b1v[nt] = T ? make_float2(0.f, 0.f)
                    : __ldg((const float2*)b1 + nt * 4 + tig);
    }

    __half2* tab = T ? g_B : g_A;
    __half2* st  = &sStage[warp][0];

    const int G = gridDim.x;
    int t = blockIdx.x;

    float2 r[8];
#pragma unroll
    for (int j = 0; j < 8; ++j) {
        int n = t * 32 + j * 4 + lni;
        r[j] = (t < n_tiles && n < N)
                   ? __ldg((const float2*)(emb + (size_t)n * DD) + lh)
                   : make_float2(0.f, 0.f);
    }
#pragma unroll
    for (int j = 0; j < 8; ++j)
        sE[0][(j * 4 + lni) * PITCH2 + lh] = __floats2half2_rn(r[j].x, r[j].y);
    __syncthreads();

    int buf = 0;
    for (; t < n_tiles; t += G) {
        const int tn = t + G;
        if (tn < n_tiles) {
#pragma unroll
            for (int j = 0; j < 8; ++j) {
                int n = tn * 32 + j * 4 + lni;
                r[j] = (n < N)
                           ? __ldg((const float2*)(emb + (size_t)n * DD) + lh)
                           : make_float2(0.f, 0.f);
            }
        }

        const int n0 = t * 32;
        const __half2* p0 = &sE[buf][(base + gid)     * PITCH2];
        const __half2* p1 = &sE[buf][(base + gid + 8) * PITCH2];

        float acc[8][4];
#pragma unroll
        for (int nt = 0; nt < 8; ++nt)
#pragma unroll
            for (int c = 0; c < 4; ++c) acc[nt][c] = 0.f;

#pragma unroll
        for (int kt = 0; kt < 4; ++kt) {
            unsigned a0 = *(const unsigned*)&p0[kt * 8 + tig];
            unsigned a1 = *(const unsigned*)&p1[kt * 8 + tig];
            unsigned a2 = *(const unsigned*)&p0[kt * 8 + tig + 4];
            unsigned a3 = *(const unsigned*)&p1[kt * 8 + tig + 4];
#pragma unroll
            for (int nt = 0; nt < 8; ++nt) {
                asm volatile(
                    "mma.sync.aligned.m16n8k16.row.col.f32.f16.f16.f32 "
                    "{%0,%1,%2,%3}, {%4,%5,%6,%7}, {%8,%9}, {%0,%1,%2,%3};"
                    : "+f"(acc[nt][0]), "+f"(acc[nt][1]),
                      "+f"(acc[nt][2]), "+f"(acc[nt][3])
                    : "r"(a0), "r"(a1), "r"(a2), "r"(a3),
                      "r"(bf[kt][nt][0]), "r"(bf[kt][nt][1]));
            }
        }

#pragma unroll
        for (int nt = 0; nt < 8; ++nt) {
            float2 bb = b1v[nt];
            st[gid * PITCH2 + nt * 4 + tig] =
                __floats2half2_rn(acc[nt][0] + bb.x, acc[nt][1] + bb.y);
            st[(gid + 8) * PITCH2 + nt * 4 + tig] =
                __floats2half2_rn(acc[nt][2] + bb.x, acc[nt][3] + bb.y);
        }
        __syncwarp();
#pragma unroll
        for (int i = 0; i < 4; ++i) {
            int rr = i * 4 + (lane >> 3);
            int cc = lane & 7;
            int n  = n0 + base + rr;
            if (n < N) {
                uint4 v = *(const uint4*)((const char*)st + rr * (PITCH2 * 4) + cc * 16);
                stg_el((uint4*)((char*)(tab + (size_t)n * 32) + cc * 16), v, pol);
            }
        }

        if (tn < n_tiles) {
#pragma unroll
            for (int j = 0; j < 8; ++j)
                sE[buf ^ 1][(j * 4 + lni) * PITCH2 + lh] =
                    __floats2half2_rn(r[j].x, r[j].y);
        }
        __syncthreads();
        buf ^= 1;
    }
}

// ---------------------------------------------------------------------------
// Kernel 2: row histogram over all (edge + random) entries.
// ---------------------------------------------------------------------------
__global__ void hist_kernel(const int* __restrict__ ei,
                            const int* __restrict__ ri, int E, int R) {
    int i = blockIdx.x * blockDim.x + threadIdx.x;
    if (i < E)          atomicAdd(&g_cnt[ei[i]], 1);
    else if (i < E + R) atomicAdd(&g_cnt[ri[i - E]], 1);
}

// ---------------------------------------------------------------------------
// Register-only half2-bits -> float2 (no pointer reinterpretation).
// ---------------------------------------------------------------------------
__device__ __forceinline__ float2 u2f2(unsigned u) {
    __half2_raw hr;
    hr.x = (unsigned short)(u & 0xFFFFu);
    hr.y = (unsigned short)(u >> 16);
    return __half22float2(__half2(hr));
}

__device__ __forceinline__ float dot_u4(uint4 a, uint4 b, const float2* w2v) {
    float acc = 0.f;
    float2 av, bv;
    av = u2f2(a.x); bv = u2f2(b.x);
    acc += fmaxf(av.x + bv.x, 0.f) * w2v[0].x + fmaxf(av.y + bv.y, 0.f) * w2v[0].y;
    av = u2f2(a.y); bv = u2f2(b.y);
    acc += fmaxf(av.x + bv.x, 0.f) * w2v[1].x + fmaxf(av.y + bv.y, 0.f) * w2v[1].y;
    av = u2f2(a.z); bv = u2f2(b.z);
    acc += fmaxf(av.x + bv.x, 0.f) * w2v[2].x + fmaxf(av.y + bv.y, 0.f) * w2v[2].y;
    av = u2f2(a.w); bv = u2f2(b.w);
    acc += fmaxf(av.x + bv.x, 0.f) * w2v[3].x + fmaxf(av.y + bv.y, 0.f) * w2v[3].y;
    return acc;
}

// ---------------------------------------------------------------------------
// Kernel 3: edges + random entries in one launch; packed uint4 scatter.
// Gathers carry the evict_last policy; phase 1 stashes src/dst in smem so
// phase 2 avoids re-gathering indices.
// ---------------------------------------------------------------------------
__global__ void edge_rand_kernel(const int* __restrict__ ei,
                                 const float* __restrict__ W2,
                                 const float* __restrict__ b2,
                                 const float* __restrict__ eps_u,
                                 const float* __restrict__ rb_u,
                                 const int* __restrict__ ri,
                                 int E, int R, int EB) {
    __shared__ float s_logit[256];
    __shared__ int   s_src[256];
    __shared__ int   s_dst[256];

    if (blockIdx.x >= EB) {
        int r = (blockIdx.x - EB) * 256 + threadIdx.x;
        if (r < R) {
            int row = __ldg(ri + r);
            int col = __ldg(ri + R + r);
            int pos = atomicAdd(&g_offs[row], 1);
            g_ent[pos] = make_uint4((unsigned)row, (unsigned)col,
                                    __float_as_uint(0.05f), 0u);
        }
        return;
    }

    const int tid  = threadIdx.x;
    const int sub  = tid & 7;
    const int le   = tid >> 3;          // 0..31
    const int base = blockIdx.x * 256;

    const uint4* At = (const uint4*)g_A;   // row = 8 uint4
    const uint4* Bt = (const uint4*)g_B;
    const unsigned long long pol = mk_evict_last_policy();

    float2 w2v[4];
#pragma unroll
    for (int q = 0; q < 4; ++q)
        w2v[q] = __ldg((const float2*)W2 + sub * 4 + q);

    // batch all index loads (coalesced, L2-hot); clamp OOB lanes to row 0
    int srcs[8], dsts[8];
#pragma unroll
    for (int i = 0; i < 8; ++i) {
        int e = base + i * 32 + le;
        bool ok = (e < E);
        srcs[i] = ok ? __ldg(ei + e)     : 0;
        dsts[i] = ok ? __ldg(ei + E + e) : 0;
        if (sub == 0) {
            s_src[i * 32 + le] = srcs[i];
            s_dst[i * 32 + le] = dsts[i];
        }
    }

    float p[8];
#pragma unroll
    for (int h = 0; h < 2; ++h) {
        const int i0 = h * 4;
        // 8 independent LDG.128 (evict_last) before any dependent arithmetic
        uint4 A0 = ldg_el(At + (size_t)srcs[i0 + 0] * 8 + sub, pol);
        uint4 B0 = ldg_el(Bt + (size_t)dsts[i0 + 0] * 8 + sub, pol);
        uint4 A1 = ldg_el(At + (size_t)srcs[i0 + 1] * 8 + sub, pol);
        uint4 B1 = ldg_el(Bt + (size_t)dsts[i0 + 1] * 8 + sub, pol);
        uint4 A2 = ldg_el(At + (size_t)srcs[i0 + 2] * 8 + sub, pol);
        uint4 B2 = ldg_el(Bt + (size_t)dsts[i0 + 2] * 8 + sub, pol);
        uint4 A3 = ldg_el(At + (size_t)srcs[i0 + 3] * 8 + sub, pol);
        uint4 B3 = ldg_el(Bt + (size_t)dsts[i0 + 3] * 8 + sub, pol);
        p[i0 + 0] = dot_u4(A0, B0, w2v);
        p[i0 + 1] = dot_u4(A1, B1, w2v);
        p[i0 + 2] = dot_u4(A2, B2, w2v);
        p[i0 + 3] = dot_u4(A3, B3, w2v);
    }

#pragma unroll
    for (int i = 0; i < 8; ++i) {
        float v = p[i];
        v += __shfl_xor_sync(0xffffffffu, v, 4);
        v += __shfl_xor_sync(0xffffffffu, v, 2);
        v += __shfl_xor_sync(0xffffffffu, v, 1);
        if (sub == 0) s_logit[i * 32 + le] = v;
    }
    __syncthreads();

    int e = base + tid;
    if (e < E) {
        const float LOG2E  = 1.4426950408889634f;
        const float LOG299 = 6.6293566200796095f;   // log2(99)

        int src = s_src[tid];
        int dst = s_dst[tid];
        float logit = s_logit[tid] + __ldg(b2);

        float eu        = __ldg(eps_u + e);
        float eps       = fmaf(-0.9998f, eu, 0.9999f);
        float one_m_eps = fmaf( 0.9998f, eu, 0.0001f);   // exact complement
        float u         = fminf(fmaxf(__ldg(rb_u + e), 1e-7f), 1.0f - 1e-7f);
        float one_m_u   = 1.0f - u;

        float La = __log2f(eps) - __log2f(one_m_eps) + logit * LOG2E;
        float Lc = fminf(fmaxf(La, -LOG299), LOG299);
        float Lz = (Lc + __log2f(u) - __log2f(one_m_u)) * (10.0f / 9.0f);
        float z  = exp2f(Lz);
        float s  = __fdividef(z, 1.0f + z);
        // mask = (s > 0) is always 1 (z > 0), so mat = s
        int pos = atomicAdd(&g_offs[src], 1);
        g_ent[pos] = make_uint4((unsigned)src, (unsigned)dst,
                                __float_as_uint(s), 0u);
    }
}

// ---------------------------------------------------------------------------
// Kernel 4: element-parallel rank/coalesce + output (packed entries).
// out layout: [0..M) rows, [M..2M) cols, [2M..3M) vals (float32)
// ---------------------------------------------------------------------------
__global__ void finalize_kernel(float* __restrict__ out, int M, int vals_only) {
    int i = blockIdx.x * blockDim.x + threadIdx.x;
    if (i >= M) return;

    uint4 me = g_ent[i];
    int      row   = (int)me.x;
    unsigned mycol = me.y;
    float    sum   = __uint_as_float(me.z);

    int end   = g_offs[row];          // segment end (post-scatter cursor)
    int cnt   = g_cnt[row];
    int start = end - cnt;

    int  rank = 0;
    bool head = true;
    for (int j = start; j < end; ++j) {
        if (j == i) continue;
        uint4 ej = g_ent[j];
        unsigned c = ej.y;
        if (c < mycol || (c == mycol && j < i)) ++rank;
        if (c == mycol) {
            if (j < i) head = false;
            sum += __uint_as_float(ej.z);
        }
    }

    int   o  = start + rank;
    float ov = head ? sum : 0.0f;
    if (vals_only) {
        out[o] = ov;
    } else {
        out[o]         = (float)row;
        out[M + o]     = (float)mycol;
        out[2 * M + o] = ov;
    }
}

// ---------------------------------------------------------------------------
extern "C" void kernel_launch(void* const* d_in, const int* in_sizes, int n_in,
                              void* d_out, int out_size) {
    const float* emb   = (const float*)d_in[0];
    const float* W1    = (const float*)d_in[1];
    const float* b1    = (const float*)d_in[2];
    const float* W2    = (const float*)d_in[3];
    const float* b2    = (const float*)d_in[4];
    const int*   ei    = (const int*)  d_in[5];
    const int*   ri    = (const int*)  d_in[6];
    const float* eps_u = (const float*)d_in[7];
    const float* rb_u  = (const float*)d_in[8];

    const int N = in_sizes[0] / DD;
    const int E = in_sizes[5] / 2;
    const int R = in_sizes[6] / 2;
    const int M = E + R;

    void *p_cnt, *p_offs, *p_tmp;
    cudaGetSymbolAddress(&p_cnt,  g_cnt);
    cudaGetSymbolAddress(&p_offs, g_offs);
    cudaGetSymbolAddress(&p_tmp,  g_temp);

    // Aux stream + fork/join events (host objects only; leaked deliberately —
    // destroying them mid-capture would invalidate the capture).
    cudaStream_t s_aux;
    cudaEvent_t  ev_fork, ev_join;
    cudaStreamCreateWithFlags(&s_aux, cudaStreamNonBlocking);
    cudaEventCreateWithFlags(&ev_fork, cudaEventDisableTiming);
    cudaEventCreateWithFlags(&ev_join, cudaEventDisableTiming);

    // ---- fork: index chain (memset -> hist -> scan) on aux stream ----
    cudaEventRecord(ev_fork, (cudaStream_t)0);
    cudaStreamWaitEvent(s_aux, ev_fork, 0);

    cudaMemsetAsync(p_cnt, 0, (size_t)N * sizeof(int), s_aux);
    hist_kernel<<<(E + R + 255) / 256, 256, 0, s_aux>>>(ei, ri, E, R);
    size_t tb = TEMP_BYTES;
    cub::DeviceScan::ExclusiveSum(p_tmp, tb, (const int*)p_cnt, (int*)p_offs,
                                  N, s_aux);
    cudaEventRecord(ev_join, s_aux);

    // ---- main stream: fp16 tensor-core MLP partials (overlaps aux) ----
    int n_tiles = (N + 31) / 32;
    int grid = 148 * 3;
    if (grid > n_tiles) grid = n_tiles;
    precompute_mma<<<grid, 128>>>(emb, W1, b1, N, n_tiles);

    // ---- join ----
    cudaStreamWaitEvent((cudaStream_t)0, ev_join, 0);

    // ---- edges + random entries, packed scatter into row segments ----
    int EB = (E + 255) / 256;
    int RB = (R + 255) / 256;
    edge_rand_kernel<<<EB + RB, 256>>>(ei, W2, b2, eps_u, rb_u, ri, E, R, EB);

    // ---- element-parallel rank/coalesce + output ----
    int vals_only = (out_size == M) ? 1 : 0;
    finalize_kernel<<<(M + 255) / 256, 256>>>((float*)d_out, M, vals_only);
}